// round 1
// baseline (speedup 1.0000x reference)
#include <cuda_runtime.h>
#include <math.h>

#define NB 2
#define NL 2048
#define NK 48
#define NH 128
#define NIN 384
#define NTOK (NB*NL)
#define NEDGE (NB*NL*NK)

__device__ int g_is64;
__device__ int g_idx32[NEDGE];
__device__ float g_hV2[NTOK*NH];

__device__ __forceinline__ float gelu_f(float x) {
    return 0.5f * x * (1.0f + erff(x * 0.7071067811865475f));
}

// ---------------------------------------------------------------------------
// E_idx dtype detection: jnp.int64 usually materializes as int32 (x64 off),
// but handle both. If data is int64 (values < 2^31), every odd 32-bit word is
// zero. If int32, odd words are random indices in [0,2048) -> ~certainly some
// nonzero among 512 samples.
// ---------------------------------------------------------------------------
__global__ void detect_kernel(const int* __restrict__ w) {
    int nz = 0;
    for (int i = 2 * (int)threadIdx.x + 1; i < 1024; i += 512) nz |= (w[i] != 0);
    unsigned any = __ballot_sync(0xffffffffu, nz);
    __shared__ int s[8];
    if ((threadIdx.x & 31) == 0) s[threadIdx.x >> 5] = (any != 0);
    __syncthreads();
    if (threadIdx.x == 0) {
        int a = 0;
        #pragma unroll
        for (int i = 0; i < 8; i++) a |= s[i];
        g_is64 = (a == 0);
    }
}

__global__ void convert_kernel(const void* __restrict__ e) {
    int i = blockIdx.x * blockDim.x + threadIdx.x;
    if (i >= NEDGE) return;
    if (g_is64) g_idx32[i] = (int)((const long long*)e)[i];
    else        g_idx32[i] = ((const int*)e)[i];
}

// ---------------------------------------------------------------------------
// Shared GEMM core: C[48x128] = A[48xKdim] @ W[Kdimx128], A in smem,
// W streamed through a 32x128 smem tile. 256 threads, thread tile 6x4.
// a-operands are warp-broadcast LDS; b-operands one LDS.128.
// ---------------------------------------------------------------------------
__device__ __forceinline__ void gemm48(
    const float* __restrict__ As, int lda,
    const float* __restrict__ Wg, int Kdim,
    float* Wt, int r0, int c0, int tid, float acc[6][4])
{
    #pragma unroll
    for (int r = 0; r < 6; r++)
        #pragma unroll
        for (int c = 0; c < 4; c++) acc[r][c] = 0.0f;

    for (int kt = 0; kt < Kdim; kt += 32) {
        __syncthreads();
        #pragma unroll
        for (int i = 0; i < 16; i++) Wt[tid + 256*i] = Wg[kt*NH + tid + 256*i];
        __syncthreads();
        #pragma unroll 8
        for (int kk = 0; kk < 32; kk++) {
            float4 bb = *(const float4*)&Wt[kk*NH + c0];
            #pragma unroll
            for (int r = 0; r < 6; r++) {
                float a = As[(r0 + r)*lda + kt + kk];
                acc[r][0] += a * bb.x;
                acc[r][1] += a * bb.y;
                acc[r][2] += a * bb.z;
                acc[r][3] += a * bb.w;
            }
        }
    }
}

// ---------------------------------------------------------------------------
// Node update kernel: per (b,l) block. MLP3 over 48 neighbors, masked K-sum,
// LN1, FFN(128->512->128), LN2, mask_V. Writes h_V2 (global scratch + output).
// ---------------------------------------------------------------------------
__global__ void __launch_bounds__(256, 2) node_kernel(
    const float* __restrict__ h_V, const float* __restrict__ h_E,
    const float* __restrict__ mask_V, const float* __restrict__ mask_attend,
    const float* __restrict__ W1, const float* __restrict__ b1,
    const float* __restrict__ W2, const float* __restrict__ b2,
    const float* __restrict__ W3, const float* __restrict__ b3,
    const float* __restrict__ Wi, const float* __restrict__ bi,
    const float* __restrict__ Wo, const float* __restrict__ bo,
    const float* __restrict__ ln1s, const float* __restrict__ ln1b,
    const float* __restrict__ ln2s, const float* __restrict__ ln2b,
    float* __restrict__ out_hV)
{
    extern __shared__ float smem[];
    float* Xs = smem;                 // 48*384 = 18432 floats
    float* Wt = Xs + NK*NIN;          // 32*128 = 4096
    float* Ys = Wt + 32*NH;           // 48*128 = 6144
    float* Zs = Xs;                   // alias: layer2 out / FFN hvec
    float* redA = Wt + 1200;          // 8 floats (offsets beyond partial area)
    float* redB = Wt + 1216;

    int bl = blockIdx.x;
    int b  = bl >> 11;
    int tid = threadIdx.x;
    int warp = tid >> 5, lane = tid & 31;
    int r0 = warp * 6, c0 = lane * 4;
    const float* hv = h_V + (size_t)bl * NH;

    // Build X = [h_V | h_E | gathered h_V] per neighbor row
    for (int i = tid; i < NK*NH; i += 256) {
        int k = i >> 7, c = i & 127;
        Xs[k*NIN + c]        = hv[c];
        Xs[k*NIN + NH + c]   = h_E[((size_t)bl*NK + k)*NH + c];
        int g = g_idx32[bl*NK + k];
        Xs[k*NIN + 2*NH + c] = h_V[((size_t)b*NL + g)*NH + c];
    }

    float acc[6][4];
    // layer 1: 384 -> 128, gelu
    gemm48(Xs, NIN, W1, NIN, Wt, r0, c0, tid, acc);
    {
        float4 bv = *(const float4*)&b1[c0];
        #pragma unroll
        for (int r = 0; r < 6; r++) {
            Ys[(r0+r)*NH + c0+0] = gelu_f(acc[r][0] + bv.x);
            Ys[(r0+r)*NH + c0+1] = gelu_f(acc[r][1] + bv.y);
            Ys[(r0+r)*NH + c0+2] = gelu_f(acc[r][2] + bv.z);
            Ys[(r0+r)*NH + c0+3] = gelu_f(acc[r][3] + bv.w);
        }
    }
    // layer 2: 128 -> 128, gelu (writes Zs == Xs, safe: Xs consumed)
    gemm48(Ys, NH, W2, NH, Wt, r0, c0, tid, acc);
    {
        float4 bv = *(const float4*)&b2[c0];
        #pragma unroll
        for (int r = 0; r < 6; r++) {
            Zs[(r0+r)*NH + c0+0] = gelu_f(acc[r][0] + bv.x);
            Zs[(r0+r)*NH + c0+1] = gelu_f(acc[r][1] + bv.y);
            Zs[(r0+r)*NH + c0+2] = gelu_f(acc[r][2] + bv.z);
            Zs[(r0+r)*NH + c0+3] = gelu_f(acc[r][3] + bv.w);
        }
    }
    // layer 3: 128 -> 128 (linear), mask, partial K-sum per thread
    gemm48(Zs, NH, W3, NH, Wt, r0, c0, tid, acc);
    float4 bv3 = *(const float4*)&b3[c0];
    float part0 = 0.f, part1 = 0.f, part2 = 0.f, part3 = 0.f;
    #pragma unroll
    for (int r = 0; r < 6; r++) {
        float mk = mask_attend[bl*NK + r0 + r];
        part0 += (acc[r][0] + bv3.x) * mk;
        part1 += (acc[r][1] + bv3.y) * mk;
        part2 += (acc[r][2] + bv3.z) * mk;
        part3 += (acc[r][3] + bv3.w) * mk;
    }
    __syncthreads();                       // Wt free now
    Wt[warp*NH + c0+0] = part0;
    Wt[warp*NH + c0+1] = part1;
    Wt[warp*NH + c0+2] = part2;
    Wt[warp*NH + c0+3] = part3;
    __syncthreads();

    float t = 0.0f;
    if (tid < NH) {
        float dh = 0.0f;
        #pragma unroll
        for (int w = 0; w < 8; w++) dh += Wt[w*NH + tid];
        t = hv[tid] + dh * (1.0f / 30.0f);
    }
    // LN1 block reduce (threads >=128 contribute 0)
    float s1 = t, s2 = t * t;
    #pragma unroll
    for (int o = 16; o; o >>= 1) {
        s1 += __shfl_xor_sync(0xffffffffu, s1, o);
        s2 += __shfl_xor_sync(0xffffffffu, s2, o);
    }
    if (lane == 0) { redA[warp] = s1; redB[warp] = s2; }
    __syncthreads();
    float sum = 0.f, ssq = 0.f;
    #pragma unroll
    for (int w = 0; w < 8; w++) { sum += redA[w]; ssq += redB[w]; }
    float mu = sum * (1.0f / NH);
    float var = ssq * (1.0f / NH) - mu * mu;
    float rinv = rsqrtf(var + 1e-5f);
    float h1 = 0.0f;
    if (tid < NH) {
        h1 = (t - mu) * rinv * ln1s[tid] + ln1b[tid];
        Zs[tid] = h1;                      // hvec for FFN
    }
    __syncthreads();

    // FFN hidden: 512 units, 2 per thread
    float a0 = bi[tid], a1 = bi[tid + 256];
    #pragma unroll 8
    for (int i2 = 0; i2 < NH; i2++) {
        float x = Zs[i2];
        a0 += x * Wi[i2*512 + tid];
        a1 += x * Wi[i2*512 + tid + 256];
    }
    Ys[tid]       = gelu_f(a0);
    Ys[tid + 256] = gelu_f(a1);
    __syncthreads();

    float t2 = 0.0f;
    if (tid < NH) {
        float s = bo[tid];
        #pragma unroll 8
        for (int i2 = 0; i2 < 512; i2++) s += Ys[i2] * Wo[i2*NH + tid];
        t2 = h1 + s;
    }
    // LN2 block reduce
    s1 = t2; s2 = t2 * t2;
    #pragma unroll
    for (int o = 16; o; o >>= 1) {
        s1 += __shfl_xor_sync(0xffffffffu, s1, o);
        s2 += __shfl_xor_sync(0xffffffffu, s2, o);
    }
    if (lane == 0) { redA[warp] = s1; redB[warp] = s2; }
    __syncthreads();
    sum = 0.f; ssq = 0.f;
    #pragma unroll
    for (int w = 0; w < 8; w++) { sum += redA[w]; ssq += redB[w]; }
    mu = sum * (1.0f / NH);
    var = ssq * (1.0f / NH) - mu * mu;
    rinv = rsqrtf(var + 1e-5f);
    if (tid < NH) {
        float o = ((t2 - mu) * rinv * ln2s[tid] + ln2b[tid]) * mask_V[bl];
        g_hV2[bl*NH + tid] = o;
        out_hV[(size_t)bl*NH + tid] = o;
    }
}

// ---------------------------------------------------------------------------
// Edge update kernel: per (b,l) block. MLP3 on updated h_V, per-row LN3.
// ---------------------------------------------------------------------------
__global__ void __launch_bounds__(256, 2) edge_kernel(
    const float* __restrict__ h_E,
    const float* __restrict__ W11, const float* __restrict__ b11,
    const float* __restrict__ W12, const float* __restrict__ b12,
    const float* __restrict__ W13, const float* __restrict__ b13,
    const float* __restrict__ ln3s, const float* __restrict__ ln3b,
    float* __restrict__ out_hE)
{
    extern __shared__ float smem[];
    float* Xs = smem;
    float* Wt = Xs + NK*NIN;
    float* Ys = Wt + 32*NH;
    float* Zs = Xs;

    int bl = blockIdx.x;
    int b  = bl >> 11;
    int tid = threadIdx.x;
    int warp = tid >> 5, lane = tid & 31;
    int r0 = warp * 6, c0 = lane * 4;
    const float* hv = g_hV2 + (size_t)bl * NH;

    for (int i = tid; i < NK*NH; i += 256) {
        int k = i >> 7, c = i & 127;
        Xs[k*NIN + c]        = hv[c];
        Xs[k*NIN + NH + c]   = h_E[((size_t)bl*NK + k)*NH + c];
        int g = g_idx32[bl*NK + k];
        Xs[k*NIN + 2*NH + c] = g_hV2[((size_t)b*NL + g)*NH + c];
    }

    float acc[6][4];
    gemm48(Xs, NIN, W11, NIN, Wt, r0, c0, tid, acc);
    {
        float4 bv = *(const float4*)&b11[c0];
        #pragma unroll
        for (int r = 0; r < 6; r++) {
            Ys[(r0+r)*NH + c0+0] = gelu_f(acc[r][0] + bv.x);
            Ys[(r0+r)*NH + c0+1] = gelu_f(acc[r][1] + bv.y);
            Ys[(r0+r)*NH + c0+2] = gelu_f(acc[r][2] + bv.z);
            Ys[(r0+r)*NH + c0+3] = gelu_f(acc[r][3] + bv.w);
        }
    }
    gemm48(Ys, NH, W12, NH, Wt, r0, c0, tid, acc);
    {
        float4 bv = *(const float4*)&b12[c0];
        #pragma unroll
        for (int r = 0; r < 6; r++) {
            Zs[(r0+r)*NH + c0+0] = gelu_f(acc[r][0] + bv.x);
            Zs[(r0+r)*NH + c0+1] = gelu_f(acc[r][1] + bv.y);
            Zs[(r0+r)*NH + c0+2] = gelu_f(acc[r][2] + bv.z);
            Zs[(r0+r)*NH + c0+3] = gelu_f(acc[r][3] + bv.w);
        }
    }
    gemm48(Zs, NH, W13, NH, Wt, r0, c0, tid, acc);

    float4 bv  = *(const float4*)&b13[c0];
    float4 g3s = *(const float4*)&ln3s[c0];
    float4 g3b = *(const float4*)&ln3b[c0];
    #pragma unroll
    for (int r = 0; r < 6; r++) {
        size_t off = ((size_t)bl*NK + r0 + r) * NH;
        float4 he = *(const float4*)&h_E[off + c0];
        float v0 = he.x + acc[r][0] + bv.x;
        float v1 = he.y + acc[r][1] + bv.y;
        float v2 = he.z + acc[r][2] + bv.z;
        float v3 = he.w + acc[r][3] + bv.w;
        float s1 = v0 + v1 + v2 + v3;
        float s2 = v0*v0 + v1*v1 + v2*v2 + v3*v3;
        #pragma unroll
        for (int o = 16; o; o >>= 1) {
            s1 += __shfl_xor_sync(0xffffffffu, s1, o);
            s2 += __shfl_xor_sync(0xffffffffu, s2, o);
        }
        float mu = s1 * (1.0f / NH);
        float var = s2 * (1.0f / NH) - mu * mu;
        float rinv = rsqrtf(var + 1e-5f);
        float4 o4;
        o4.x = (v0 - mu) * rinv * g3s.x + g3b.x;
        o4.y = (v1 - mu) * rinv * g3s.y + g3b.y;
        o4.z = (v2 - mu) * rinv * g3s.z + g3b.z;
        o4.w = (v3 - mu) * rinv * g3s.w + g3b.w;
        *(float4*)&out_hE[off + c0] = o4;
    }
}

// ---------------------------------------------------------------------------

extern "C" void kernel_launch(void* const* d_in, const int* in_sizes, int n_in,
                              void* d_out, int out_size)
{
    const float* h_V         = (const float*)d_in[0];
    const float* h_E         = (const float*)d_in[1];
    const void*  E_idx       =               d_in[2];
    const float* mask_V      = (const float*)d_in[3];
    const float* mask_attend = (const float*)d_in[4];
    const float* W1  = (const float*)d_in[5],  *b1  = (const float*)d_in[6];
    const float* W2  = (const float*)d_in[7],  *b2  = (const float*)d_in[8];
    const float* W3  = (const float*)d_in[9],  *b3  = (const float*)d_in[10];
    const float* W11 = (const float*)d_in[11], *b11 = (const float*)d_in[12];
    const float* W12 = (const float*)d_in[13], *b12 = (const float*)d_in[14];
    const float* W13 = (const float*)d_in[15], *b13 = (const float*)d_in[16];
    const float* Wi  = (const float*)d_in[17], *bi  = (const float*)d_in[18];
    const float* Wo  = (const float*)d_in[19], *bo  = (const float*)d_in[20];
    const float* ln1s = (const float*)d_in[21], *ln1b = (const float*)d_in[22];
    const float* ln2s = (const float*)d_in[23], *ln2b = (const float*)d_in[24];
    const float* ln3s = (const float*)d_in[25], *ln3b = (const float*)d_in[26];
    float* out = (float*)d_out;

    int shmem = (NK*NIN + 32*NH + NK*NH) * (int)sizeof(float);  // 114688 B
    cudaFuncSetAttribute(node_kernel, cudaFuncAttributeMaxDynamicSharedMemorySize, shmem);
    cudaFuncSetAttribute(edge_kernel, cudaFuncAttributeMaxDynamicSharedMemorySize, shmem);

    detect_kernel<<<1, 256>>>((const int*)E_idx);
    convert_kernel<<<(NEDGE + 255) / 256, 256>>>(E_idx);
    node_kernel<<<NTOK, 256, shmem>>>(h_V, h_E, mask_V, mask_attend,
                                      W1, b1, W2, b2, W3, b3,
                                      Wi, bi, Wo, bo,
                                      ln1s, ln1b, ln2s, ln2b, out);
    edge_kernel<<<NTOK, 256, shmem>>>(h_E, W11, b11, W12, b12, W13, b13,
                                      ln3s, ln3b, out + (size_t)NTOK * NH);
}

// round 2
// speedup vs baseline: 1.7672x; 1.7672x over previous
#include <cuda_runtime.h>
#include <math.h>

#define NB 2
#define NL 2048
#define NK 48
#define NH 128
#define NTOK (NB*NL)
#define NEDGE (NB*NL*NK)
#define FFH 512

__device__ int   g_is64;
__device__ int   g_idx32[NEDGE];
__device__ float g_hV2[NTOK*NH];
__device__ float g_h1 [NTOK*NH];
__device__ float g_H  [NTOK*FFH];
__device__ float g_P1 [NTOK*NH];
__device__ float g_G1 [NTOK*NH];
__device__ float g_P2 [NTOK*NH];
__device__ float g_G2 [NTOK*NH];

__device__ __forceinline__ float gelu_f(float x) {
    return 0.5f * x * (1.0f + erff(x * 0.7071067811865475f));
}

// ---------------------------------------------------------------------------
// E_idx dtype detect + normalize to int32
// ---------------------------------------------------------------------------
__global__ void detect_kernel(const int* __restrict__ w) {
    int nz = 0;
    for (int i = 2 * (int)threadIdx.x + 1; i < 1024; i += 512) nz |= (w[i] != 0);
    unsigned any = __ballot_sync(0xffffffffu, nz);
    __shared__ int s[8];
    if ((threadIdx.x & 31) == 0) s[threadIdx.x >> 5] = (any != 0);
    __syncthreads();
    if (threadIdx.x == 0) {
        int a = 0;
        #pragma unroll
        for (int i = 0; i < 8; i++) a |= s[i];
        g_is64 = (a == 0);
    }
}

__global__ void convert_kernel(const void* __restrict__ e) {
    int i = blockIdx.x * blockDim.x + threadIdx.x;
    if (i >= NEDGE) return;
    if (g_is64) g_idx32[i] = (int)((const long long*)e)[i];
    else        g_idx32[i] = ((const int*)e)[i];
}

// ---------------------------------------------------------------------------
// Core GEMM: acc[R][4] += A[smem, lda=128, K=128] @ W[global, row-stride ws]
// b streamed through Wt[32x128] smem tile; a loaded as float4 (broadcast).
// ---------------------------------------------------------------------------
#define GSTEP(CMP, J) { \
    float4 bb = *(const float4*)&Wt[(kk4*4 + J)*NH + c0]; \
    _Pragma("unroll") \
    for (int r = 0; r < R; r++) { \
        float a = a4[r].CMP; \
        acc[r][0] += a * bb.x; acc[r][1] += a * bb.y; \
        acc[r][2] += a * bb.z; acc[r][3] += a * bb.w; } }

template<int R>
__device__ __forceinline__ void gemm_k128(
    const float* __restrict__ As, const float* __restrict__ Wg, int ws,
    float* Wt, int r0, int c0, int tid, float (&acc)[R][4])
{
    #pragma unroll
    for (int r = 0; r < R; r++)
        #pragma unroll
        for (int c = 0; c < 4; c++) acc[r][c] = 0.0f;

    for (int kt = 0; kt < 128; kt += 32) {
        __syncthreads();
        #pragma unroll
        for (int j = 0; j < 16; j++) {
            int i = tid + 256*j;
            Wt[i] = Wg[(kt + (i >> 7))*ws + (i & 127)];
        }
        __syncthreads();
        #pragma unroll
        for (int kk4 = 0; kk4 < 8; kk4++) {
            float4 a4[R];
            #pragma unroll
            for (int r = 0; r < R; r++)
                a4[r] = *(const float4*)&As[(r0 + r)*NH + kt + kk4*4];
            GSTEP(x, 0) GSTEP(y, 1) GSTEP(z, 2) GSTEP(w, 3)
        }
    }
}

// ---------------------------------------------------------------------------
// token_gemm: C[4096x128] = A[4096x128] @ W[128x128] (+bias). grid=64 CTAs,
// CTA = 64 tokens. Used for P/G precomputes.
// ---------------------------------------------------------------------------
__global__ void __launch_bounds__(256) token_gemm(
    const float* __restrict__ A, const float* __restrict__ W,
    const float* __restrict__ bias, float* __restrict__ C)
{
    extern __shared__ float smem[];
    float* As = smem;            // 64*128 = 8192
    float* Wt = As + 64*NH;      // 32*128 = 4096
    int bl0 = blockIdx.x * 64;
    int tid = threadIdx.x;
    int warp = tid >> 5, lane = tid & 31;
    int r0 = warp * 8, c0 = lane * 4;

    #pragma unroll
    for (int j = 0; j < 32; j++) As[tid + 256*j] = A[(size_t)bl0*NH + tid + 256*j];

    float acc[8][4];
    gemm_k128<8>(As, W, NH, Wt, r0, c0, tid, acc);

    float4 bv = make_float4(0.f, 0.f, 0.f, 0.f);
    if (bias) bv = *(const float4*)&bias[c0];
    #pragma unroll
    for (int r = 0; r < 8; r++) {
        float4 o4;
        o4.x = acc[r][0] + bv.x; o4.y = acc[r][1] + bv.y;
        o4.z = acc[r][2] + bv.z; o4.w = acc[r][3] + bv.w;
        *(float4*)&C[(size_t)(bl0 + r0 + r)*NH + c0] = o4;
    }
}

// ---------------------------------------------------------------------------
// nodeA: per-token CTA. MLP3 on [48x128] hE (K=128 via P1/G1 trick),
// masked K-sum, LN1 -> g_h1.
// ---------------------------------------------------------------------------
__global__ void __launch_bounds__(256) nodeA_kernel(
    const float* __restrict__ h_V, const float* __restrict__ h_E,
    const float* __restrict__ mask_attend,
    const float* __restrict__ W1E,
    const float* __restrict__ W2, const float* __restrict__ b2,
    const float* __restrict__ W3, const float* __restrict__ b3,
    const float* __restrict__ ln1s, const float* __restrict__ ln1b)
{
    extern __shared__ float smem[];
    float* As = smem;            // 48*128 = 6144
    float* Wt = As + NK*NH;      // 4096
    float* Ys = Wt + 32*NH;      // 6144
    float* Zs = As;              // alias
    float* redA = Wt + 1024;
    float* redB = Wt + 1040;

    int bl = blockIdx.x;
    int b  = bl >> 11;
    int tid = threadIdx.x;
    int warp = tid >> 5, lane = tid & 31;
    int r0 = warp * 6, c0 = lane * 4;

    #pragma unroll
    for (int j = 0; j < 24; j++) As[tid + 256*j] = h_E[(size_t)bl*NK*NH + tid + 256*j];

    float acc[6][4];
    // layer1: hE @ W1E, + P1[token] + G1[gather], gelu
    gemm_k128<6>(As, W1E, NH, Wt, r0, c0, tid, acc);
    {
        float4 Pv = *(const float4*)&g_P1[(size_t)bl*NH + c0];
        #pragma unroll
        for (int r = 0; r < 6; r++) {
            int g = g_idx32[bl*NK + r0 + r];
            float4 Gv = *(const float4*)&g_G1[(size_t)(b*NL + g)*NH + c0];
            Ys[(r0+r)*NH + c0+0] = gelu_f(acc[r][0] + Pv.x + Gv.x);
            Ys[(r0+r)*NH + c0+1] = gelu_f(acc[r][1] + Pv.y + Gv.y);
            Ys[(r0+r)*NH + c0+2] = gelu_f(acc[r][2] + Pv.z + Gv.z);
            Ys[(r0+r)*NH + c0+3] = gelu_f(acc[r][3] + Pv.w + Gv.w);
        }
    }
    // layer2
    gemm_k128<6>(Ys, W2, NH, Wt, r0, c0, tid, acc);
    {
        float4 bv = *(const float4*)&b2[c0];
        #pragma unroll
        for (int r = 0; r < 6; r++) {
            Zs[(r0+r)*NH + c0+0] = gelu_f(acc[r][0] + bv.x);
            Zs[(r0+r)*NH + c0+1] = gelu_f(acc[r][1] + bv.y);
            Zs[(r0+r)*NH + c0+2] = gelu_f(acc[r][2] + bv.z);
            Zs[(r0+r)*NH + c0+3] = gelu_f(acc[r][3] + bv.w);
        }
    }
    // layer3 + masked K-sum
    gemm_k128<6>(Zs, W3, NH, Wt, r0, c0, tid, acc);
    float4 bv3 = *(const float4*)&b3[c0];
    float p0 = 0.f, p1 = 0.f, p2 = 0.f, p3 = 0.f;
    #pragma unroll
    for (int r = 0; r < 6; r++) {
        float mk = mask_attend[bl*NK + r0 + r];
        p0 += (acc[r][0] + bv3.x) * mk;
        p1 += (acc[r][1] + bv3.y) * mk;
        p2 += (acc[r][2] + bv3.z) * mk;
        p3 += (acc[r][3] + bv3.w) * mk;
    }
    __syncthreads();
    Wt[warp*NH + c0+0] = p0; Wt[warp*NH + c0+1] = p1;
    Wt[warp*NH + c0+2] = p2; Wt[warp*NH + c0+3] = p3;
    __syncthreads();

    float t = 0.0f;
    if (tid < NH) {
        float dh = 0.0f;
        #pragma unroll
        for (int w = 0; w < 8; w++) dh += Wt[w*NH + tid];
        t = h_V[(size_t)bl*NH + tid] + dh * (1.0f / 30.0f);
    }
    float s1 = t, s2 = t * t;
    #pragma unroll
    for (int o = 16; o; o >>= 1) {
        s1 += __shfl_xor_sync(0xffffffffu, s1, o);
        s2 += __shfl_xor_sync(0xffffffffu, s2, o);
    }
    if (lane == 0) { redA[warp] = s1; redB[warp] = s2; }
    __syncthreads();
    float sum = 0.f, ssq = 0.f;
    #pragma unroll
    for (int w = 0; w < 8; w++) { sum += redA[w]; ssq += redB[w]; }
    float mu = sum * (1.0f / NH);
    float var = ssq * (1.0f / NH) - mu * mu;
    float rinv = rsqrtf(var + 1e-5f);
    if (tid < NH)
        g_h1[(size_t)bl*NH + tid] = (t - mu) * rinv * ln1s[tid] + ln1b[tid];
}

// ---------------------------------------------------------------------------
// ffn1: H[4096x512] = gelu(h1 @ Wi + bi). grid (64,4).
// ---------------------------------------------------------------------------
__global__ void __launch_bounds__(256) ffn1_kernel(
    const float* __restrict__ Wi, const float* __restrict__ bi)
{
    extern __shared__ float smem[];
    float* As = smem;            // 64*128
    float* Wt = As + 64*NH;      // 32*128
    int bl0 = blockIdx.x * 64;
    int nb  = blockIdx.y * 128;
    int tid = threadIdx.x;
    int warp = tid >> 5, lane = tid & 31;
    int r0 = warp * 8, c0 = lane * 4;

    #pragma unroll
    for (int j = 0; j < 32; j++) As[tid + 256*j] = g_h1[(size_t)bl0*NH + tid + 256*j];

    float acc[8][4];
    gemm_k128<8>(As, Wi + nb, FFH, Wt, r0, c0, tid, acc);

    float4 bv = *(const float4*)&bi[nb + c0];
    #pragma unroll
    for (int r = 0; r < 8; r++) {
        float4 o4;
        o4.x = gelu_f(acc[r][0] + bv.x); o4.y = gelu_f(acc[r][1] + bv.y);
        o4.z = gelu_f(acc[r][2] + bv.z); o4.w = gelu_f(acc[r][3] + bv.w);
        *(float4*)&g_H[(size_t)(bl0 + r0 + r)*FFH + nb + c0] = o4;
    }
}

// ---------------------------------------------------------------------------
// ffn2: hV2 = LN2(h1 + H @ Wo + bo) * mask_V ; writes g_hV2 and out_hV.
// grid 64 CTAs, CTA = 64 tokens x full 128 cols, K=512.
// ---------------------------------------------------------------------------
__global__ void __launch_bounds__(256) ffn2_kernel(
    const float* __restrict__ Wo, const float* __restrict__ bo,
    const float* __restrict__ ln2s, const float* __restrict__ ln2b,
    const float* __restrict__ mask_V, float* __restrict__ out_hV)
{
    extern __shared__ float smem[];
    float* At = smem;            // 64*32 = 2048
    float* Wt = At + 64*32;      // 32*128 = 4096
    int bl0 = blockIdx.x * 64;
    int tid = threadIdx.x;
    int warp = tid >> 5, lane = tid & 31;
    int r0 = warp * 8, c0 = lane * 4;

    float acc[8][4];
    #pragma unroll
    for (int r = 0; r < 8; r++)
        #pragma unroll
        for (int c = 0; c < 4; c++) acc[r][c] = 0.0f;

    for (int kt = 0; kt < FFH; kt += 32) {
        __syncthreads();
        #pragma unroll
        for (int j = 0; j < 8; j++) {
            int i = tid + 256*j;
            At[i] = g_H[(size_t)(bl0 + (i >> 5))*FFH + kt + (i & 31)];
        }
        #pragma unroll
        for (int j = 0; j < 16; j++) {
            int i = tid + 256*j;
            Wt[i] = Wo[(kt + (i >> 7))*NH + (i & 127)];
        }
        __syncthreads();
        #pragma unroll
        for (int kk4 = 0; kk4 < 8; kk4++) {
            float4 a4[8];
            #pragma unroll
            for (int r = 0; r < 8; r++)
                a4[r] = *(const float4*)&At[(r0 + r)*32 + kk4*4];
            {
                const int R = 8;
                GSTEP(x, 0) GSTEP(y, 1) GSTEP(z, 2) GSTEP(w, 3)
            }
        }
    }

    float4 bv  = *(const float4*)&bo[c0];
    float4 g2s = *(const float4*)&ln2s[c0];
    float4 g2b = *(const float4*)&ln2b[c0];
    #pragma unroll
    for (int r = 0; r < 8; r++) {
        int token = bl0 + r0 + r;
        float4 hv = *(const float4*)&g_h1[(size_t)token*NH + c0];
        float v0 = hv.x + acc[r][0] + bv.x;
        float v1 = hv.y + acc[r][1] + bv.y;
        float v2 = hv.z + acc[r][2] + bv.z;
        float v3 = hv.w + acc[r][3] + bv.w;
        float s1 = v0 + v1 + v2 + v3;
        float s2 = v0*v0 + v1*v1 + v2*v2 + v3*v3;
        #pragma unroll
        for (int o = 16; o; o >>= 1) {
            s1 += __shfl_xor_sync(0xffffffffu, s1, o);
            s2 += __shfl_xor_sync(0xffffffffu, s2, o);
        }
        float mu = s1 * (1.0f / NH);
        float var = s2 * (1.0f / NH) - mu * mu;
        float rinv = rsqrtf(var + 1e-5f);
        float mk = mask_V[token];
        float4 o4;
        o4.x = ((v0 - mu) * rinv * g2s.x + g2b.x) * mk;
        o4.y = ((v1 - mu) * rinv * g2s.y + g2b.y) * mk;
        o4.z = ((v2 - mu) * rinv * g2s.z + g2b.z) * mk;
        o4.w = ((v3 - mu) * rinv * g2s.w + g2b.w) * mk;
        *(float4*)&g_hV2[(size_t)token*NH + c0] = o4;
        *(float4*)&out_hV[(size_t)token*NH + c0] = o4;
    }
}

// ---------------------------------------------------------------------------
// edge: per-token CTA. MLP3 on [48x128] hE (K=128 via P2/G2), per-row LN3.
// ---------------------------------------------------------------------------
__global__ void __launch_bounds__(256) edge_kernel(
    const float* __restrict__ h_E,
    const float* __restrict__ W11E,
    const float* __restrict__ W12, const float* __restrict__ b12,
    const float* __restrict__ W13, const float* __restrict__ b13,
    const float* __restrict__ ln3s, const float* __restrict__ ln3b,
    float* __restrict__ out_hE)
{
    extern __shared__ float smem[];
    float* As = smem;
    float* Wt = As + NK*NH;
    float* Ys = Wt + 32*NH;
    float* Zs = As;

    int bl = blockIdx.x;
    int b  = bl >> 11;
    int tid = threadIdx.x;
    int warp = tid >> 5, lane = tid & 31;
    int r0 = warp * 6, c0 = lane * 4;

    #pragma unroll
    for (int j = 0; j < 24; j++) As[tid + 256*j] = h_E[(size_t)bl*NK*NH + tid + 256*j];

    float acc[6][4];
    gemm_k128<6>(As, W11E, NH, Wt, r0, c0, tid, acc);
    {
        float4 Pv = *(const float4*)&g_P2[(size_t)bl*NH + c0];
        #pragma unroll
        for (int r = 0; r < 6; r++) {
            int g = g_idx32[bl*NK + r0 + r];
            float4 Gv = *(const float4*)&g_G2[(size_t)(b*NL + g)*NH + c0];
            Ys[(r0+r)*NH + c0+0] = gelu_f(acc[r][0] + Pv.x + Gv.x);
            Ys[(r0+r)*NH + c0+1] = gelu_f(acc[r][1] + Pv.y + Gv.y);
            Ys[(r0+r)*NH + c0+2] = gelu_f(acc[r][2] + Pv.z + Gv.z);
            Ys[(r0+r)*NH + c0+3] = gelu_f(acc[r][3] + Pv.w + Gv.w);
        }
    }
    gemm_k128<6>(Ys, W12, NH, Wt, r0, c0, tid, acc);
    {
        float4 bv = *(const float4*)&b12[c0];
        #pragma unroll
        for (int r = 0; r < 6; r++) {
            Zs[(r0+r)*NH + c0+0] = gelu_f(acc[r][0] + bv.x);
            Zs[(r0+r)*NH + c0+1] = gelu_f(acc[r][1] + bv.y);
            Zs[(r0+r)*NH + c0+2] = gelu_f(acc[r][2] + bv.z);
            Zs[(r0+r)*NH + c0+3] = gelu_f(acc[r][3] + bv.w);
        }
    }
    gemm_k128<6>(Zs, W13, NH, Wt, r0, c0, tid, acc);

    float4 bv  = *(const float4*)&b13[c0];
    float4 g3s = *(const float4*)&ln3s[c0];
    float4 g3b = *(const float4*)&ln3b[c0];
    #pragma unroll
    for (int r = 0; r < 6; r++) {
        size_t off = ((size_t)bl*NK + r0 + r) * NH;
        float4 he = *(const float4*)&h_E[off + c0];
        float v0 = he.x + acc[r][0] + bv.x;
        float v1 = he.y + acc[r][1] + bv.y;
        float v2 = he.z + acc[r][2] + bv.z;
        float v3 = he.w + acc[r][3] + bv.w;
        float s1 = v0 + v1 + v2 + v3;
        float s2 = v0*v0 + v1*v1 + v2*v2 + v3*v3;
        #pragma unroll
        for (int o = 16; o; o >>= 1) {
            s1 += __shfl_xor_sync(0xffffffffu, s1, o);
            s2 += __shfl_xor_sync(0xffffffffu, s2, o);
        }
        float mu = s1 * (1.0f / NH);
        float var = s2 * (1.0f / NH) - mu * mu;
        float rinv = rsqrtf(var + 1e-5f);
        float4 o4;
        o4.x = (v0 - mu) * rinv * g3s.x + g3b.x;
        o4.y = (v1 - mu) * rinv * g3s.y + g3b.y;
        o4.z = (v2 - mu) * rinv * g3s.z + g3b.z;
        o4.w = (v3 - mu) * rinv * g3s.w + g3b.w;
        *(float4*)&out_hE[off + c0] = o4;
    }
}

// ---------------------------------------------------------------------------

extern "C" void kernel_launch(void* const* d_in, const int* in_sizes, int n_in,
                              void* d_out, int out_size)
{
    const float* h_V         = (const float*)d_in[0];
    const float* h_E         = (const float*)d_in[1];
    const void*  E_idx       =               d_in[2];
    const float* mask_V      = (const float*)d_in[3];
    const float* mask_attend = (const float*)d_in[4];
    const float* W1  = (const float*)d_in[5],  *b1  = (const float*)d_in[6];
    const float* W2  = (const float*)d_in[7],  *b2  = (const float*)d_in[8];
    const float* W3  = (const float*)d_in[9],  *b3  = (const float*)d_in[10];
    const float* W11 = (const float*)d_in[11], *b11 = (const float*)d_in[12];
    const float* W12 = (const float*)d_in[13], *b12 = (const float*)d_in[14];
    const float* W13 = (const float*)d_in[15], *b13 = (const float*)d_in[16];
    const float* Wi  = (const float*)d_in[17], *bi  = (const float*)d_in[18];
    const float* Wo  = (const float*)d_in[19], *bo  = (const float*)d_in[20];
    const float* ln1s = (const float*)d_in[21], *ln1b = (const float*)d_in[22];
    const float* ln2s = (const float*)d_in[23], *ln2b = (const float*)d_in[24];
    const float* ln3s = (const float*)d_in[25], *ln3b = (const float*)d_in[26];
    float* out = (float*)d_out;

    float *pP1, *pG1, *pP2, *pG2, *pHV2;
    cudaGetSymbolAddress((void**)&pP1,  g_P1);
    cudaGetSymbolAddress((void**)&pG1,  g_G1);
    cudaGetSymbolAddress((void**)&pP2,  g_P2);
    cudaGetSymbolAddress((void**)&pG2,  g_G2);
    cudaGetSymbolAddress((void**)&pHV2, g_hV2);

    int sm_big = (NK*NH + 32*NH + NK*NH) * (int)sizeof(float);   // 65536
    int sm_tg  = (64*NH + 32*NH) * (int)sizeof(float);           // 49152
    int sm_f2  = (64*32 + 32*NH) * (int)sizeof(float);           // 24576

    cudaFuncSetAttribute(nodeA_kernel, cudaFuncAttributeMaxDynamicSharedMemorySize, sm_big);
    cudaFuncSetAttribute(edge_kernel,  cudaFuncAttributeMaxDynamicSharedMemorySize, sm_big);
    cudaFuncSetAttribute(token_gemm,   cudaFuncAttributeMaxDynamicSharedMemorySize, sm_tg);
    cudaFuncSetAttribute(ffn1_kernel,  cudaFuncAttributeMaxDynamicSharedMemorySize, sm_tg);
    cudaFuncSetAttribute(ffn2_kernel,  cudaFuncAttributeMaxDynamicSharedMemorySize, sm_f2);

    detect_kernel<<<1, 256>>>((const int*)E_idx);
    convert_kernel<<<(NEDGE + 255) / 256, 256>>>(E_idx);

    // node-phase precomputes: P1 = hV@W1[0:128] + b1 ; G1 = hV@W1[256:384]
    token_gemm<<<64, 256, sm_tg>>>(h_V, W1,            b1,      pP1);
    token_gemm<<<64, 256, sm_tg>>>(h_V, W1 + 256*NH,   nullptr, pG1);

    nodeA_kernel<<<NTOK, 256, sm_big>>>(h_V, h_E, mask_attend,
                                        W1 + 128*NH, W2, b2, W3, b3, ln1s, ln1b);

    ffn1_kernel<<<dim3(64, 4), 256, sm_tg>>>(Wi, bi);
    ffn2_kernel<<<64, 256, sm_f2>>>(Wo, bo, ln2s, ln2b, mask_V, out);

    // edge-phase precomputes from updated hV2
    token_gemm<<<64, 256, sm_tg>>>(pHV2, W11,          b11,     pP2);
    token_gemm<<<64, 256, sm_tg>>>(pHV2, W11 + 256*NH, nullptr, pG2);

    edge_kernel<<<NTOK, 256, sm_big>>>(h_E, W11 + 128*NH, W12, b12, W13, b13,
                                       ln3s, ln3b, out + (size_t)NTOK * NH);
}

// round 4
// speedup vs baseline: 2.5887x; 1.4649x over previous
#include <cuda_runtime.h>
#include <cuda_bf16.h>
#include <math.h>
#include <stdint.h>

#define NB 2
#define NL 2048
#define NK 48
#define NH 128
#define NTOK (NB*NL)
#define NEDGE (NB*NL*NK)
#define FFH 512

__device__ int   g_is64;
__device__ int   g_idx32[NEDGE];
__device__ float g_hV2[NTOK*NH];
__device__ float g_h1 [NTOK*NH];
__device__ float g_H  [NTOK*FFH];
__device__ float g_P1 [NTOK*NH];
__device__ float g_G1 [NTOK*NH];
__device__ float g_P2 [NTOK*NH];
__device__ float g_G2 [NTOK*NH];
__device__ float g_partA[NTOK*NH];
__device__ float g_partB[NTOK*NH];
// 6 matrices x (hi 34816B + lo 34816B), [k][n] rows padded to 272B
__device__ uint4 g_Wb[6*4352];

__device__ __forceinline__ float gelu_f(float x) {
    return 0.5f * x * (1.0f + erff(x * 0.7071067811865475f));
}

__device__ __forceinline__ uint32_t smem_u32(const void* p) {
    uint32_t a;
    asm("{ .reg .u64 t; cvta.to.shared.u64 t, %1; cvt.u32.u64 %0, t; }"
        : "=r"(a) : "l"(p));
    return a;
}

__device__ __forceinline__ uint32_t pack_bf16(__nv_bfloat16 a, __nv_bfloat16 b) {
    return ((uint32_t)__bfloat16_as_ushort(b) << 16) | (uint32_t)__bfloat16_as_ushort(a);
}

// split (v0,v1) -> {hi pair, lo pair}
__device__ __forceinline__ uint2 split2(float v0, float v1) {
    __nv_bfloat16 h0 = __float2bfloat16(v0), h1 = __float2bfloat16(v1);
    float r0 = v0 - __bfloat162float(h0), r1 = v1 - __bfloat162float(h1);
    return make_uint2(pack_bf16(h0, h1),
                      pack_bf16(__float2bfloat16(r0), __float2bfloat16(r1)));
}

__device__ __forceinline__ void ldm4(uint32_t r[4], uint32_t a) {
    asm volatile("ldmatrix.sync.aligned.m8n8.x4.shared.b16 {%0,%1,%2,%3}, [%4];"
        : "=r"(r[0]), "=r"(r[1]), "=r"(r[2]), "=r"(r[3]) : "r"(a));
}
__device__ __forceinline__ void ldm4t(uint32_t r[4], uint32_t a) {
    asm volatile("ldmatrix.sync.aligned.m8n8.x4.trans.shared.b16 {%0,%1,%2,%3}, [%4];"
        : "=r"(r[0]), "=r"(r[1]), "=r"(r[2]), "=r"(r[3]) : "r"(a));
}
__device__ __forceinline__ void mma_bf(float c[4], const uint32_t a[4],
                                       uint32_t b0, uint32_t b1) {
    asm volatile(
        "mma.sync.aligned.m16n8k16.row.col.f32.bf16.bf16.f32 "
        "{%0,%1,%2,%3}, {%4,%5,%6,%7}, {%8,%9}, {%0,%1,%2,%3};"
        : "+f"(c[0]), "+f"(c[1]), "+f"(c[2]), "+f"(c[3])
        : "r"(a[0]), "r"(a[1]), "r"(a[2]), "r"(a[3]), "r"(b0), "r"(b1));
}

// ---------------------------------------------------------------------------
__global__ void detect_kernel(const int* __restrict__ w) {
    int nz = 0;
    for (int i = 2 * (int)threadIdx.x + 1; i < 1024; i += 512) nz |= (w[i] != 0);
    unsigned any = __ballot_sync(0xffffffffu, nz);
    __shared__ int s[8];
    if ((threadIdx.x & 31) == 0) s[threadIdx.x >> 5] = (any != 0);
    __syncthreads();
    if (threadIdx.x == 0) {
        int a = 0;
        #pragma unroll
        for (int i = 0; i < 8; i++) a |= s[i];
        g_is64 = (a == 0);
    }
}

__global__ void convert_kernel(const void* __restrict__ e) {
    int i = blockIdx.x * blockDim.x + threadIdx.x;
    if (i >= NEDGE) return;
    if (g_is64) g_idx32[i] = (int)((const long long*)e)[i];
    else        g_idx32[i] = ((const int*)e)[i];
}

// ---------------------------------------------------------------------------
// wprep: split weights (fp32 [k][n]) into hi/lo bf16, rows padded to 272B.
// ---------------------------------------------------------------------------
__global__ void wprep_kernel(const float* W0, const float* W1, const float* W2,
                             const float* W3, const float* W4, const float* W5) {
    int gid = blockIdx.x * 256 + threadIdx.x;
    if (gid >= 6 * 16384) return;
    int m = gid >> 14, rem = gid & 16383;
    int k = rem >> 7, n = rem & 127;
    const float* W = (m == 0) ? W0 : (m == 1) ? W1 : (m == 2) ? W2
                   : (m == 3) ? W3 : (m == 4) ? W4 : W5;
    float v = W[k * 128 + n];
    __nv_bfloat16 h = __float2bfloat16(v);
    __nv_bfloat16 l = __float2bfloat16(v - __bfloat162float(h));
    char* basep = (char*)g_Wb + (size_t)m * 69632;
    uint32_t byte = (uint32_t)k * 272u + (uint32_t)n * 2u;
    *(__nv_bfloat16*)(basep + byte)         = h;
    *(__nv_bfloat16*)(basep + 34816 + byte) = l;
}

// ---------------------------------------------------------------------------
// FFMA GEMM core (token_gemm / ffn)
// ---------------------------------------------------------------------------
#define GSTEP(CMP, J) { \
    float4 bb = *(const float4*)&Wt[(kk4*4 + J)*NH + c0]; \
    _Pragma("unroll") \
    for (int r = 0; r < R; r++) { \
        float a = a4[r].CMP; \
        acc[r][0] += a * bb.x; acc[r][1] += a * bb.y; \
        acc[r][2] += a * bb.z; acc[r][3] += a * bb.w; } }

template<int R>
__device__ __forceinline__ void gemm_k128(
    const float* __restrict__ As, const float* __restrict__ Wg, int ws,
    float* Wt, int r0, int c0, int tid, float (&acc)[R][4])
{
    #pragma unroll
    for (int r = 0; r < R; r++)
        #pragma unroll
        for (int c = 0; c < 4; c++) acc[r][c] = 0.0f;

    for (int kt = 0; kt < 128; kt += 32) {
        __syncthreads();
        #pragma unroll
        for (int j = 0; j < 16; j++) {
            int i = tid + 256*j;
            Wt[i] = Wg[(kt + (i >> 7))*ws + (i & 127)];
        }
        __syncthreads();
        #pragma unroll
        for (int kk4 = 0; kk4 < 8; kk4++) {
            float4 a4[R];
            #pragma unroll
            for (int r = 0; r < R; r++)
                a4[r] = *(const float4*)&As[(r0 + r)*NH + kt + kk4*4];
            GSTEP(x, 0) GSTEP(y, 1) GSTEP(z, 2) GSTEP(w, 3)
        }
    }
}

__global__ void __launch_bounds__(256) token_gemm(
    const float* __restrict__ A, const float* __restrict__ W,
    const float* __restrict__ bias, float* __restrict__ C)
{
    extern __shared__ float smemf[];
    float* As = smemf;
    float* Wt = As + 64*NH;
    int bl0 = blockIdx.x * 64;
    int tid = threadIdx.x;
    int warp = tid >> 5, lane = tid & 31;
    int r0 = warp * 8, c0 = lane * 4;

    #pragma unroll
    for (int j = 0; j < 32; j++) As[tid + 256*j] = A[(size_t)bl0*NH + tid + 256*j];

    float acc[8][4];
    gemm_k128<8>(As, W, NH, Wt, r0, c0, tid, acc);

    float4 bv = make_float4(0.f, 0.f, 0.f, 0.f);
    if (bias) bv = *(const float4*)&bias[c0];
    #pragma unroll
    for (int r = 0; r < 8; r++) {
        float4 o4;
        o4.x = acc[r][0] + bv.x; o4.y = acc[r][1] + bv.y;
        o4.z = acc[r][2] + bv.z; o4.w = acc[r][3] + bv.w;
        *(float4*)&C[(size_t)(bl0 + r0 + r)*NH + c0] = o4;
    }
}

__global__ void __launch_bounds__(256) ffn1_kernel(
    const float* __restrict__ Wi, const float* __restrict__ bi)
{
    extern __shared__ float smemf[];
    float* As = smemf;
    float* Wt = As + 64*NH;
    int bl0 = blockIdx.x * 64;
    int nb  = blockIdx.y * 128;
    int tid = threadIdx.x;
    int warp = tid >> 5, lane = tid & 31;
    int r0 = warp * 8, c0 = lane * 4;

    #pragma unroll
    for (int j = 0; j < 32; j++) As[tid + 256*j] = g_h1[(size_t)bl0*NH + tid + 256*j];

    float acc[8][4];
    gemm_k128<8>(As, Wi + nb, FFH, Wt, r0, c0, tid, acc);

    float4 bv = *(const float4*)&bi[nb + c0];
    #pragma unroll
    for (int r = 0; r < 8; r++) {
        float4 o4;
        o4.x = gelu_f(acc[r][0] + bv.x); o4.y = gelu_f(acc[r][1] + bv.y);
        o4.z = gelu_f(acc[r][2] + bv.z); o4.w = gelu_f(acc[r][3] + bv.w);
        *(float4*)&g_H[(size_t)(bl0 + r0 + r)*FFH + nb + c0] = o4;
    }
}

__global__ void __launch_bounds__(256) ffn2_kernel(
    const float* __restrict__ Wo, const float* __restrict__ bo,
    const float* __restrict__ ln2s, const float* __restrict__ ln2b,
    const float* __restrict__ mask_V, float* __restrict__ out_hV)
{
    extern __shared__ float smemf[];
    float* At = smemf;
    float* Wt = At + 64*32;
    int bl0 = blockIdx.x * 64;
    int tid = threadIdx.x;
    int warp = tid >> 5, lane = tid & 31;
    int r0 = warp * 8, c0 = lane * 4;

    float acc[8][4];
    #pragma unroll
    for (int r = 0; r < 8; r++)
        #pragma unroll
        for (int c = 0; c < 4; c++) acc[r][c] = 0.0f;

    for (int kt = 0; kt < FFH; kt += 32) {
        __syncthreads();
        #pragma unroll
        for (int j = 0; j < 8; j++) {
            int i = tid + 256*j;
            At[i] = g_H[(size_t)(bl0 + (i >> 5))*FFH + kt + (i & 31)];
        }
        #pragma unroll
        for (int j = 0; j < 16; j++) {
            int i = tid + 256*j;
            Wt[i] = Wo[(kt + (i >> 7))*NH + (i & 127)];
        }
        __syncthreads();
        #pragma unroll
        for (int kk4 = 0; kk4 < 8; kk4++) {
            float4 a4[8];
            #pragma unroll
            for (int r = 0; r < 8; r++)
                a4[r] = *(const float4*)&At[(r0 + r)*32 + kk4*4];
            {
                const int R = 8;
                GSTEP(x, 0) GSTEP(y, 1) GSTEP(z, 2) GSTEP(w, 3)
            }
        }
    }

    float4 bv  = *(const float4*)&bo[c0];
    float4 g2s = *(const float4*)&ln2s[c0];
    float4 g2b = *(const float4*)&ln2b[c0];
    #pragma unroll
    for (int r = 0; r < 8; r++) {
        int token = bl0 + r0 + r;
        float4 hv = *(const float4*)&g_h1[(size_t)token*NH + c0];
        float v0 = hv.x + acc[r][0] + bv.x;
        float v1 = hv.y + acc[r][1] + bv.y;
        float v2 = hv.z + acc[r][2] + bv.z;
        float v3 = hv.w + acc[r][3] + bv.w;
        float s1 = v0 + v1 + v2 + v3;
        float s2 = v0*v0 + v1*v1 + v2*v2 + v3*v3;
        #pragma unroll
        for (int o = 16; o; o >>= 1) {
            s1 += __shfl_xor_sync(0xffffffffu, s1, o);
            s2 += __shfl_xor_sync(0xffffffffu, s2, o);
        }
        float mu = s1 * (1.0f / NH);
        float var = s2 * (1.0f / NH) - mu * mu;
        float rinv = rsqrtf(var + 1e-5f);
        float mk = mask_V[token];
        float4 o4;
        o4.x = ((v0 - mu) * rinv * g2s.x + g2b.x) * mk;
        o4.y = ((v1 - mu) * rinv * g2s.y + g2b.y) * mk;
        o4.z = ((v2 - mu) * rinv * g2s.z + g2b.z) * mk;
        o4.w = ((v3 - mu) * rinv * g2s.w + g2b.w) * mk;
        *(float4*)&g_hV2[(size_t)token*NH + c0] = o4;
        *(float4*)&out_hV[(size_t)token*NH + c0] = o4;
    }
}

// ---------------------------------------------------------------------------
// nodeLN: gather 2-slot partials, scale, residual, LN1 -> g_h1
// ---------------------------------------------------------------------------
__global__ void nodeLN_kernel(const float* __restrict__ hV,
                              const float* __restrict__ ln1s,
                              const float* __restrict__ ln1b)
{
    int t = blockIdx.x, c = threadIdx.x;   // 128 threads
    int s0 = t * 48;
    float p = g_partA[(size_t)t*NH + c];
    if (s0 / 128 != (s0 + 47) / 128) p += g_partB[(size_t)t*NH + c];
    float x = hV[(size_t)t*NH + c] + p * (1.0f / 30.0f);
    float a = x, b = x * x;
    #pragma unroll
    for (int o = 16; o; o >>= 1) {
        a += __shfl_xor_sync(0xffffffffu, a, o);
        b += __shfl_xor_sync(0xffffffffu, b, o);
    }
    __shared__ float sA[4], sB[4];
    int w = c >> 5, l = c & 31;
    if (l == 0) { sA[w] = a; sB[w] = b; }
    __syncthreads();
    float sum = sA[0] + sA[1] + sA[2] + sA[3];
    float ssq = sB[0] + sB[1] + sB[2] + sB[3];
    float mu = sum * (1.0f / NH);
    float var = ssq * (1.0f / NH) - mu * mu;
    float ri = rsqrtf(var + 1e-5f);
    g_h1[(size_t)t*NH + c] = (x - mu) * ri * ln1s[c] + ln1b[c];
}

// ---------------------------------------------------------------------------
// mlp3 (mma.sync): 128 rows x 128 cols per CTA, 3 chained layers, hi/lo split.
// MODE 0 = node (mask + K-sum partials), MODE 1 = edge (residual + LN3 + out)
// ---------------------------------------------------------------------------
#define AST 272
#define OFF_AHI 0
#define OFF_ALO 34816
#define OFF_BHI 69632
#define OFF_BLO 104448
#define OFF_STAT 139264
#define SMEM_MLP3 141312

__device__ __forceinline__ void copyB(char* sm, int mat) {
    const uint4* src = &g_Wb[(size_t)mat * 4352];
    uint4* dst = (uint4*)(sm + OFF_BHI);
    #pragma unroll
    for (int i = 0; i < 17; i++) dst[threadIdx.x + 256*i] = src[threadIdx.x + 256*i];
}

__device__ __forceinline__ void mma_layer(uint32_t sb, int warpM, int warpN,
                                          int lane, float (&acc)[2][8][4]) {
    #pragma unroll
    for (int m = 0; m < 2; m++)
        #pragma unroll
        for (int j = 0; j < 8; j++)
            #pragma unroll
            for (int c = 0; c < 4; c++) acc[m][j][c] = 0.0f;

    uint32_t aHi = sb + OFF_AHI + (uint32_t)(warpM*32 + (lane & 15))*AST
                 + (uint32_t)(lane >> 4)*16;
    uint32_t aLo = aHi + (OFF_ALO - OFF_AHI);
    uint32_t bHi = sb + OFF_BHI + (uint32_t)(lane & 15)*AST
                 + (uint32_t)(warpN*8 + (lane >> 4))*16;
    uint32_t bLo = bHi + (OFF_BLO - OFF_BHI);

    #pragma unroll
    for (int ks = 0; ks < 8; ks++) {
        uint32_t ah0[4], ah1[4], al0[4], al1[4];
        ldm4(ah0, aHi + ks*32);
        ldm4(ah1, aHi + ks*32 + 16*AST);
        ldm4(al0, aLo + ks*32);
        ldm4(al1, aLo + ks*32 + 16*AST);
        #pragma unroll
        for (int ng = 0; ng < 4; ng++) {
            uint32_t bh[4], bl[4];
            ldm4t(bh, bHi + ks*16*AST + ng*32);
            ldm4t(bl, bLo + ks*16*AST + ng*32);
            mma_bf(acc[0][2*ng],   ah0, bh[0], bh[1]);
            mma_bf(acc[1][2*ng],   ah1, bh[0], bh[1]);
            mma_bf(acc[0][2*ng+1], ah0, bh[2], bh[3]);
            mma_bf(acc[1][2*ng+1], ah1, bh[2], bh[3]);
            mma_bf(acc[0][2*ng],   al0, bh[0], bh[1]);
            mma_bf(acc[1][2*ng],   al1, bh[0], bh[1]);
            mma_bf(acc[0][2*ng+1], al0, bh[2], bh[3]);
            mma_bf(acc[1][2*ng+1], al1, bh[2], bh[3]);
            mma_bf(acc[0][2*ng],   ah0, bl[0], bl[1]);
            mma_bf(acc[1][2*ng],   ah1, bl[0], bl[1]);
            mma_bf(acc[0][2*ng+1], ah0, bl[2], bl[3]);
            mma_bf(acc[1][2*ng+1], ah1, bl[2], bl[3]);
        }
    }
}

template<int MODE>
__global__ void __launch_bounds__(256, 1) mlp3_kernel(
    const float* __restrict__ hE,
    const float* __restrict__ P, const float* __restrict__ G,
    const float* __restrict__ bias2, const float* __restrict__ bias3,
    const float* __restrict__ mask_attend,
    const float* __restrict__ ln3s, const float* __restrict__ ln3b,
    float* __restrict__ out_hE, int matBase)
{
    extern __shared__ char sm[];
    uint32_t sb = smem_u32(sm);

    int tid = threadIdx.x;
    int wid = tid >> 5, lane = tid & 31;
    int warpM = wid & 3, warpN = wid >> 2;
    int qr = lane >> 2, qc = lane & 3;
    int e0 = blockIdx.x * 128;
    int cBase = warpN*64 + 2*qc;

    // rows owned by this thread: R[mf][h]
    int Row[2][2];
    #pragma unroll
    for (int mf = 0; mf < 2; mf++)
        #pragma unroll
        for (int h = 0; h < 2; h++)
            Row[mf][h] = warpM*32 + mf*16 + h*8 + qr;

    // build A0 = hE rows split hi/lo
    for (int idx = tid; idx < 128*64; idx += 256) {
        int r = idx >> 6, cp = idx & 63;
        float2 x = *(const float2*)&hE[(size_t)(e0 + r)*NH + cp*2];
        uint2 s = split2(x.x, x.y);
        *(uint32_t*)(sm + OFF_AHI + r*AST + cp*4) = s.x;
        *(uint32_t*)(sm + OFF_ALO + r*AST + cp*4) = s.y;
    }
    copyB(sm, matBase + 0);
    __syncthreads();

    float acc[2][8][4];

    // ---- layer 1 ----
    mma_layer(sb, warpM, warpN, lane, acc);
    __syncthreads();
    {
        const float* Pr[2][2];
        const float* Gr[2][2];
        #pragma unroll
        for (int mf = 0; mf < 2; mf++)
            #pragma unroll
            for (int h = 0; h < 2; h++) {
                int e = e0 + Row[mf][h];
                int tok = e / 48;
                int batch = (e >= NL*NK) ? 1 : 0;
                Pr[mf][h] = P + (size_t)tok * NH;
                Gr[mf][h] = G + (size_t)(batch*NL + g_idx32[e]) * NH;
            }
        #pragma unroll
        for (int mf = 0; mf < 2; mf++)
            #pragma unroll
            for (int j = 0; j < 8; j++) {
                int C = cBase + j*8;
                #pragma unroll
                for (int h = 0; h < 2; h++) {
                    float2 pv = *(const float2*)&Pr[mf][h][C];
                    float2 gv = *(const float2*)&Gr[mf][h][C];
                    float v0 = gelu_f(acc[mf][j][2*h+0] + pv.x + gv.x);
                    float v1 = gelu_f(acc[mf][j][2*h+1] + pv.y + gv.y);
                    uint2 s = split2(v0, v1);
                    int R = Row[mf][h];
                    *(uint32_t*)(sm + OFF_AHI + R*AST + C*2) = s.x;
                    *(uint32_t*)(sm + OFF_ALO + R*AST + C*2) = s.y;
                }
            }
    }
    copyB(sm, matBase + 1);
    __syncthreads();

    // ---- layer 2 ----
    mma_layer(sb, warpM, warpN, lane, acc);
    __syncthreads();
    #pragma unroll
    for (int mf = 0; mf < 2; mf++)
        #pragma unroll
        for (int j = 0; j < 8; j++) {
            int C = cBase + j*8;
            float2 bv = *(const float2*)&bias2[C];
            #pragma unroll
            for (int h = 0; h < 2; h++) {
                float v0 = gelu_f(acc[mf][j][2*h+0] + bv.x);
                float v1 = gelu_f(acc[mf][j][2*h+1] + bv.y);
                uint2 s = split2(v0, v1);
                int R = Row[mf][h];
                *(uint32_t*)(sm + OFF_AHI + R*AST + C*2) = s.x;
                *(uint32_t*)(sm + OFF_ALO + R*AST + C*2) = s.y;
            }
        }
    copyB(sm, matBase + 2);
    __syncthreads();

    // ---- layer 3 ----
    mma_layer(sb, warpM, warpN, lane, acc);
    __syncthreads();

    if (MODE == 0) {
        float* stage = (float*)(sm + OFF_BHI);  // [128][136] f32, aliases B
        #pragma unroll
        for (int mf = 0; mf < 2; mf++)
            #pragma unroll
            for (int h = 0; h < 2; h++) {
                int R = Row[mf][h];
                float mk = mask_attend[e0 + R];
                #pragma unroll
                for (int j = 0; j < 8; j++) {
                    int C = cBase + j*8;
                    float2 bv = *(const float2*)&bias3[C];
                    float2 o2;
                    o2.x = (acc[mf][j][2*h+0] + bv.x) * mk;
                    o2.y = (acc[mf][j][2*h+1] + bv.y) * mk;
                    *(float2*)&stage[R*136 + C] = o2;
                }
            }
        __syncthreads();
        int t0 = e0 / 48;
        int tend = (e0 + 127) / 48;
        for (int t = t0 + (tid >> 7); t <= tend; t += 2) {
            int col = tid & 127;
            int rs = max(t*48 - e0, 0), re = min(t*48 + 47 - e0, 127);
            float sacc = 0.0f;
            for (int rr = rs; rr <= re; rr++) sacc += stage[rr*136 + col];
            if (t*48 >= e0) g_partA[(size_t)t*NH + col] = sacc;
            else            g_partB[(size_t)t*NH + col] = sacc;
        }
    } else {
        // residual + bias, row stats via quad shuffle + cross-warpN combine
        float* stats = (float*)(sm + OFF_STAT);  // [2 warpN][128 rows][2]
        float s1[2][2], s2[2][2];
        #pragma unroll
        for (int mf = 0; mf < 2; mf++)
            #pragma unroll
            for (int h = 0; h < 2; h++) { s1[mf][h] = 0.f; s2[mf][h] = 0.f; }
        #pragma unroll
        for (int mf = 0; mf < 2; mf++)
            #pragma unroll
            for (int j = 0; j < 8; j++) {
                int C = cBase + j*8;
                float2 bv = *(const float2*)&bias3[C];
                #pragma unroll
                for (int h = 0; h < 2; h++) {
                    int R = Row[mf][h];
                    float2 he = *(const float2*)&hE[(size_t)(e0 + R)*NH + C];
                    float v0 = acc[mf][j][2*h+0] + bv.x + he.x;
                    float v1 = acc[mf][j][2*h+1] + bv.y + he.y;
                    acc[mf][j][2*h+0] = v0;
                    acc[mf][j][2*h+1] = v1;
                    s1[mf][h] += v0 + v1;
                    s2[mf][h] += v0*v0 + v1*v1;
                }
            }
        #pragma unroll
        for (int mf = 0; mf < 2; mf++)
            #pragma unroll
            for (int h = 0; h < 2; h++) {
                #pragma unroll
                for (int o = 1; o < 4; o <<= 1) {
                    s1[mf][h] += __shfl_xor_sync(0xffffffffu, s1[mf][h], o);
                    s2[mf][h] += __shfl_xor_sync(0xffffffffu, s2[mf][h], o);
                }
                if (qc == 0) {
                    stats[(warpN*128 + Row[mf][h])*2 + 0] = s1[mf][h];
                    stats[(warpN*128 + Row[mf][h])*2 + 1] = s2[mf][h];
                }
            }
        __syncthreads();
        #pragma unroll
        for (int mf = 0; mf < 2; mf++)
            #pragma unroll
            for (int h = 0; h < 2; h++) {
                int R = Row[mf][h];
                float S1 = stats[R*2] + stats[(128 + R)*2];
                float S2 = stats[R*2 + 1] + stats[(128 + R)*2 + 1];
                float mu = S1 * (1.0f / NH);
                float var = S2 * (1.0f / NH) - mu * mu;
                float rinv = rsqrtf(var + 1e-5f);
                #pragma unroll
                for (int j = 0; j < 8; j++) {
                    int C = cBase + j*8;
                    float2 gs = *(const float2*)&ln3s[C];
                    float2 gb = *(const float2*)&ln3b[C];
                    float2 o2;
                    o2.x = (acc[mf][j][2*h+0] - mu) * rinv * gs.x + gb.x;
                    o2.y = (acc[mf][j][2*h+1] - mu) * rinv * gs.y + gb.y;
                    *(float2*)&out_hE[(size_t)(e0 + R)*NH + C] = o2;
                }
            }
    }
}

// ---------------------------------------------------------------------------

extern "C" void kernel_launch(void* const* d_in, const int* in_sizes, int n_in,
                              void* d_out, int out_size)
{
    const float* h_V         = (const float*)d_in[0];
    const float* h_E         = (const float*)d_in[1];
    const void*  E_idx       =               d_in[2];
    const float* mask_V      = (const float*)d_in[3];
    const float* mask_attend = (const float*)d_in[4];
    const float* W1  = (const float*)d_in[5],  *b1  = (const float*)d_in[6];
    const float* W2  = (const float*)d_in[7],  *b2  = (const float*)d_in[8];
    const float* W3  = (const float*)d_in[9],  *b3  = (const float*)d_in[10];
    const float* W11 = (const float*)d_in[11], *b11 = (const float*)d_in[12];
    const float* W12 = (const float*)d_in[13], *b12 = (const float*)d_in[14];
    const float* W13 = (const float*)d_in[15], *b13 = (const float*)d_in[16];
    const float* Wi  = (const float*)d_in[17], *bi  = (const float*)d_in[18];
    const float* Wo  = (const float*)d_in[19], *bo  = (const float*)d_in[20];
    const float* ln1s = (const float*)d_in[21], *ln1b = (const float*)d_in[22];
    const float* ln2s = (const float*)d_in[23], *ln2b = (const float*)d_in[24];
    const float* ln3s = (const float*)d_in[25], *ln3b = (const float*)d_in[26];
    float* out = (float*)d_out;

    float *pP1, *pG1, *pP2, *pG2, *pHV2;
    cudaGetSymbolAddress((void**)&pP1,  g_P1);
    cudaGetSymbolAddress((void**)&pG1,  g_G1);
    cudaGetSymbolAddress((void**)&pP2,  g_P2);
    cudaGetSymbolAddress((void**)&pG2,  g_G2);
    cudaGetSymbolAddress((void**)&pHV2, g_hV2);

    int sm_tg = (64*NH + 32*NH) * (int)sizeof(float);
    int sm_f2 = (64*32 + 32*NH) * (int)sizeof(float);

    cudaFuncSetAttribute(token_gemm,  cudaFuncAttributeMaxDynamicSharedMemorySize, sm_tg);
    cudaFuncSetAttribute(ffn1_kernel, cudaFuncAttributeMaxDynamicSharedMemorySize, sm_tg);
    cudaFuncSetAttribute(ffn2_kernel, cudaFuncAttributeMaxDynamicSharedMemorySize, sm_f2);
    cudaFuncSetAttribute(mlp3_kernel<0>, cudaFuncAttributeMaxDynamicSharedMemorySize, SMEM_MLP3);
    cudaFuncSetAttribute(mlp3_kernel<1>, cudaFuncAttributeMaxDynamicSharedMemorySize, SMEM_MLP3);

    detect_kernel<<<1, 256>>>((const int*)E_idx);
    convert_kernel<<<(NEDGE + 255) / 256, 256>>>(E_idx);

    // mats 0-2: node (W1E, W2, W3); 3-5: edge (W11E, W12, W13)
    wprep_kernel<<<(6*16384 + 255)/256, 256>>>(W1 + 128*NH, W2, W3,
                                               W11 + 128*NH, W12, W13);

    token_gemm<<<64, 256, sm_tg>>>(h_V, W1,          b1,      pP1);
    token_gemm<<<64, 256, sm_tg>>>(h_V, W1 + 256*NH, nullptr, pG1);

    mlp3_kernel<0><<<NEDGE/128, 256, SMEM_MLP3>>>(h_E, pP1, pG1, b2, b3,
                                                  mask_attend, nullptr, nullptr,
                                                  nullptr, 0);
    nodeLN_kernel<<<NTOK, 128>>>(h_V, ln1s, ln1b);

    ffn1_kernel<<<dim3(64, 4), 256, sm_tg>>>(Wi, bi);
    ffn2_kernel<<<64, 256, sm_f2>>>(Wo, bo, ln2s, ln2b, mask_V, out);

    token_gemm<<<64, 256, sm_tg>>>(pHV2, W11,          b11,     pP2);
    token_gemm<<<64, 256, sm_tg>>>(pHV2, W11 + 256*NH, nullptr, pG2);

    mlp3_kernel<1><<<NEDGE/128, 256, SMEM_MLP3>>>(h_E, pP2, pG2, b12, b13,
                                                  nullptr, ln3s, ln3b,
                                                  out + (size_t)NTOK * NH, 3);
}

// round 5
// speedup vs baseline: 3.1479x; 1.2160x over previous
#include <cuda_runtime.h>
#include <cuda_fp16.h>
#include <math.h>
#include <stdint.h>

#define NB 2
#define NL 2048
#define NK 48
#define NH 128
#define NTOK (NB*NL)
#define NEDGE (NB*NL*NK)
#define FFH 512

__device__ int   g_is64;
__device__ int   g_idx32[NEDGE];
__device__ float g_hV2[NTOK*NH];
__device__ float g_h1 [NTOK*NH];
__device__ float g_H  [NTOK*FFH];
__device__ float g_P1 [NTOK*NH];
__device__ float g_G1 [NTOK*NH];
__device__ float g_P2 [NTOK*NH];
__device__ float g_G2 [NTOK*NH];
__device__ float g_partA[NTOK*NH];
__device__ float g_partB[NTOK*NH];
// 6 matrices fp16 [k][n], rows padded to 272B -> 34816 B = 2176 uint4 each
__device__ uint4 g_Wb[6*2176];

__device__ __forceinline__ float gelu_f(float x) {
    return 0.5f * x * (1.0f + erff(x * 0.7071067811865475f));
}

__device__ __forceinline__ uint32_t smem_u32(const void* p) {
    uint32_t a;
    asm("{ .reg .u64 t; cvta.to.shared.u64 t, %1; cvt.u32.u64 %0, t; }"
        : "=r"(a) : "l"(p));
    return a;
}

__device__ __forceinline__ uint32_t pack_f16(float v0, float v1) {
    __half2 h = __floats2half2_rn(v0, v1);
    return *(uint32_t*)&h;
}

// split (v0,v1) -> {hi fp16 pair, lo fp16 pair}
__device__ __forceinline__ uint2 split2(float v0, float v1) {
    __half h0 = __float2half_rn(v0), h1 = __float2half_rn(v1);
    float r0 = v0 - __half2float(h0), r1 = v1 - __half2float(h1);
    uint32_t hi = ((uint32_t)__half_as_ushort(h1) << 16) | (uint32_t)__half_as_ushort(h0);
    return make_uint2(hi, pack_f16(r0, r1));
}

__device__ __forceinline__ void ldm4(uint32_t r[4], uint32_t a) {
    asm volatile("ldmatrix.sync.aligned.m8n8.x4.shared.b16 {%0,%1,%2,%3}, [%4];"
        : "=r"(r[0]), "=r"(r[1]), "=r"(r[2]), "=r"(r[3]) : "r"(a));
}
__device__ __forceinline__ void ldm4t(uint32_t r[4], uint32_t a) {
    asm volatile("ldmatrix.sync.aligned.m8n8.x4.trans.shared.b16 {%0,%1,%2,%3}, [%4];"
        : "=r"(r[0]), "=r"(r[1]), "=r"(r[2]), "=r"(r[3]) : "r"(a));
}
__device__ __forceinline__ void mma_f16(float c[4], const uint32_t a[4],
                                        uint32_t b0, uint32_t b1) {
    asm volatile(
        "mma.sync.aligned.m16n8k16.row.col.f32.f16.f16.f32 "
        "{%0,%1,%2,%3}, {%4,%5,%6,%7}, {%8,%9}, {%0,%1,%2,%3};"
        : "+f"(c[0]), "+f"(c[1]), "+f"(c[2]), "+f"(c[3])
        : "r"(a[0]), "r"(a[1]), "r"(a[2]), "r"(a[3]), "r"(b0), "r"(b1));
}

// ---------------------------------------------------------------------------
__global__ void detect_kernel(const int* __restrict__ w) {
    int nz = 0;
    for (int i = 2 * (int)threadIdx.x + 1; i < 1024; i += 512) nz |= (w[i] != 0);
    unsigned any = __ballot_sync(0xffffffffu, nz);
    __shared__ int s[8];
    if ((threadIdx.x & 31) == 0) s[threadIdx.x >> 5] = (any != 0);
    __syncthreads();
    if (threadIdx.x == 0) {
        int a = 0;
        #pragma unroll
        for (int i = 0; i < 8; i++) a |= s[i];
        g_is64 = (a == 0);
    }
}

__global__ void convert_kernel(const void* __restrict__ e) {
    int i = blockIdx.x * blockDim.x + threadIdx.x;
    if (i >= NEDGE) return;
    if (g_is64) g_idx32[i] = (int)((const long long*)e)[i];
    else        g_idx32[i] = ((const int*)e)[i];
}

// ---------------------------------------------------------------------------
// wprep: weights (fp32 [k][n]) -> fp16, rows padded to 272B.
// ---------------------------------------------------------------------------
__global__ void wprep_kernel(const float* W0, const float* W1, const float* W2,
                             const float* W3, const float* W4, const float* W5) {
    int gid = blockIdx.x * 256 + threadIdx.x;
    if (gid >= 6 * 16384) return;
    int m = gid >> 14, rem = gid & 16383;
    int k = rem >> 7, n = rem & 127;
    const float* W = (m == 0) ? W0 : (m == 1) ? W1 : (m == 2) ? W2
                   : (m == 3) ? W3 : (m == 4) ? W4 : W5;
    float v = W[k * 128 + n];
    char* basep = (char*)g_Wb + (size_t)m * 34816;
    *(__half*)(basep + (uint32_t)k * 272u + (uint32_t)n * 2u) = __float2half_rn(v);
}

// ---------------------------------------------------------------------------
// FFMA GEMM core (token_gemm / ffn)
// ---------------------------------------------------------------------------
#define GSTEP(CMP, J) { \
    float4 bb = *(const float4*)&Wt[(kk4*4 + J)*NH + c0]; \
    _Pragma("unroll") \
    for (int r = 0; r < R; r++) { \
        float a = a4[r].CMP; \
        acc[r][0] += a * bb.x; acc[r][1] += a * bb.y; \
        acc[r][2] += a * bb.z; acc[r][3] += a * bb.w; } }

template<int R>
__device__ __forceinline__ void gemm_k128(
    const float* __restrict__ As, const float* __restrict__ Wg, int ws,
    float* Wt, int r0, int c0, int tid, float (&acc)[R][4])
{
    #pragma unroll
    for (int r = 0; r < R; r++)
        #pragma unroll
        for (int c = 0; c < 4; c++) acc[r][c] = 0.0f;

    for (int kt = 0; kt < 128; kt += 32) {
        __syncthreads();
        #pragma unroll
        for (int j = 0; j < 16; j++) {
            int i = tid + 256*j;
            Wt[i] = Wg[(kt + (i >> 7))*ws + (i & 127)];
        }
        __syncthreads();
        #pragma unroll
        for (int kk4 = 0; kk4 < 8; kk4++) {
            float4 a4[R];
            #pragma unroll
            for (int r = 0; r < R; r++)
                a4[r] = *(const float4*)&As[(r0 + r)*NH + kt + kk4*4];
            GSTEP(x, 0) GSTEP(y, 1) GSTEP(z, 2) GSTEP(w, 3)
        }
    }
}

__global__ void __launch_bounds__(256) token_gemm(
    const float* __restrict__ A, const float* __restrict__ W,
    const float* __restrict__ bias, float* __restrict__ C)
{
    extern __shared__ float smemf[];
    float* As = smemf;
    float* Wt = As + 64*NH;
    int bl0 = blockIdx.x * 64;
    int tid = threadIdx.x;
    int warp = tid >> 5, lane = tid & 31;
    int r0 = warp * 8, c0 = lane * 4;

    #pragma unroll
    for (int j = 0; j < 32; j++) As[tid + 256*j] = A[(size_t)bl0*NH + tid + 256*j];

    float acc[8][4];
    gemm_k128<8>(As, W, NH, Wt, r0, c0, tid, acc);

    float4 bv = make_float4(0.f, 0.f, 0.f, 0.f);
    if (bias) bv = *(const float4*)&bias[c0];
    #pragma unroll
    for (int r = 0; r < 8; r++) {
        float4 o4;
        o4.x = acc[r][0] + bv.x; o4.y = acc[r][1] + bv.y;
        o4.z = acc[r][2] + bv.z; o4.w = acc[r][3] + bv.w;
        *(float4*)&C[(size_t)(bl0 + r0 + r)*NH + c0] = o4;
    }
}

__global__ void __launch_bounds__(256) ffn1_kernel(
    const float* __restrict__ Wi, const float* __restrict__ bi)
{
    extern __shared__ float smemf[];
    float* As = smemf;
    float* Wt = As + 64*NH;
    int bl0 = blockIdx.x * 64;
    int nb  = blockIdx.y * 128;
    int tid = threadIdx.x;
    int warp = tid >> 5, lane = tid & 31;
    int r0 = warp * 8, c0 = lane * 4;

    #pragma unroll
    for (int j = 0; j < 32; j++) As[tid + 256*j] = g_h1[(size_t)bl0*NH + tid + 256*j];

    float acc[8][4];
    gemm_k128<8>(As, Wi + nb, FFH, Wt, r0, c0, tid, acc);

    float4 bv = *(const float4*)&bi[nb + c0];
    #pragma unroll
    for (int r = 0; r < 8; r++) {
        float4 o4;
        o4.x = gelu_f(acc[r][0] + bv.x); o4.y = gelu_f(acc[r][1] + bv.y);
        o4.z = gelu_f(acc[r][2] + bv.z); o4.w = gelu_f(acc[r][3] + bv.w);
        *(float4*)&g_H[(size_t)(bl0 + r0 + r)*FFH + nb + c0] = o4;
    }
}

__global__ void __launch_bounds__(256) ffn2_kernel(
    const float* __restrict__ Wo, const float* __restrict__ bo,
    const float* __restrict__ ln2s, const float* __restrict__ ln2b,
    const float* __restrict__ mask_V, float* __restrict__ out_hV)
{
    extern __shared__ float smemf[];
    float* At = smemf;
    float* Wt = At + 64*32;
    int bl0 = blockIdx.x * 64;
    int tid = threadIdx.x;
    int warp = tid >> 5, lane = tid & 31;
    int r0 = warp * 8, c0 = lane * 4;

    float acc[8][4];
    #pragma unroll
    for (int r = 0; r < 8; r++)
        #pragma unroll
        for (int c = 0; c < 4; c++) acc[r][c] = 0.0f;

    for (int kt = 0; kt < FFH; kt += 32) {
        __syncthreads();
        #pragma unroll
        for (int j = 0; j < 8; j++) {
            int i = tid + 256*j;
            At[i] = g_H[(size_t)(bl0 + (i >> 5))*FFH + kt + (i & 31)];
        }
        #pragma unroll
        for (int j = 0; j < 16; j++) {
            int i = tid + 256*j;
            Wt[i] = Wo[(kt + (i >> 7))*NH + (i & 127)];
        }
        __syncthreads();
        #pragma unroll
        for (int kk4 = 0; kk4 < 8; kk4++) {
            float4 a4[8];
            #pragma unroll
            for (int r = 0; r < 8; r++)
                a4[r] = *(const float4*)&At[(r0 + r)*32 + kk4*4];
            {
                const int R = 8;
                GSTEP(x, 0) GSTEP(y, 1) GSTEP(z, 2) GSTEP(w, 3)
            }
        }
    }

    float4 bv  = *(const float4*)&bo[c0];
    float4 g2s = *(const float4*)&ln2s[c0];
    float4 g2b = *(const float4*)&ln2b[c0];
    #pragma unroll
    for (int r = 0; r < 8; r++) {
        int token = bl0 + r0 + r;
        float4 hv = *(const float4*)&g_h1[(size_t)token*NH + c0];
        float v0 = hv.x + acc[r][0] + bv.x;
        float v1 = hv.y + acc[r][1] + bv.y;
        float v2 = hv.z + acc[r][2] + bv.z;
        float v3 = hv.w + acc[r][3] + bv.w;
        float s1 = v0 + v1 + v2 + v3;
        float s2 = v0*v0 + v1*v1 + v2*v2 + v3*v3;
        #pragma unroll
        for (int o = 16; o; o >>= 1) {
            s1 += __shfl_xor_sync(0xffffffffu, s1, o);
            s2 += __shfl_xor_sync(0xffffffffu, s2, o);
        }
        float mu = s1 * (1.0f / NH);
        float var = s2 * (1.0f / NH) - mu * mu;
        float rinv = rsqrtf(var + 1e-5f);
        float mk = mask_V[token];
        float4 o4;
        o4.x = ((v0 - mu) * rinv * g2s.x + g2b.x) * mk;
        o4.y = ((v1 - mu) * rinv * g2s.y + g2b.y) * mk;
        o4.z = ((v2 - mu) * rinv * g2s.z + g2b.z) * mk;
        o4.w = ((v3 - mu) * rinv * g2s.w + g2b.w) * mk;
        *(float4*)&g_hV2[(size_t)token*NH + c0] = o4;
        *(float4*)&out_hV[(size_t)token*NH + c0] = o4;
    }
}

// ---------------------------------------------------------------------------
// nodeLN: gather 2-slot partials, scale, residual, LN1 -> g_h1
// ---------------------------------------------------------------------------
__global__ void nodeLN_kernel(const float* __restrict__ hV,
                              const float* __restrict__ ln1s,
                              const float* __restrict__ ln1b)
{
    int t = blockIdx.x, c = threadIdx.x;   // 128 threads
    int s0 = t * 48;
    float p = g_partA[(size_t)t*NH + c];
    if (s0 / 128 != (s0 + 47) / 128) p += g_partB[(size_t)t*NH + c];
    float x = hV[(size_t)t*NH + c] + p * (1.0f / 30.0f);
    float a = x, b = x * x;
    #pragma unroll
    for (int o = 16; o; o >>= 1) {
        a += __shfl_xor_sync(0xffffffffu, a, o);
        b += __shfl_xor_sync(0xffffffffu, b, o);
    }
    __shared__ float sA[4], sB[4];
    int w = c >> 5, l = c & 31;
    if (l == 0) { sA[w] = a; sB[w] = b; }
    __syncthreads();
    float sum = sA[0] + sA[1] + sA[2] + sA[3];
    float ssq = sB[0] + sB[1] + sB[2] + sB[3];
    float mu = sum * (1.0f / NH);
    float var = ssq * (1.0f / NH) - mu * mu;
    float ri = rsqrtf(var + 1e-5f);
    g_h1[(size_t)t*NH + c] = (x - mu) * ri * ln1s[c] + ln1b[c];
}

// ---------------------------------------------------------------------------
// mlp3 (mma.sync fp16 2-pass): 128 rows x 128 cols per CTA, 3 chained layers.
// A split hi/lo fp16; B single fp16. Dropped term ~2^-11 relative.
// MODE 0 = node (mask + K-sum partials), MODE 1 = edge (residual + LN3 + out)
// ---------------------------------------------------------------------------
#define AST 272
#define OFF_AHI 0
#define OFF_ALO 34816
#define OFF_B   69632
#define OFF_STAT 104448
#define SMEM_MLP3 106496

__device__ __forceinline__ void copyB(char* sm, int mat) {
    const uint4* src = &g_Wb[(size_t)mat * 2176];
    uint4* dst = (uint4*)(sm + OFF_B);
    #pragma unroll
    for (int i = 0; i < 9; i++) {
        int idx = threadIdx.x + 256*i;
        if (idx < 2176) dst[idx] = src[idx];
    }
}

__device__ __forceinline__ void mma_layer(uint32_t sb, int warpM, int warpN,
                                          int lane, float (&acc)[2][8][4]) {
    #pragma unroll
    for (int m = 0; m < 2; m++)
        #pragma unroll
        for (int j = 0; j < 8; j++)
            #pragma unroll
            for (int c = 0; c < 4; c++) acc[m][j][c] = 0.0f;

    uint32_t aHi = sb + OFF_AHI + (uint32_t)(warpM*32 + (lane & 15))*AST
                 + (uint32_t)(lane >> 4)*16;
    uint32_t aLo = aHi + (OFF_ALO - OFF_AHI);
    uint32_t bB  = sb + OFF_B + (uint32_t)(lane & 15)*AST
                 + (uint32_t)(warpN*8 + (lane >> 4))*16;

    #pragma unroll
    for (int ks = 0; ks < 8; ks++) {
        uint32_t ah0[4], ah1[4], al0[4], al1[4];
        ldm4(ah0, aHi + ks*32);
        ldm4(ah1, aHi + ks*32 + 16*AST);
        ldm4(al0, aLo + ks*32);
        ldm4(al1, aLo + ks*32 + 16*AST);
        #pragma unroll
        for (int ng = 0; ng < 4; ng++) {
            uint32_t bh[4];
            ldm4t(bh, bB + ks*16*AST + ng*32);
            mma_f16(acc[0][2*ng],   ah0, bh[0], bh[1]);
            mma_f16(acc[1][2*ng],   ah1, bh[0], bh[1]);
            mma_f16(acc[0][2*ng+1], ah0, bh[2], bh[3]);
            mma_f16(acc[1][2*ng+1], ah1, bh[2], bh[3]);
            mma_f16(acc[0][2*ng],   al0, bh[0], bh[1]);
            mma_f16(acc[1][2*ng],   al1, bh[0], bh[1]);
            mma_f16(acc[0][2*ng+1], al0, bh[2], bh[3]);
            mma_f16(acc[1][2*ng+1], al1, bh[2], bh[3]);
        }
    }
}

template<int MODE>
__global__ void __launch_bounds__(256, 1) mlp3_kernel(
    const float* __restrict__ hE,
    const float* __restrict__ P, const float* __restrict__ G,
    const float* __restrict__ bias2, const float* __restrict__ bias3,
    const float* __restrict__ mask_attend,
    const float* __restrict__ ln3s, const float* __restrict__ ln3b,
    float* __restrict__ out_hE, int matBase)
{
    extern __shared__ char sm[];
    uint32_t sb = smem_u32(sm);

    int tid = threadIdx.x;
    int wid = tid >> 5, lane = tid & 31;
    int warpM = wid & 3, warpN = wid >> 2;
    int qr = lane >> 2, qc = lane & 3;
    int e0 = blockIdx.x * 128;
    int cBase = warpN*64 + 2*qc;

    int Row[2][2];
    #pragma unroll
    for (int mf = 0; mf < 2; mf++)
        #pragma unroll
        for (int h = 0; h < 2; h++)
            Row[mf][h] = warpM*32 + mf*16 + h*8 + qr;

    // build A0 = hE rows split hi/lo fp16
    for (int idx = tid; idx < 128*64; idx += 256) {
        int r = idx >> 6, cp = idx & 63;
        float2 x = *(const float2*)&hE[(size_t)(e0 + r)*NH + cp*2];
        uint2 s = split2(x.x, x.y);
        *(uint32_t*)(sm + OFF_AHI + r*AST + cp*4) = s.x;
        *(uint32_t*)(sm + OFF_ALO + r*AST + cp*4) = s.y;
    }
    copyB(sm, matBase + 0);
    __syncthreads();

    float acc[2][8][4];

    // ---- layer 1 ----
    mma_layer(sb, warpM, warpN, lane, acc);
    __syncthreads();
    {
        const float* Pr[2][2];
        const float* Gr[2][2];
        #pragma unroll
        for (int mf = 0; mf < 2; mf++)
            #pragma unroll
            for (int h = 0; h < 2; h++) {
                int e = e0 + Row[mf][h];
                int tok = e / 48;
                int batch = (e >= NL*NK) ? 1 : 0;
                Pr[mf][h] = P + (size_t)tok * NH;
                Gr[mf][h] = G + (size_t)(batch*NL + g_idx32[e]) * NH;
            }
        #pragma unroll
        for (int mf = 0; mf < 2; mf++)
            #pragma unroll
            for (int j = 0; j < 8; j++) {
                int C = cBase + j*8;
                #pragma unroll
                for (int h = 0; h < 2; h++) {
                    float2 pv = *(const float2*)&Pr[mf][h][C];
                    float2 gv = *(const float2*)&Gr[mf][h][C];
                    float v0 = gelu_f(acc[mf][j][2*h+0] + pv.x + gv.x);
                    float v1 = gelu_f(acc[mf][j][2*h+1] + pv.y + gv.y);
                    uint2 s = split2(v0, v1);
                    int R = Row[mf][h];
                    *(uint32_t*)(sm + OFF_AHI + R*AST + C*2) = s.x;
                    *(uint32_t*)(sm + OFF_ALO + R*AST + C*2) = s.y;
                }
            }
    }
    copyB(sm, matBase + 1);
    __syncthreads();

    // ---- layer 2 ----
    mma_layer(sb, warpM, warpN, lane, acc);
    __syncthreads();
    #pragma unroll
    for (int mf = 0; mf < 2; mf++)
        #pragma unroll
        for (int j = 0; j < 8; j++) {
            int C = cBase + j*8;
            float2 bv = *(const float2*)&bias2[C];
            #pragma unroll
            for (int h = 0; h < 2; h++) {
                float v0 = gelu_f(acc[mf][j][2*h+0] + bv.x);
                float v1 = gelu_f(acc[mf][j][2*h+1] + bv.y);
                uint2 s = split2(v0, v1);
                int R = Row[mf][h];
                *(uint32_t*)(sm + OFF_AHI + R*AST + C*2) = s.x;
                *(uint32_t*)(sm + OFF_ALO + R*AST + C*2) = s.y;
            }
        }
    copyB(sm, matBase + 2);
    __syncthreads();

    // ---- layer 3 ----
    mma_layer(sb, warpM, warpN, lane, acc);
    __syncthreads();

    if (MODE == 0) {
        float* stage = (float*)(sm + OFF_AHI);  // [128][136] f32, aliases A
        #pragma unroll
        for (int mf = 0; mf < 2; mf++)
            #pragma unroll
            for (int h = 0; h < 2; h++) {
                int R = Row[mf][h];
                float mk = mask_attend[e0 + R];
                #pragma unroll
                for (int j = 0; j < 8; j++) {
                    int C = cBase + j*8;
                    float2 bv = *(const float2*)&bias3[C];
                    float2 o2;
                    o2.x = (acc[mf][j][2*h+0] + bv.x) * mk;
                    o2.y = (acc[mf][j][2*h+1] + bv.y) * mk;
                    *(float2*)&stage[R*136 + C] = o2;
                }
            }
        __syncthreads();
        int t0 = e0 / 48;
        int tend = (e0 + 127) / 48;
        for (int t = t0 + (tid >> 7); t <= tend; t += 2) {
            int col = tid & 127;
            int rs = max(t*48 - e0, 0), re = min(t*48 + 47 - e0, 127);
            float sacc = 0.0f;
            for (int rr = rs; rr <= re; rr++) sacc += stage[rr*136 + col];
            if (t*48 >= e0) g_partA[(size_t)t*NH + col] = sacc;
            else            g_partB[(size_t)t*NH + col] = sacc;
        }
    } else {
        float* stats = (float*)(sm + OFF_STAT);  // [2 warpN][128 rows][2]
        float s1[2][2], s2[2][2];
        #pragma unroll
        for (int mf = 0; mf < 2; mf++)
            #pragma unroll
            for (int h = 0; h < 2; h++) { s1[mf][h] = 0.f; s2[mf][h] = 0.f; }
        #pragma unroll
        for (int mf = 0; mf < 2; mf++)
            #pragma unroll
            for (int j = 0; j < 8; j++) {
                int C = cBase + j*8;
                float2 bv = *(const float2*)&bias3[C];
                #pragma unroll
                for (int h = 0; h < 2; h++) {
                    int R = Row[mf][h];
                    float2 he = *(const float2*)&hE[(size_t)(e0 + R)*NH + C];
                    float v0 = acc[mf][j][2*h+0] + bv.x + he.x;
                    float v1 = acc[mf][j][2*h+1] + bv.y + he.y;
                    acc[mf][j][2*h+0] = v0;
                    acc[mf][j][2*h+1] = v1;
                    s1[mf][h] += v0 + v1;
                    s2[mf][h] += v0*v0 + v1*v1;
                }
            }
        #pragma unroll
        for (int mf = 0; mf < 2; mf++)
            #pragma unroll
            for (int h = 0; h < 2; h++) {
                #pragma unroll
                for (int o = 1; o < 4; o <<= 1) {
                    s1[mf][h] += __shfl_xor_sync(0xffffffffu, s1[mf][h], o);
                    s2[mf][h] += __shfl_xor_sync(0xffffffffu, s2[mf][h], o);
                }
                if (qc == 0) {
                    stats[(warpN*128 + Row[mf][h])*2 + 0] = s1[mf][h];
                    stats[(warpN*128 + Row[mf][h])*2 + 1] = s2[mf][h];
                }
            }
        __syncthreads();
        #pragma unroll
        for (int mf = 0; mf < 2; mf++)
            #pragma unroll
            for (int h = 0; h < 2; h++) {
                int R = Row[mf][h];
                float S1 = stats[R*2] + stats[(128 + R)*2];
                float S2 = stats[R*2 + 1] + stats[(128 + R)*2 + 1];
                float mu = S1 * (1.0f / NH);
                float var = S2 * (1.0f / NH) - mu * mu;
                float rinv = rsqrtf(var + 1e-5f);
                #pragma unroll
                for (int j = 0; j < 8; j++) {
                    int C = cBase + j*8;
                    float2 gs = *(const float2*)&ln3s[C];
                    float2 gb = *(const float2*)&ln3b[C];
                    float2 o2;
                    o2.x = (acc[mf][j][2*h+0] - mu) * rinv * gs.x + gb.x;
                    o2.y = (acc[mf][j][2*h+1] - mu) * rinv * gs.y + gb.y;
                    *(float2*)&out_hE[(size_t)(e0 + R)*NH + C] = o2;
                }
            }
    }
}

// ---------------------------------------------------------------------------

extern "C" void kernel_launch(void* const* d_in, const int* in_sizes, int n_in,
                              void* d_out, int out_size)
{
    const float* h_V         = (const float*)d_in[0];
    const float* h_E         = (const float*)d_in[1];
    const void*  E_idx       =               d_in[2];
    const float* mask_V      = (const float*)d_in[3];
    const float* mask_attend = (const float*)d_in[4];
    const float* W1  = (const float*)d_in[5],  *b1  = (const float*)d_in[6];
    const float* W2  = (const float*)d_in[7],  *b2  = (const float*)d_in[8];
    const float* W3  = (const float*)d_in[9],  *b3  = (const float*)d_in[10];
    const float* W11 = (const float*)d_in[11], *b11 = (const float*)d_in[12];
    const float* W12 = (const float*)d_in[13], *b12 = (const float*)d_in[14];
    const float* W13 = (const float*)d_in[15], *b13 = (const float*)d_in[16];
    const float* Wi  = (const float*)d_in[17], *bi  = (const float*)d_in[18];
    const float* Wo  = (const float*)d_in[19], *bo  = (const float*)d_in[20];
    const float* ln1s = (const float*)d_in[21], *ln1b = (const float*)d_in[22];
    const float* ln2s = (const float*)d_in[23], *ln2b = (const float*)d_in[24];
    const float* ln3s = (const float*)d_in[25], *ln3b = (const float*)d_in[26];
    float* out = (float*)d_out;

    float *pP1, *pG1, *pP2, *pG2, *pHV2;
    cudaGetSymbolAddress((void**)&pP1,  g_P1);
    cudaGetSymbolAddress((void**)&pG1,  g_G1);
    cudaGetSymbolAddress((void**)&pP2,  g_P2);
    cudaGetSymbolAddress((void**)&pG2,  g_G2);
    cudaGetSymbolAddress((void**)&pHV2, g_hV2);

    int sm_tg = (64*NH + 32*NH) * (int)sizeof(float);
    int sm_f2 = (64*32 + 32*NH) * (int)sizeof(float);

    cudaFuncSetAttribute(token_gemm,  cudaFuncAttributeMaxDynamicSharedMemorySize, sm_tg);
    cudaFuncSetAttribute(ffn1_kernel, cudaFuncAttributeMaxDynamicSharedMemorySize, sm_tg);
    cudaFuncSetAttribute(ffn2_kernel, cudaFuncAttributeMaxDynamicSharedMemorySize, sm_f2);
    cudaFuncSetAttribute(mlp3_kernel<0>, cudaFuncAttributeMaxDynamicSharedMemorySize, SMEM_MLP3);
    cudaFuncSetAttribute(mlp3_kernel<1>, cudaFuncAttributeMaxDynamicSharedMemorySize, SMEM_MLP3);

    detect_kernel<<<1, 256>>>((const int*)E_idx);
    convert_kernel<<<(NEDGE + 255) / 256, 256>>>(E_idx);

    // mats 0-2: node (W1E, W2, W3); 3-5: edge (W11E, W12, W13)
    wprep_kernel<<<(6*16384 + 255)/256, 256>>>(W1 + 128*NH, W2, W3,
                                               W11 + 128*NH, W12, W13);

    token_gemm<<<64, 256, sm_tg>>>(h_V, W1,          b1,      pP1);
    token_gemm<<<64, 256, sm_tg>>>(h_V, W1 + 256*NH, nullptr, pG1);

    mlp3_kernel<0><<<NEDGE/128, 256, SMEM_MLP3>>>(h_E, pP1, pG1, b2, b3,
                                                  mask_attend, nullptr, nullptr,
                                                  nullptr, 0);
    nodeLN_kernel<<<NTOK, 128>>>(h_V, ln1s, ln1b);

    ffn1_kernel<<<dim3(64, 4), 256, sm_tg>>>(Wi, bi);
    ffn2_kernel<<<64, 256, sm_f2>>>(Wo, bo, ln2s, ln2b, mask_V, out);

    token_gemm<<<64, 256, sm_tg>>>(pHV2, W11,          b11,     pP2);
    token_gemm<<<64, 256, sm_tg>>>(pHV2, W11 + 256*NH, nullptr, pG2);

    mlp3_kernel<1><<<NEDGE/128, 256, SMEM_MLP3>>>(h_E, pP2, pG2, b12, b13,
                                                  nullptr, ln3s, ln3b,
                                                  out + (size_t)NTOK * NH, 3);
}

// round 6
// speedup vs baseline: 3.8078x; 1.2096x over previous
#include <cuda_runtime.h>
#include <cuda_fp16.h>
#include <math.h>
#include <stdint.h>

#define NB 2
#define NL 2048
#define NK 48
#define NH 128
#define NTOK (NB*NL)
#define NEDGE (NB*NL*NK)
#define FFH 512

__device__ int   g_is64;
__device__ int   g_idx32[NEDGE];
__device__ float g_hV2[NTOK*NH];
__device__ float g_h1 [NTOK*NH];
__device__ float g_H  [NTOK*FFH];
__device__ float g_P1 [NTOK*NH];
__device__ float g_G1 [NTOK*NH];
__device__ float g_P2 [NTOK*NH];
__device__ float g_G2 [NTOK*NH];
__device__ float g_partA[NTOK*NH];
__device__ float g_partB[NTOK*NH];
// 6 matrices fp16 [k][n], rows padded to 272B -> 34816 B = 2176 uint4 each
__device__ uint4 g_Wb[6*2176];

__device__ __forceinline__ float gelu_f(float x) {
    return 0.5f * x * (1.0f + erff(x * 0.7071067811865475f));
}

__device__ __forceinline__ uint32_t smem_u32(const void* p) {
    uint32_t a;
    asm("{ .reg .u64 t; cvta.to.shared.u64 t, %1; cvt.u32.u64 %0, t; }"
        : "=r"(a) : "l"(p));
    return a;
}

__device__ __forceinline__ uint32_t pack_f16(float v0, float v1) {
    __half2 h = __floats2half2_rn(v0, v1);
    return *(uint32_t*)&h;
}

// split (v0,v1) -> {hi fp16 pair, lo fp16 pair}
__device__ __forceinline__ uint2 split2(float v0, float v1) {
    __half h0 = __float2half_rn(v0), h1 = __float2half_rn(v1);
    float r0 = v0 - __half2float(h0), r1 = v1 - __half2float(h1);
    uint32_t hi = ((uint32_t)__half_as_ushort(h1) << 16) | (uint32_t)__half_as_ushort(h0);
    return make_uint2(hi, pack_f16(r0, r1));
}

__device__ __forceinline__ void ldm4(uint32_t r[4], uint32_t a) {
    asm volatile("ldmatrix.sync.aligned.m8n8.x4.shared.b16 {%0,%1,%2,%3}, [%4];"
        : "=r"(r[0]), "=r"(r[1]), "=r"(r[2]), "=r"(r[3]) : "r"(a));
}
__device__ __forceinline__ void ldm4t(uint32_t r[4], uint32_t a) {
    asm volatile("ldmatrix.sync.aligned.m8n8.x4.trans.shared.b16 {%0,%1,%2,%3}, [%4];"
        : "=r"(r[0]), "=r"(r[1]), "=r"(r[2]), "=r"(r[3]) : "r"(a));
}
__device__ __forceinline__ void mma_f16(float c[4], const uint32_t a[4],
                                        uint32_t b0, uint32_t b1) {
    asm volatile(
        "mma.sync.aligned.m16n8k16.row.col.f32.f16.f16.f32 "
        "{%0,%1,%2,%3}, {%4,%5,%6,%7}, {%8,%9}, {%0,%1,%2,%3};"
        : "+f"(c[0]), "+f"(c[1]), "+f"(c[2]), "+f"(c[3])
        : "r"(a[0]), "r"(a[1]), "r"(a[2]), "r"(a[3]), "r"(b0), "r"(b1));
}

// ---------------------------------------------------------------------------
__global__ void detect_kernel(const int* __restrict__ w) {
    int nz = 0;
    for (int i = 2 * (int)threadIdx.x + 1; i < 1024; i += 512) nz |= (w[i] != 0);
    unsigned any = __ballot_sync(0xffffffffu, nz);
    __shared__ int s[8];
    if ((threadIdx.x & 31) == 0) s[threadIdx.x >> 5] = (any != 0);
    __syncthreads();
    if (threadIdx.x == 0) {
        int a = 0;
        #pragma unroll
        for (int i = 0; i < 8; i++) a |= s[i];
        g_is64 = (a == 0);
    }
}

__global__ void convert_kernel(const void* __restrict__ e) {
    int i = blockIdx.x * blockDim.x + threadIdx.x;
    if (i >= NEDGE) return;
    if (g_is64) g_idx32[i] = (int)((const long long*)e)[i];
    else        g_idx32[i] = ((const int*)e)[i];
}

// ---------------------------------------------------------------------------
// wprep: weights (fp32 [k][n]) -> fp16, rows padded to 272B.
// ---------------------------------------------------------------------------
__global__ void wprep_kernel(const float* W0, const float* W1, const float* W2,
                             const float* W3, const float* W4, const float* W5) {
    int gid = blockIdx.x * 256 + threadIdx.x;
    if (gid >= 6 * 16384) return;
    int m = gid >> 14, rem = gid & 16383;
    int k = rem >> 7, n = rem & 127;
    const float* W = (m == 0) ? W0 : (m == 1) ? W1 : (m == 2) ? W2
                   : (m == 3) ? W3 : (m == 4) ? W4 : W5;
    float v = W[k * 128 + n];
    char* basep = (char*)g_Wb + (size_t)m * 34816;
    *(__half*)(basep + (uint32_t)k * 272u + (uint32_t)n * 2u) = __float2half_rn(v);
}

// ---------------------------------------------------------------------------
// FFMA GEMM core (token_gemm / ffn)
// ---------------------------------------------------------------------------
#define GSTEP(CMP, J) { \
    float4 bb = *(const float4*)&Wt[(kk4*4 + J)*NH + c0]; \
    _Pragma("unroll") \
    for (int r = 0; r < R; r++) { \
        float a = a4[r].CMP; \
        acc[r][0] += a * bb.x; acc[r][1] += a * bb.y; \
        acc[r][2] += a * bb.z; acc[r][3] += a * bb.w; } }

template<int R>
__device__ __forceinline__ void gemm_k128(
    const float* __restrict__ As, const float* __restrict__ Wg, int ws,
    float* Wt, int r0, int c0, int tid, float (&acc)[R][4])
{
    #pragma unroll
    for (int r = 0; r < R; r++)
        #pragma unroll
        for (int c = 0; c < 4; c++) acc[r][c] = 0.0f;

    for (int kt = 0; kt < 128; kt += 32) {
        __syncthreads();
        #pragma unroll
        for (int j = 0; j < 16; j++) {
            int i = tid + 256*j;
            Wt[i] = Wg[(kt + (i >> 7))*ws + (i & 127)];
        }
        __syncthreads();
        #pragma unroll
        for (int kk4 = 0; kk4 < 8; kk4++) {
            float4 a4[R];
            #pragma unroll
            for (int r = 0; r < R; r++)
                a4[r] = *(const float4*)&As[(r0 + r)*NH + kt + kk4*4];
            GSTEP(x, 0) GSTEP(y, 1) GSTEP(z, 2) GSTEP(w, 3)
        }
    }
}

// 32 tokens per CTA -> grid 128
__global__ void __launch_bounds__(256) token_gemm(
    const float* __restrict__ A, const float* __restrict__ W,
    const float* __restrict__ bias, float* __restrict__ C)
{
    extern __shared__ float smemf[];
    float* As = smemf;           // 32*128
    float* Wt = As + 32*NH;      // 32*128
    int bl0 = blockIdx.x * 32;
    int tid = threadIdx.x;
    int warp = tid >> 5, lane = tid & 31;
    int r0 = warp * 4, c0 = lane * 4;

    #pragma unroll
    for (int j = 0; j < 16; j++) As[tid + 256*j] = A[(size_t)bl0*NH + tid + 256*j];

    float acc[4][4];
    gemm_k128<4>(As, W, NH, Wt, r0, c0, tid, acc);

    float4 bv = make_float4(0.f, 0.f, 0.f, 0.f);
    if (bias) bv = *(const float4*)&bias[c0];
    #pragma unroll
    for (int r = 0; r < 4; r++) {
        float4 o4;
        o4.x = acc[r][0] + bv.x; o4.y = acc[r][1] + bv.y;
        o4.z = acc[r][2] + bv.z; o4.w = acc[r][3] + bv.w;
        *(float4*)&C[(size_t)(bl0 + r0 + r)*NH + c0] = o4;
    }
}

__global__ void __launch_bounds__(256) ffn1_kernel(
    const float* __restrict__ Wi, const float* __restrict__ bi)
{
    extern __shared__ float smemf[];
    float* As = smemf;
    float* Wt = As + 64*NH;
    int bl0 = blockIdx.x * 64;
    int nb  = blockIdx.y * 128;
    int tid = threadIdx.x;
    int warp = tid >> 5, lane = tid & 31;
    int r0 = warp * 8, c0 = lane * 4;

    #pragma unroll
    for (int j = 0; j < 32; j++) As[tid + 256*j] = g_h1[(size_t)bl0*NH + tid + 256*j];

    float acc[8][4];
    gemm_k128<8>(As, Wi + nb, FFH, Wt, r0, c0, tid, acc);

    float4 bv = *(const float4*)&bi[nb + c0];
    #pragma unroll
    for (int r = 0; r < 8; r++) {
        float4 o4;
        o4.x = gelu_f(acc[r][0] + bv.x); o4.y = gelu_f(acc[r][1] + bv.y);
        o4.z = gelu_f(acc[r][2] + bv.z); o4.w = gelu_f(acc[r][3] + bv.w);
        *(float4*)&g_H[(size_t)(bl0 + r0 + r)*FFH + nb + c0] = o4;
    }
}

// 32 tokens per CTA -> grid 128
__global__ void __launch_bounds__(256) ffn2_kernel(
    const float* __restrict__ Wo, const float* __restrict__ bo,
    const float* __restrict__ ln2s, const float* __restrict__ ln2b,
    const float* __restrict__ mask_V, float* __restrict__ out_hV)
{
    extern __shared__ float smemf[];
    float* At = smemf;           // 32*32
    float* Wt = At + 32*32;      // 32*128
    int bl0 = blockIdx.x * 32;
    int tid = threadIdx.x;
    int warp = tid >> 5, lane = tid & 31;
    int r0 = warp * 4, c0 = lane * 4;

    float acc[4][4];
    #pragma unroll
    for (int r = 0; r < 4; r++)
        #pragma unroll
        for (int c = 0; c < 4; c++) acc[r][c] = 0.0f;

    for (int kt = 0; kt < FFH; kt += 32) {
        __syncthreads();
        #pragma unroll
        for (int j = 0; j < 4; j++) {
            int i = tid + 256*j;
            At[i] = g_H[(size_t)(bl0 + (i >> 5))*FFH + kt + (i & 31)];
        }
        #pragma unroll
        for (int j = 0; j < 16; j++) {
            int i = tid + 256*j;
            Wt[i] = Wo[(kt + (i >> 7))*NH + (i & 127)];
        }
        __syncthreads();
        #pragma unroll
        for (int kk4 = 0; kk4 < 8; kk4++) {
            float4 a4[4];
            #pragma unroll
            for (int r = 0; r < 4; r++)
                a4[r] = *(const float4*)&At[(r0 + r)*32 + kk4*4];
            {
                const int R = 4;
                GSTEP(x, 0) GSTEP(y, 1) GSTEP(z, 2) GSTEP(w, 3)
            }
        }
    }

    float4 bv  = *(const float4*)&bo[c0];
    float4 g2s = *(const float4*)&ln2s[c0];
    float4 g2b = *(const float4*)&ln2b[c0];
    #pragma unroll
    for (int r = 0; r < 4; r++) {
        int token = bl0 + r0 + r;
        float4 hv = *(const float4*)&g_h1[(size_t)token*NH + c0];
        float v0 = hv.x + acc[r][0] + bv.x;
        float v1 = hv.y + acc[r][1] + bv.y;
        float v2 = hv.z + acc[r][2] + bv.z;
        float v3 = hv.w + acc[r][3] + bv.w;
        float s1 = v0 + v1 + v2 + v3;
        float s2 = v0*v0 + v1*v1 + v2*v2 + v3*v3;
        #pragma unroll
        for (int o = 16; o; o >>= 1) {
            s1 += __shfl_xor_sync(0xffffffffu, s1, o);
            s2 += __shfl_xor_sync(0xffffffffu, s2, o);
        }
        float mu = s1 * (1.0f / NH);
        float var = s2 * (1.0f / NH) - mu * mu;
        float rinv = rsqrtf(var + 1e-5f);
        float mk = mask_V[token];
        float4 o4;
        o4.x = ((v0 - mu) * rinv * g2s.x + g2b.x) * mk;
        o4.y = ((v1 - mu) * rinv * g2s.y + g2b.y) * mk;
        o4.z = ((v2 - mu) * rinv * g2s.z + g2b.z) * mk;
        o4.w = ((v3 - mu) * rinv * g2s.w + g2b.w) * mk;
        *(float4*)&g_hV2[(size_t)token*NH + c0] = o4;
        *(float4*)&out_hV[(size_t)token*NH + c0] = o4;
    }
}

// ---------------------------------------------------------------------------
// nodeLN: gather 2-slot partials, scale, residual, LN1 -> g_h1
// ---------------------------------------------------------------------------
__global__ void nodeLN_kernel(const float* __restrict__ hV,
                              const float* __restrict__ ln1s,
                              const float* __restrict__ ln1b)
{
    int t = blockIdx.x, c = threadIdx.x;   // 128 threads
    int s0 = t * 48;
    float p = g_partA[(size_t)t*NH + c];
    if (s0 / 128 != (s0 + 47) / 128) p += g_partB[(size_t)t*NH + c];
    float x = hV[(size_t)t*NH + c] + p * (1.0f / 30.0f);
    float a = x, b = x * x;
    #pragma unroll
    for (int o = 16; o; o >>= 1) {
        a += __shfl_xor_sync(0xffffffffu, a, o);
        b += __shfl_xor_sync(0xffffffffu, b, o);
    }
    __shared__ float sA[4], sB[4];
    int w = c >> 5, l = c & 31;
    if (l == 0) { sA[w] = a; sB[w] = b; }
    __syncthreads();
    float sum = sA[0] + sA[1] + sA[2] + sA[3];
    float ssq = sB[0] + sB[1] + sB[2] + sB[3];
    float mu = sum * (1.0f / NH);
    float var = ssq * (1.0f / NH) - mu * mu;
    float ri = rsqrtf(var + 1e-5f);
    g_h1[(size_t)t*NH + c] = (x - mu) * ri * ln1s[c] + ln1b[c];
}

// ---------------------------------------------------------------------------
// mlp3 (mma.sync fp16 2-pass): 128 rows x 128 cols per CTA, 3 chained layers.
// occ=2 CTAs/SM for latency hiding.
// MODE 0 = node (mask + K-sum partials), MODE 1 = edge (residual + LN3 + out)
// ---------------------------------------------------------------------------
#define AST 272
#define OFF_AHI 0
#define OFF_ALO 34816
#define OFF_B   69632
#define OFF_STAT 104448
#define SMEM_MLP3 106496

__device__ __forceinline__ void copyB(char* sm, int mat) {
    const uint4* src = &g_Wb[(size_t)mat * 2176];
    uint4* dst = (uint4*)(sm + OFF_B);
    #pragma unroll
    for (int i = 0; i < 9; i++) {
        int idx = threadIdx.x + 256*i;
        if (idx < 2176) dst[idx] = src[idx];
    }
}

__device__ __forceinline__ void mma_layer(uint32_t sb, int warpM, int warpN,
                                          int lane, float (&acc)[2][8][4]) {
    #pragma unroll
    for (int m = 0; m < 2; m++)
        #pragma unroll
        for (int j = 0; j < 8; j++)
            #pragma unroll
            for (int c = 0; c < 4; c++) acc[m][j][c] = 0.0f;

    uint32_t aHi = sb + OFF_AHI + (uint32_t)(warpM*32 + (lane & 15))*AST
                 + (uint32_t)(lane >> 4)*16;
    uint32_t aLo = aHi + (OFF_ALO - OFF_AHI);
    uint32_t bB  = sb + OFF_B + (uint32_t)(lane & 15)*AST
                 + (uint32_t)(warpN*8 + (lane >> 4))*16;

    #pragma unroll
    for (int ks = 0; ks < 8; ks++) {
        uint32_t ah0[4], ah1[4], al0[4], al1[4];
        ldm4(ah0, aHi + ks*32);
        ldm4(ah1, aHi + ks*32 + 16*AST);
        ldm4(al0, aLo + ks*32);
        ldm4(al1, aLo + ks*32 + 16*AST);
        #pragma unroll
        for (int ng = 0; ng < 4; ng++) {
            uint32_t bh[4];
            ldm4t(bh, bB + ks*16*AST + ng*32);
            mma_f16(acc[0][2*ng],   ah0, bh[0], bh[1]);
            mma_f16(acc[1][2*ng],   ah1, bh[0], bh[1]);
            mma_f16(acc[0][2*ng+1], ah0, bh[2], bh[3]);
            mma_f16(acc[1][2*ng+1], ah1, bh[2], bh[3]);
            mma_f16(acc[0][2*ng],   al0, bh[0], bh[1]);
            mma_f16(acc[1][2*ng],   al1, bh[0], bh[1]);
            mma_f16(acc[0][2*ng+1], al0, bh[2], bh[3]);
            mma_f16(acc[1][2*ng+1], al1, bh[2], bh[3]);
        }
    }
}

template<int MODE>
__global__ void __launch_bounds__(256, 2) mlp3_kernel(
    const float* __restrict__ hE,
    const float* __restrict__ P, const float* __restrict__ G,
    const float* __restrict__ bias2, const float* __restrict__ bias3,
    const float* __restrict__ mask_attend,
    const float* __restrict__ ln3s, const float* __restrict__ ln3b,
    float* __restrict__ out_hE, int matBase)
{
    extern __shared__ char sm[];
    uint32_t sb = smem_u32(sm);

    int tid = threadIdx.x;
    int wid = tid >> 5, lane = tid & 31;
    int warpM = wid & 3, warpN = wid >> 2;
    int qr = lane >> 2, qc = lane & 3;
    int e0 = blockIdx.x * 128;
    int cBase = warpN*64 + 2*qc;

    int Row[2][2];
    #pragma unroll
    for (int mf = 0; mf < 2; mf++)
        #pragma unroll
        for (int h = 0; h < 2; h++)
            Row[mf][h] = warpM*32 + mf*16 + h*8 + qr;

    // build A0 = hE rows split hi/lo fp16
    for (int idx = tid; idx < 128*64; idx += 256) {
        int r = idx >> 6, cp = idx & 63;
        float2 x = *(const float2*)&hE[(size_t)(e0 + r)*NH + cp*2];
        uint2 s = split2(x.x, x.y);
        *(uint32_t*)(sm + OFF_AHI + r*AST + cp*4) = s.x;
        *(uint32_t*)(sm + OFF_ALO + r*AST + cp*4) = s.y;
    }
    copyB(sm, matBase + 0);
    __syncthreads();

    float acc[2][8][4];

    // ---- layer 1 ----
    mma_layer(sb, warpM, warpN, lane, acc);
    __syncthreads();
    {
        const float* Pr[2][2];
        const float* Gr[2][2];
        #pragma unroll
        for (int mf = 0; mf < 2; mf++)
            #pragma unroll
            for (int h = 0; h < 2; h++) {
                int e = e0 + Row[mf][h];
                int tok = e / 48;
                int batch = (e >= NL*NK) ? 1 : 0;
                Pr[mf][h] = P + (size_t)tok * NH;
                Gr[mf][h] = G + (size_t)(batch*NL + g_idx32[e]) * NH;
            }
        #pragma unroll
        for (int mf = 0; mf < 2; mf++)
            #pragma unroll
            for (int j = 0; j < 8; j++) {
                int C = cBase + j*8;
                #pragma unroll
                for (int h = 0; h < 2; h++) {
                    float2 pv = *(const float2*)&Pr[mf][h][C];
                    float2 gv = *(const float2*)&Gr[mf][h][C];
                    float v0 = gelu_f(acc[mf][j][2*h+0] + pv.x + gv.x);
                    float v1 = gelu_f(acc[mf][j][2*h+1] + pv.y + gv.y);
                    uint2 s = split2(v0, v1);
                    int R = Row[mf][h];
                    *(uint32_t*)(sm + OFF_AHI + R*AST + C*2) = s.x;
                    *(uint32_t*)(sm + OFF_ALO + R*AST + C*2) = s.y;
                }
            }
    }
    copyB(sm, matBase + 1);
    __syncthreads();

    // ---- layer 2 ----
    mma_layer(sb, warpM, warpN, lane, acc);
    __syncthreads();
    #pragma unroll
    for (int mf = 0; mf < 2; mf++)
        #pragma unroll
        for (int j = 0; j < 8; j++) {
            int C = cBase + j*8;
            float2 bv = *(const float2*)&bias2[C];
            #pragma unroll
            for (int h = 0; h < 2; h++) {
                float v0 = gelu_f(acc[mf][j][2*h+0] + bv.x);
                float v1 = gelu_f(acc[mf][j][2*h+1] + bv.y);
                uint2 s = split2(v0, v1);
                int R = Row[mf][h];
                *(uint32_t*)(sm + OFF_AHI + R*AST + C*2) = s.x;
                *(uint32_t*)(sm + OFF_ALO + R*AST + C*2) = s.y;
            }
        }
    copyB(sm, matBase + 2);
    __syncthreads();

    // ---- layer 3 ----
    mma_layer(sb, warpM, warpN, lane, acc);
    __syncthreads();

    if (MODE == 0) {
        float* stage = (float*)(sm + OFF_AHI);  // [128][136] f32, aliases A
        #pragma unroll
        for (int mf = 0; mf < 2; mf++)
            #pragma unroll
            for (int h = 0; h < 2; h++) {
                int R = Row[mf][h];
                float mk = mask_attend[e0 + R];
                #pragma unroll
                for (int j = 0; j < 8; j++) {
                    int C = cBase + j*8;
                    float2 bv = *(const float2*)&bias3[C];
                    float2 o2;
                    o2.x = (acc[mf][j][2*h+0] + bv.x) * mk;
                    o2.y = (acc[mf][j][2*h+1] + bv.y) * mk;
                    *(float2*)&stage[R*136 + C] = o2;
                }
            }
        __syncthreads();
        int t0 = e0 / 48;
        int tend = (e0 + 127) / 48;
        for (int t = t0 + (tid >> 7); t <= tend; t += 2) {
            int col = tid & 127;
            int rs = max(t*48 - e0, 0), re = min(t*48 + 47 - e0, 127);
            float sacc = 0.0f;
            for (int rr = rs; rr <= re; rr++) sacc += stage[rr*136 + col];
            if (t*48 >= e0) g_partA[(size_t)t*NH + col] = sacc;
            else            g_partB[(size_t)t*NH + col] = sacc;
        }
    } else {
        float* stats = (float*)(sm + OFF_STAT);  // [2 warpN][128 rows][2]
        float s1[2][2], s2[2][2];
        #pragma unroll
        for (int mf = 0; mf < 2; mf++)
            #pragma unroll
            for (int h = 0; h < 2; h++) { s1[mf][h] = 0.f; s2[mf][h] = 0.f; }
        #pragma unroll
        for (int mf = 0; mf < 2; mf++)
            #pragma unroll
            for (int j = 0; j < 8; j++) {
                int C = cBase + j*8;
                float2 bv = *(const float2*)&bias3[C];
                #pragma unroll
                for (int h = 0; h < 2; h++) {
                    int R = Row[mf][h];
                    float2 he = *(const float2*)&hE[(size_t)(e0 + R)*NH + C];
                    float v0 = acc[mf][j][2*h+0] + bv.x + he.x;
                    float v1 = acc[mf][j][2*h+1] + bv.y + he.y;
                    acc[mf][j][2*h+0] = v0;
                    acc[mf][j][2*h+1] = v1;
                    s1[mf][h] += v0 + v1;
                    s2[mf][h] += v0*v0 + v1*v1;
                }
            }
        #pragma unroll
        for (int mf = 0; mf < 2; mf++)
            #pragma unroll
            for (int h = 0; h < 2; h++) {
                #pragma unroll
                for (int o = 1; o < 4; o <<= 1) {
                    s1[mf][h] += __shfl_xor_sync(0xffffffffu, s1[mf][h], o);
                    s2[mf][h] += __shfl_xor_sync(0xffffffffu, s2[mf][h], o);
                }
                if (qc == 0) {
                    stats[(warpN*128 + Row[mf][h])*2 + 0] = s1[mf][h];
                    stats[(warpN*128 + Row[mf][h])*2 + 1] = s2[mf][h];
                }
            }
        __syncthreads();
        #pragma unroll
        for (int mf = 0; mf < 2; mf++)
            #pragma unroll
            for (int h = 0; h < 2; h++) {
                int R = Row[mf][h];
                float S1 = stats[R*2] + stats[(128 + R)*2];
                float S2 = stats[R*2 + 1] + stats[(128 + R)*2 + 1];
                float mu = S1 * (1.0f / NH);
                float var = S2 * (1.0f / NH) - mu * mu;
                float rinv = rsqrtf(var + 1e-5f);
                #pragma unroll
                for (int j = 0; j < 8; j++) {
                    int C = cBase + j*8;
                    float2 gs = *(const float2*)&ln3s[C];
                    float2 gb = *(const float2*)&ln3b[C];
                    float2 o2;
                    o2.x = (acc[mf][j][2*h+0] - mu) * rinv * gs.x + gb.x;
                    o2.y = (acc[mf][j][2*h+1] - mu) * rinv * gs.y + gb.y;
                    *(float2*)&out_hE[(size_t)(e0 + R)*NH + C] = o2;
                }
            }
    }
}

// ---------------------------------------------------------------------------

extern "C" void kernel_launch(void* const* d_in, const int* in_sizes, int n_in,
                              void* d_out, int out_size)
{
    const float* h_V         = (const float*)d_in[0];
    const float* h_E         = (const float*)d_in[1];
    const void*  E_idx       =               d_in[2];
    const float* mask_V      = (const float*)d_in[3];
    const float* mask_attend = (const float*)d_in[4];
    const float* W1  = (const float*)d_in[5],  *b1  = (const float*)d_in[6];
    const float* W2  = (const float*)d_in[7],  *b2  = (const float*)d_in[8];
    const float* W3  = (const float*)d_in[9],  *b3  = (const float*)d_in[10];
    const float* W11 = (const float*)d_in[11], *b11 = (const float*)d_in[12];
    const float* W12 = (const float*)d_in[13], *b12 = (const float*)d_in[14];
    const float* W13 = (const float*)d_in[15], *b13 = (const float*)d_in[16];
    const float* Wi  = (const float*)d_in[17], *bi  = (const float*)d_in[18];
    const float* Wo  = (const float*)d_in[19], *bo  = (const float*)d_in[20];
    const float* ln1s = (const float*)d_in[21], *ln1b = (const float*)d_in[22];
    const float* ln2s = (const float*)d_in[23], *ln2b = (const float*)d_in[24];
    const float* ln3s = (const float*)d_in[25], *ln3b = (const float*)d_in[26];
    float* out = (float*)d_out;

    float *pP1, *pG1, *pP2, *pG2, *pHV2;
    cudaGetSymbolAddress((void**)&pP1,  g_P1);
    cudaGetSymbolAddress((void**)&pG1,  g_G1);
    cudaGetSymbolAddress((void**)&pP2,  g_P2);
    cudaGetSymbolAddress((void**)&pG2,  g_G2);
    cudaGetSymbolAddress((void**)&pHV2, g_hV2);

    int sm_tg = (32*NH + 32*NH) * (int)sizeof(float);
    int sm_f1 = (64*NH + 32*NH) * (int)sizeof(float);
    int sm_f2 = (32*32 + 32*NH) * (int)sizeof(float);

    cudaFuncSetAttribute(token_gemm,  cudaFuncAttributeMaxDynamicSharedMemorySize, sm_tg);
    cudaFuncSetAttribute(ffn1_kernel, cudaFuncAttributeMaxDynamicSharedMemorySize, sm_f1);
    cudaFuncSetAttribute(ffn2_kernel, cudaFuncAttributeMaxDynamicSharedMemorySize, sm_f2);
    cudaFuncSetAttribute(mlp3_kernel<0>, cudaFuncAttributeMaxDynamicSharedMemorySize, SMEM_MLP3);
    cudaFuncSetAttribute(mlp3_kernel<1>, cudaFuncAttributeMaxDynamicSharedMemorySize, SMEM_MLP3);

    detect_kernel<<<1, 256>>>((const int*)E_idx);
    convert_kernel<<<(NEDGE + 255) / 256, 256>>>(E_idx);

    // mats 0-2: node (W1E, W2, W3); 3-5: edge (W11E, W12, W13)
    wprep_kernel<<<(6*16384 + 255)/256, 256>>>(W1 + 128*NH, W2, W3,
                                               W11 + 128*NH, W12, W13);

    token_gemm<<<128, 256, sm_tg>>>(h_V, W1,          b1,      pP1);
    token_gemm<<<128, 256, sm_tg>>>(h_V, W1 + 256*NH, nullptr, pG1);

    mlp3_kernel<0><<<NEDGE/128, 256, SMEM_MLP3>>>(h_E, pP1, pG1, b2, b3,
                                                  mask_attend, nullptr, nullptr,
                                                  nullptr, 0);
    nodeLN_kernel<<<NTOK, 128>>>(h_V, ln1s, ln1b);

    ffn1_kernel<<<dim3(64, 4), 256, sm_f1>>>(Wi, bi);
    ffn2_kernel<<<128, 256, sm_f2>>>(Wo, bo, ln2s, ln2b, mask_V, out);

    token_gemm<<<128, 256, sm_tg>>>(pHV2, W11,          b11,     pP2);
    token_gemm<<<128, 256, sm_tg>>>(pHV2, W11 + 256*NH, nullptr, pG2);

    mlp3_kernel<1><<<NEDGE/128, 256, SMEM_MLP3>>>(h_E, pP2, pG2, b12, b13,
                                                  nullptr, ln3s, ln3b,
                                                  out + (size_t)NTOK * NH, 3);
}

// round 7
// speedup vs baseline: 4.0643x; 1.0674x over previous
#include <cuda_runtime.h>
#include <cuda_fp16.h>
#include <math.h>
#include <stdint.h>

#define NB 2
#define NL 2048
#define NK 48
#define NH 128
#define NTOK (NB*NL)
#define NEDGE (NB*NL*NK)
#define FFH 512

__device__ int   g_is64;
__device__ int   g_idx32[NEDGE];
__device__ float g_hV2[NTOK*NH];
__device__ float g_h1 [NTOK*NH];
__device__ uint32_t g_Hhi[NTOK*FFH/2];
__device__ uint32_t g_Hlo[NTOK*FFH/2];
__device__ float g_P1 [NTOK*NH];
__device__ float g_G1 [NTOK*NH];
__device__ float g_P2 [NTOK*NH];
__device__ float g_G2 [NTOK*NH];
__device__ float g_partA[NTOK*NH];
__device__ float g_partB[NTOK*NH];
// 14 matrices fp16 [k][n], rows padded to 272B -> 34816 B = 2176 uint4 each
// 0-2 node MLP, 3-5 edge MLP, 6-9 Wi col-tiles, 10-13 Wo k-chunks
__device__ uint4 g_Wb[14*2176];

__device__ __forceinline__ float gelu_f(float x) {
    return 0.5f * x * (1.0f + erff(x * 0.7071067811865475f));
}

__device__ __forceinline__ uint32_t smem_u32(const void* p) {
    uint32_t a;
    asm("{ .reg .u64 t; cvta.to.shared.u64 t, %1; cvt.u32.u64 %0, t; }"
        : "=r"(a) : "l"(p));
    return a;
}

__device__ __forceinline__ uint32_t pack_f16(float v0, float v1) {
    __half2 h = __floats2half2_rn(v0, v1);
    return *(uint32_t*)&h;
}

__device__ __forceinline__ uint2 split2(float v0, float v1) {
    __half h0 = __float2half_rn(v0), h1 = __float2half_rn(v1);
    float r0 = v0 - __half2float(h0), r1 = v1 - __half2float(h1);
    uint32_t hi = ((uint32_t)__half_as_ushort(h1) << 16) | (uint32_t)__half_as_ushort(h0);
    return make_uint2(hi, pack_f16(r0, r1));
}

__device__ __forceinline__ void ldm4(uint32_t r[4], uint32_t a) {
    asm volatile("ldmatrix.sync.aligned.m8n8.x4.shared.b16 {%0,%1,%2,%3}, [%4];"
        : "=r"(r[0]), "=r"(r[1]), "=r"(r[2]), "=r"(r[3]) : "r"(a));
}
__device__ __forceinline__ void ldm4t(uint32_t r[4], uint32_t a) {
    asm volatile("ldmatrix.sync.aligned.m8n8.x4.trans.shared.b16 {%0,%1,%2,%3}, [%4];"
        : "=r"(r[0]), "=r"(r[1]), "=r"(r[2]), "=r"(r[3]) : "r"(a));
}
__device__ __forceinline__ void mma_f16(float c[4], const uint32_t a[4],
                                        uint32_t b0, uint32_t b1) {
    asm volatile(
        "mma.sync.aligned.m16n8k16.row.col.f32.f16.f16.f32 "
        "{%0,%1,%2,%3}, {%4,%5,%6,%7}, {%8,%9}, {%0,%1,%2,%3};"
        : "+f"(c[0]), "+f"(c[1]), "+f"(c[2]), "+f"(c[3])
        : "r"(a[0]), "r"(a[1]), "r"(a[2]), "r"(a[3]), "r"(b0), "r"(b1));
}

// ---------------------------------------------------------------------------
__global__ void detect_kernel(const int* __restrict__ w) {
    int nz = 0;
    for (int i = 2 * (int)threadIdx.x + 1; i < 1024; i += 512) nz |= (w[i] != 0);
    unsigned any = __ballot_sync(0xffffffffu, nz);
    __shared__ int s[8];
    if ((threadIdx.x & 31) == 0) s[threadIdx.x >> 5] = (any != 0);
    __syncthreads();
    if (threadIdx.x == 0) {
        int a = 0;
        #pragma unroll
        for (int i = 0; i < 8; i++) a |= s[i];
        g_is64 = (a == 0);
    }
}

__global__ void convert_kernel(const void* __restrict__ e) {
    int i = blockIdx.x * blockDim.x + threadIdx.x;
    if (i >= NEDGE) return;
    if (g_is64) g_idx32[i] = (int)((const long long*)e)[i];
    else        g_idx32[i] = ((const int*)e)[i];
}

// ---------------------------------------------------------------------------
// wprep: all weights -> fp16 tiles [k][n], rows padded to 272B.
// ---------------------------------------------------------------------------
__global__ void wprep_kernel(const float* W0, const float* W1, const float* W2,
                             const float* W3, const float* W4, const float* W5,
                             const float* Wi, const float* Wo) {
    int gid = blockIdx.x * 256 + threadIdx.x;
    if (gid >= 14 * 16384) return;
    int m = gid >> 14, rem = gid & 16383;
    int k = rem >> 7, n = rem & 127;
    float v;
    if (m < 6) {
        const float* W = (m == 0) ? W0 : (m == 1) ? W1 : (m == 2) ? W2
                       : (m == 3) ? W3 : (m == 4) ? W4 : W5;
        v = W[k * 128 + n];
    } else if (m < 10) {
        v = Wi[k * FFH + (m - 6) * 128 + n];
    } else {
        v = Wo[((m - 10) * 128 + k) * 128 + n];
    }
    char* basep = (char*)g_Wb + (size_t)m * 34816;
    *(__half*)(basep + (uint32_t)k * 272u + (uint32_t)n * 2u) = __float2half_rn(v);
}

// ---------------------------------------------------------------------------
// FFMA GEMM core (token_gemmPG)
// ---------------------------------------------------------------------------
#define GSTEP(CMP, J) { \
    float4 bb = *(const float4*)&Wt[(kk4*4 + J)*NH + c0]; \
    _Pragma("unroll") \
    for (int r = 0; r < R; r++) { \
        float a = a4[r].CMP; \
        acc[r][0] += a * bb.x; acc[r][1] += a * bb.y; \
        acc[r][2] += a * bb.z; acc[r][3] += a * bb.w; } }

template<int R>
__device__ __forceinline__ void gemm_k128(
    const float* __restrict__ As, const float* __restrict__ Wg, int ws,
    float* Wt, int r0, int c0, int tid, float (&acc)[R][4])
{
    #pragma unroll
    for (int r = 0; r < R; r++)
        #pragma unroll
        for (int c = 0; c < 4; c++) acc[r][c] = 0.0f;

    for (int kt = 0; kt < 128; kt += 32) {
        __syncthreads();
        #pragma unroll
        for (int j = 0; j < 16; j++) {
            int i = tid + 256*j;
            Wt[i] = Wg[(kt + (i >> 7))*ws + (i & 127)];
        }
        __syncthreads();
        #pragma unroll
        for (int kk4 = 0; kk4 < 8; kk4++) {
            float4 a4[R];
            #pragma unroll
            for (int r = 0; r < R; r++)
                a4[r] = *(const float4*)&As[(r0 + r)*NH + kt + kk4*4];
            GSTEP(x, 0) GSTEP(y, 1) GSTEP(z, 2) GSTEP(w, 3)
        }
    }
}

// P = A@Wp + bias ; G = A@Wg. 32 tokens/CTA -> grid 128.
__global__ void __launch_bounds__(256) token_gemmPG(
    const float* __restrict__ A,
    const float* __restrict__ Wp, const float* __restrict__ bias,
    const float* __restrict__ Wg,
    float* __restrict__ P, float* __restrict__ G)
{
    extern __shared__ float smemf[];
    float* As = smemf;
    float* Wt = As + 32*NH;
    int bl0 = blockIdx.x * 32;
    int tid = threadIdx.x;
    int warp = tid >> 5, lane = tid & 31;
    int r0 = warp * 4, c0 = lane * 4;

    #pragma unroll
    for (int j = 0; j < 16; j++) As[tid + 256*j] = A[(size_t)bl0*NH + tid + 256*j];

    float acc[4][4];
    gemm_k128<4>(As, Wp, NH, Wt, r0, c0, tid, acc);
    float4 bv = *(const float4*)&bias[c0];
    #pragma unroll
    for (int r = 0; r < 4; r++) {
        float4 o4;
        o4.x = acc[r][0] + bv.x; o4.y = acc[r][1] + bv.y;
        o4.z = acc[r][2] + bv.z; o4.w = acc[r][3] + bv.w;
        *(float4*)&P[(size_t)(bl0 + r0 + r)*NH + c0] = o4;
    }

    gemm_k128<4>(As, Wg, NH, Wt, r0, c0, tid, acc);
    #pragma unroll
    for (int r = 0; r < 4; r++) {
        float4 o4;
        o4.x = acc[r][0]; o4.y = acc[r][1];
        o4.z = acc[r][2]; o4.w = acc[r][3];
        *(float4*)&G[(size_t)(bl0 + r0 + r)*NH + c0] = o4;
    }
}

// ---------------------------------------------------------------------------
// nodeLN: gather 2-slot partials, scale, residual, LN1 -> g_h1
// ---------------------------------------------------------------------------
__global__ void nodeLN_kernel(const float* __restrict__ hV,
                              const float* __restrict__ ln1s,
                              const float* __restrict__ ln1b)
{
    int t = blockIdx.x, c = threadIdx.x;   // 128 threads
    int s0 = t * 48;
    float p = g_partA[(size_t)t*NH + c];
    if (s0 / 128 != (s0 + 47) / 128) p += g_partB[(size_t)t*NH + c];
    float x = hV[(size_t)t*NH + c] + p * (1.0f / 30.0f);
    float a = x, b = x * x;
    #pragma unroll
    for (int o = 16; o; o >>= 1) {
        a += __shfl_xor_sync(0xffffffffu, a, o);
        b += __shfl_xor_sync(0xffffffffu, b, o);
    }
    __shared__ float sA[4], sB[4];
    int w = c >> 5, l = c & 31;
    if (l == 0) { sA[w] = a; sB[w] = b; }
    __syncthreads();
    float sum = sA[0] + sA[1] + sA[2] + sA[3];
    float ssq = sB[0] + sB[1] + sB[2] + sB[3];
    float mu = sum * (1.0f / NH);
    float var = ssq * (1.0f / NH) - mu * mu;
    float ri = rsqrtf(var + 1e-5f);
    g_h1[(size_t)t*NH + c] = (x - mu) * ri * ln1s[c] + ln1b[c];
}

// ---------------------------------------------------------------------------
// Shared mma machinery (128-row x 128-col tile, K=128)
// ---------------------------------------------------------------------------
#define AST 272
#define OFF_AHI 0
#define OFF_ALO 34816
#define OFF_B   69632
#define OFF_STAT 104448
#define SMEM_MLP3 106496

__device__ __forceinline__ void copyB(char* sm, int mat) {
    const uint4* src = &g_Wb[(size_t)mat * 2176];
    uint4* dst = (uint4*)(sm + OFF_B);
    #pragma unroll
    for (int i = 0; i < 9; i++) {
        int idx = threadIdx.x + 256*i;
        if (idx < 2176) dst[idx] = src[idx];
    }
}

__device__ __forceinline__ void mma_layer(uint32_t sb, int warpM, int warpN,
                                          int lane, float (&acc)[2][8][4]) {
    #pragma unroll
    for (int m = 0; m < 2; m++)
        #pragma unroll
        for (int j = 0; j < 8; j++)
            #pragma unroll
            for (int c = 0; c < 4; c++) acc[m][j][c] = 0.0f;

    uint32_t aHi = sb + OFF_AHI + (uint32_t)(warpM*32 + (lane & 15))*AST
                 + (uint32_t)(lane >> 4)*16;
    uint32_t aLo = aHi + (OFF_ALO - OFF_AHI);
    uint32_t bB  = sb + OFF_B + (uint32_t)(lane & 15)*AST
                 + (uint32_t)(warpN*8 + (lane >> 4))*16;

    #pragma unroll
    for (int ks = 0; ks < 8; ks++) {
        uint32_t ah0[4], ah1[4], al0[4], al1[4];
        ldm4(ah0, aHi + ks*32);
        ldm4(ah1, aHi + ks*32 + 16*AST);
        ldm4(al0, aLo + ks*32);
        ldm4(al1, aLo + ks*32 + 16*AST);
        #pragma unroll
        for (int ng = 0; ng < 4; ng++) {
            uint32_t bh[4];
            ldm4t(bh, bB + ks*16*AST + ng*32);
            mma_f16(acc[0][2*ng],   ah0, bh[0], bh[1]);
            mma_f16(acc[1][2*ng],   ah1, bh[0], bh[1]);
            mma_f16(acc[0][2*ng+1], ah0, bh[2], bh[3]);
            mma_f16(acc[1][2*ng+1], ah1, bh[2], bh[3]);
            mma_f16(acc[0][2*ng],   al0, bh[0], bh[1]);
            mma_f16(acc[1][2*ng],   al1, bh[0], bh[1]);
            mma_f16(acc[0][2*ng+1], al0, bh[2], bh[3]);
            mma_f16(acc[1][2*ng+1], al1, bh[2], bh[3]);
        }
    }
}

// ---------------------------------------------------------------------------
// mlp3: MODE 0 = node, MODE 1 = edge
// ---------------------------------------------------------------------------
template<int MODE>
__global__ void __launch_bounds__(256, 2) mlp3_kernel(
    const float* __restrict__ hE,
    const float* __restrict__ P, const float* __restrict__ G,
    const float* __restrict__ bias2, const float* __restrict__ bias3,
    const float* __restrict__ mask_attend,
    const float* __restrict__ ln3s, const float* __restrict__ ln3b,
    float* __restrict__ out_hE, int matBase)
{
    extern __shared__ char sm[];
    uint32_t sb = smem_u32(sm);

    int tid = threadIdx.x;
    int wid = tid >> 5, lane = tid & 31;
    int warpM = wid & 3, warpN = wid >> 2;
    int qr = lane >> 2, qc = lane & 3;
    int e0 = blockIdx.x * 128;
    int cBase = warpN*64 + 2*qc;

    int Row[2][2];
    #pragma unroll
    for (int mf = 0; mf < 2; mf++)
        #pragma unroll
        for (int h = 0; h < 2; h++)
            Row[mf][h] = warpM*32 + mf*16 + h*8 + qr;

    for (int idx = tid; idx < 128*64; idx += 256) {
        int r = idx >> 6, cp = idx & 63;
        float2 x = *(const float2*)&hE[(size_t)(e0 + r)*NH + cp*2];
        uint2 s = split2(x.x, x.y);
        *(uint32_t*)(sm + OFF_AHI + r*AST + cp*4) = s.x;
        *(uint32_t*)(sm + OFF_ALO + r*AST + cp*4) = s.y;
    }
    copyB(sm, matBase + 0);
    __syncthreads();

    float acc[2][8][4];

    // ---- layer 1 ----
    mma_layer(sb, warpM, warpN, lane, acc);
    __syncthreads();
    {
        const float* Pr[2][2];
        const float* Gr[2][2];
        #pragma unroll
        for (int mf = 0; mf < 2; mf++)
            #pragma unroll
            for (int h = 0; h < 2; h++) {
                int e = e0 + Row[mf][h];
                int tok = e / 48;
                int batch = (e >= NL*NK) ? 1 : 0;
                Pr[mf][h] = P + (size_t)tok * NH;
                Gr[mf][h] = G + (size_t)(batch*NL + g_idx32[e]) * NH;
            }
        #pragma unroll
        for (int mf = 0; mf < 2; mf++)
            #pragma unroll
            for (int j = 0; j < 8; j++) {
                int C = cBase + j*8;
                #pragma unroll
                for (int h = 0; h < 2; h++) {
                    float2 pv = *(const float2*)&Pr[mf][h][C];
                    float2 gv = *(const float2*)&Gr[mf][h][C];
                    float v0 = gelu_f(acc[mf][j][2*h+0] + pv.x + gv.x);
                    float v1 = gelu_f(acc[mf][j][2*h+1] + pv.y + gv.y);
                    uint2 s = split2(v0, v1);
                    int R = Row[mf][h];
                    *(uint32_t*)(sm + OFF_AHI + R*AST + C*2) = s.x;
                    *(uint32_t*)(sm + OFF_ALO + R*AST + C*2) = s.y;
                }
            }
    }
    copyB(sm, matBase + 1);
    __syncthreads();

    // ---- layer 2 ----
    mma_layer(sb, warpM, warpN, lane, acc);
    __syncthreads();
    #pragma unroll
    for (int mf = 0; mf < 2; mf++)
        #pragma unroll
        for (int j = 0; j < 8; j++) {
            int C = cBase + j*8;
            float2 bv = *(const float2*)&bias2[C];
            #pragma unroll
            for (int h = 0; h < 2; h++) {
                float v0 = gelu_f(acc[mf][j][2*h+0] + bv.x);
                float v1 = gelu_f(acc[mf][j][2*h+1] + bv.y);
                uint2 s = split2(v0, v1);
                int R = Row[mf][h];
                *(uint32_t*)(sm + OFF_AHI + R*AST + C*2) = s.x;
                *(uint32_t*)(sm + OFF_ALO + R*AST + C*2) = s.y;
            }
        }
    copyB(sm, matBase + 2);
    __syncthreads();

    // ---- layer 3 ----
    mma_layer(sb, warpM, warpN, lane, acc);
    __syncthreads();

    if (MODE == 0) {
        float* stage = (float*)(sm + OFF_AHI);  // [128][136] f32, aliases A
        #pragma unroll
        for (int mf = 0; mf < 2; mf++)
            #pragma unroll
            for (int h = 0; h < 2; h++) {
                int R = Row[mf][h];
                float mk = mask_attend[e0 + R];
                #pragma unroll
                for (int j = 0; j < 8; j++) {
                    int C = cBase + j*8;
                    float2 bv = *(const float2*)&bias3[C];
                    float2 o2;
                    o2.x = (acc[mf][j][2*h+0] + bv.x) * mk;
                    o2.y = (acc[mf][j][2*h+1] + bv.y) * mk;
                    *(float2*)&stage[R*136 + C] = o2;
                }
            }
        __syncthreads();
        int t0 = e0 / 48;
        int tend = (e0 + 127) / 48;
        for (int t = t0 + (tid >> 7); t <= tend; t += 2) {
            int col = tid & 127;
            int rs = max(t*48 - e0, 0), re = min(t*48 + 47 - e0, 127);
            float sacc = 0.0f;
            for (int rr = rs; rr <= re; rr++) sacc += stage[rr*136 + col];
            if (t*48 >= e0) g_partA[(size_t)t*NH + col] = sacc;
            else            g_partB[(size_t)t*NH + col] = sacc;
        }
    } else {
        float* stats = (float*)(sm + OFF_STAT);
        float s1[2][2], s2[2][2];
        #pragma unroll
        for (int mf = 0; mf < 2; mf++)
            #pragma unroll
            for (int h = 0; h < 2; h++) { s1[mf][h] = 0.f; s2[mf][h] = 0.f; }
        #pragma unroll
        for (int mf = 0; mf < 2; mf++)
            #pragma unroll
            for (int j = 0; j < 8; j++) {
                int C = cBase + j*8;
                float2 bv = *(const float2*)&bias3[C];
                #pragma unroll
                for (int h = 0; h < 2; h++) {
                    int R = Row[mf][h];
                    float2 he = *(const float2*)&hE[(size_t)(e0 + R)*NH + C];
                    float v0 = acc[mf][j][2*h+0] + bv.x + he.x;
                    float v1 = acc[mf][j][2*h+1] + bv.y + he.y;
                    acc[mf][j][2*h+0] = v0;
                    acc[mf][j][2*h+1] = v1;
                    s1[mf][h] += v0 + v1;
                    s2[mf][h] += v0*v0 + v1*v1;
                }
            }
        #pragma unroll
        for (int mf = 0; mf < 2; mf++)
            #pragma unroll
            for (int h = 0; h < 2; h++) {
                #pragma unroll
                for (int o = 1; o < 4; o <<= 1) {
                    s1[mf][h] += __shfl_xor_sync(0xffffffffu, s1[mf][h], o);
                    s2[mf][h] += __shfl_xor_sync(0xffffffffu, s2[mf][h], o);
                }
                if (qc == 0) {
                    stats[(warpN*128 + Row[mf][h])*2 + 0] = s1[mf][h];
                    stats[(warpN*128 + Row[mf][h])*2 + 1] = s2[mf][h];
                }
            }
        __syncthreads();
        #pragma unroll
        for (int mf = 0; mf < 2; mf++)
            #pragma unroll
            for (int h = 0; h < 2; h++) {
                int R = Row[mf][h];
                float S1 = stats[R*2] + stats[(128 + R)*2];
                float S2 = stats[R*2 + 1] + stats[(128 + R)*2 + 1];
                float mu = S1 * (1.0f / NH);
                float var = S2 * (1.0f / NH) - mu * mu;
                float rinv = rsqrtf(var + 1e-5f);
                #pragma unroll
                for (int j = 0; j < 8; j++) {
                    int C = cBase + j*8;
                    float2 gs = *(const float2*)&ln3s[C];
                    float2 gb = *(const float2*)&ln3b[C];
                    float2 o2;
                    o2.x = (acc[mf][j][2*h+0] - mu) * rinv * gs.x + gb.x;
                    o2.y = (acc[mf][j][2*h+1] - mu) * rinv * gs.y + gb.y;
                    *(float2*)&out_hE[(size_t)(e0 + R)*NH + C] = o2;
                }
            }
    }
}

// ---------------------------------------------------------------------------
// ffn1 (mma): H[128tok x 128col tile] = gelu(h1 @ Wi + bi), store fp16 hi/lo.
// grid (32, 4).
// ---------------------------------------------------------------------------
__global__ void __launch_bounds__(256, 2) ffn1_kernel(const float* __restrict__ bi)
{
    extern __shared__ char sm[];
    uint32_t sb = smem_u32(sm);
    int tid = threadIdx.x;
    int wid = tid >> 5, lane = tid & 31;
    int warpM = wid & 3, warpN = wid >> 2;
    int qr = lane >> 2, qc = lane & 3;
    int bl0 = blockIdx.x * 128;
    int nb  = blockIdx.y * 128;
    int cBase = warpN*64 + 2*qc;

    for (int idx = tid; idx < 128*64; idx += 256) {
        int r = idx >> 6, cp = idx & 63;
        float2 x = *(const float2*)&g_h1[(size_t)(bl0 + r)*NH + cp*2];
        uint2 s = split2(x.x, x.y);
        *(uint32_t*)(sm + OFF_AHI + r*AST + cp*4) = s.x;
        *(uint32_t*)(sm + OFF_ALO + r*AST + cp*4) = s.y;
    }
    copyB(sm, 6 + blockIdx.y);
    __syncthreads();

    float acc[2][8][4];
    mma_layer(sb, warpM, warpN, lane, acc);

    #pragma unroll
    for (int mf = 0; mf < 2; mf++)
        #pragma unroll
        for (int j = 0; j < 8; j++) {
            int C = cBase + j*8;
            float2 bv = *(const float2*)&bi[nb + C];
            #pragma unroll
            for (int h = 0; h < 2; h++) {
                int R = warpM*32 + mf*16 + h*8 + qr;
                float v0 = gelu_f(acc[mf][j][2*h+0] + bv.x);
                float v1 = gelu_f(acc[mf][j][2*h+1] + bv.y);
                uint2 s = split2(v0, v1);
                uint32_t gi = ((uint32_t)(bl0 + R)*FFH + nb + C) >> 1;
                g_Hhi[gi] = s.x;
                g_Hlo[gi] = s.y;
            }
        }
}

// ---------------------------------------------------------------------------
// ffn2 (mma): hV2 = LN2(h1 + H @ Wo + bo) * mask_V. 32 tok/CTA, K=512 in 4
// chunks. grid 128.
// ---------------------------------------------------------------------------
#define F2_AHI 0
#define F2_ALO 8704
#define F2_B   17408
#define F2_STAT 52224
#define SMEM_F2 53504

__global__ void __launch_bounds__(256) ffn2_kernel(
    const float* __restrict__ bo,
    const float* __restrict__ ln2s, const float* __restrict__ ln2b,
    const float* __restrict__ mask_V, float* __restrict__ out_hV)
{
    extern __shared__ char sm[];
    uint32_t sb = smem_u32(sm);
    int tid = threadIdx.x;
    int wid = tid >> 5, lane = tid & 31;
    int warpM = wid & 1, warpN = wid >> 1;   // 2 x 4
    int qr = lane >> 2, qc = lane & 3;
    int bl0 = blockIdx.x * 32;
    int cBase = warpN*32 + 2*qc;

    float acc[4][4];
    #pragma unroll
    for (int j = 0; j < 4; j++)
        #pragma unroll
        for (int c = 0; c < 4; c++) acc[j][c] = 0.0f;

    for (int ch = 0; ch < 4; ch++) {
        // A chunk: 32 rows x 64 uint32 (128 halves)
        #pragma unroll
        for (int i = 0; i < 8; i++) {
            int idx = tid + 256*i;
            int r = idx >> 6, q = idx & 63;
            uint32_t gi = (uint32_t)(bl0 + r)*256 + ch*64 + q;
            *(uint32_t*)(sm + F2_AHI + r*AST + q*4) = g_Hhi[gi];
            *(uint32_t*)(sm + F2_ALO + r*AST + q*4) = g_Hlo[gi];
        }
        // B chunk
        {
            const uint4* src = &g_Wb[(size_t)(10 + ch) * 2176];
            uint4* dst = (uint4*)(sm + F2_B);
            #pragma unroll
            for (int i = 0; i < 9; i++) {
                int idx = tid + 256*i;
                if (idx < 2176) dst[idx] = src[idx];
            }
        }
        __syncthreads();

        uint32_t aHi = sb + F2_AHI + (uint32_t)(warpM*16 + (lane & 15))*AST
                     + (uint32_t)(lane >> 4)*16;
        uint32_t aLo = aHi + (F2_ALO - F2_AHI);
        uint32_t bB  = sb + F2_B + (uint32_t)(lane & 15)*AST
                     + (uint32_t)(warpN*64 + (lane >> 4)*16);

        #pragma unroll
        for (int ks = 0; ks < 8; ks++) {
            uint32_t ah[4], al[4];
            ldm4(ah, aHi + ks*32);
            ldm4(al, aLo + ks*32);
            #pragma unroll
            for (int ng = 0; ng < 2; ng++) {
                uint32_t bh[4];
                ldm4t(bh, bB + ks*16*AST + ng*32);
                mma_f16(acc[2*ng],   ah, bh[0], bh[1]);
                mma_f16(acc[2*ng+1], ah, bh[2], bh[3]);
                mma_f16(acc[2*ng],   al, bh[0], bh[1]);
                mma_f16(acc[2*ng+1], al, bh[2], bh[3]);
            }
        }
        __syncthreads();
    }

    // epilogue: residual + LN2 + mask
    float* stats = (float*)(sm + F2_STAT);   // [4 warpN][32 rows][2]
    float s1[2], s2[2];
    #pragma unroll
    for (int h = 0; h < 2; h++) { s1[h] = 0.f; s2[h] = 0.f; }
    #pragma unroll
    for (int j = 0; j < 4; j++) {
        int C = cBase + j*8;
        float2 bv = *(const float2*)&bo[C];
        #pragma unroll
        for (int h = 0; h < 2; h++) {
            int R = warpM*16 + h*8 + qr;
            float2 hv = *(const float2*)&g_h1[(size_t)(bl0 + R)*NH + C];
            float v0 = acc[j][2*h+0] + bv.x + hv.x;
            float v1 = acc[j][2*h+1] + bv.y + hv.y;
            acc[j][2*h+0] = v0;
            acc[j][2*h+1] = v1;
            s1[h] += v0 + v1;
            s2[h] += v0*v0 + v1*v1;
        }
    }
    #pragma unroll
    for (int h = 0; h < 2; h++) {
        #pragma unroll
        for (int o = 1; o < 4; o <<= 1) {
            s1[h] += __shfl_xor_sync(0xffffffffu, s1[h], o);
            s2[h] += __shfl_xor_sync(0xffffffffu, s2[h], o);
        }
        if (qc == 0) {
            int R = warpM*16 + h*8 + qr;
            stats[(warpN*32 + R)*2 + 0] = s1[h];
            stats[(warpN*32 + R)*2 + 1] = s2[h];
        }
    }
    __syncthreads();
    #pragma unroll
    for (int h = 0; h < 2; h++) {
        int R = warpM*16 + h*8 + qr;
        float S1 = 0.f, S2 = 0.f;
        #pragma unroll
        for (int g = 0; g < 4; g++) {
            S1 += stats[(g*32 + R)*2 + 0];
            S2 += stats[(g*32 + R)*2 + 1];
        }
        float mu = S1 * (1.0f / NH);
        float var = S2 * (1.0f / NH) - mu * mu;
        float rinv = rsqrtf(var + 1e-5f);
        int token = bl0 + R;
        float mk = mask_V[token];
        #pragma unroll
        for (int j = 0; j < 4; j++) {
            int C = cBase + j*8;
            float2 gs = *(const float2*)&ln2s[C];
            float2 gb = *(const float2*)&ln2b[C];
            float2 o2;
            o2.x = ((acc[j][2*h+0] - mu) * rinv * gs.x + gb.x) * mk;
            o2.y = ((acc[j][2*h+1] - mu) * rinv * gs.y + gb.y) * mk;
            *(float2*)&g_hV2[(size_t)token*NH + C] = o2;
            *(float2*)&out_hV[(size_t)token*NH + C] = o2;
        }
    }
}

// ---------------------------------------------------------------------------

extern "C" void kernel_launch(void* const* d_in, const int* in_sizes, int n_in,
                              void* d_out, int out_size)
{
    const float* h_V         = (const float*)d_in[0];
    const float* h_E         = (const float*)d_in[1];
    const void*  E_idx       =               d_in[2];
    const float* mask_V      = (const float*)d_in[3];
    const float* mask_attend = (const float*)d_in[4];
    const float* W1  = (const float*)d_in[5],  *b1  = (const float*)d_in[6];
    const float* W2  = (const float*)d_in[7],  *b2  = (const float*)d_in[8];
    const float* W3  = (const float*)d_in[9],  *b3  = (const float*)d_in[10];
    const float* W11 = (const float*)d_in[11], *b11 = (const float*)d_in[12];
    const float* W12 = (const float*)d_in[13], *b12 = (const float*)d_in[14];
    const float* W13 = (const float*)d_in[15], *b13 = (const float*)d_in[16];
    const float* Wi  = (const float*)d_in[17], *bi  = (const float*)d_in[18];
    const float* Wo  = (const float*)d_in[19], *bo  = (const float*)d_in[20];
    const float* ln1s = (const float*)d_in[21], *ln1b = (const float*)d_in[22];
    const float* ln2s = (const float*)d_in[23], *ln2b = (const float*)d_in[24];
    const float* ln3s = (const float*)d_in[25], *ln3b = (const float*)d_in[26];
    float* out = (float*)d_out;

    float *pP1, *pG1, *pP2, *pG2, *pHV2;
    cudaGetSymbolAddress((void**)&pP1,  g_P1);
    cudaGetSymbolAddress((void**)&pG1,  g_G1);
    cudaGetSymbolAddress((void**)&pP2,  g_P2);
    cudaGetSymbolAddress((void**)&pG2,  g_G2);
    cudaGetSymbolAddress((void**)&pHV2, g_hV2);

    int sm_tg = (32*NH + 32*NH) * (int)sizeof(float);

    cudaFuncSetAttribute(token_gemmPG, cudaFuncAttributeMaxDynamicSharedMemorySize, sm_tg);
    cudaFuncSetAttribute(ffn1_kernel, cudaFuncAttributeMaxDynamicSharedMemorySize, SMEM_MLP3);
    cudaFuncSetAttribute(ffn2_kernel, cudaFuncAttributeMaxDynamicSharedMemorySize, SMEM_F2);
    cudaFuncSetAttribute(mlp3_kernel<0>, cudaFuncAttributeMaxDynamicSharedMemorySize, SMEM_MLP3);
    cudaFuncSetAttribute(mlp3_kernel<1>, cudaFuncAttributeMaxDynamicSharedMemorySize, SMEM_MLP3);

    detect_kernel<<<1, 256>>>((const int*)E_idx);
    convert_kernel<<<(NEDGE + 255) / 256, 256>>>(E_idx);

    wprep_kernel<<<(14*16384 + 255)/256, 256>>>(W1 + 128*NH, W2, W3,
                                                W11 + 128*NH, W12, W13, Wi, Wo);

    token_gemmPG<<<128, 256, sm_tg>>>(h_V, W1, b1, W1 + 256*NH, pP1, pG1);

    mlp3_kernel<0><<<NEDGE/128, 256, SMEM_MLP3>>>(h_E, pP1, pG1, b2, b3,
                                                  mask_attend, nullptr, nullptr,
                                                  nullptr, 0);
    nodeLN_kernel<<<NTOK, 128>>>(h_V, ln1s, ln1b);

    ffn1_kernel<<<dim3(32, 4), 256, SMEM_MLP3>>>(bi);
    ffn2_kernel<<<128, 256, SMEM_F2>>>(bo, ln2s, ln2b, mask_V, out);

    token_gemmPG<<<128, 256, sm_tg>>>(pHV2, W11, b11, W11 + 256*NH, pP2, pG2);

    mlp3_kernel<1><<<NEDGE/128, 256, SMEM_MLP3>>>(h_E, pP2, pG2, b12, b13,
                                                  nullptr, ln3s, ln3b,
                                                  out + (size_t)NTOK * NH, 3);
}

// round 8
// speedup vs baseline: 4.3690x; 1.0750x over previous
#include <cuda_runtime.h>
#include <cuda_fp16.h>
#include <math.h>
#include <stdint.h>

#define NB 2
#define NL 2048
#define NK 48
#define NH 128
#define NTOK (NB*NL)
#define NEDGE (NB*NL*NK)
#define FFH 512

__device__ int   g_is64;
__device__ int   g_idx32[NEDGE];
__device__ float g_hV2[NTOK*NH];
__device__ float g_h1 [NTOK*NH];
__device__ uint32_t g_Hhi[NTOK*FFH/2];
__device__ uint32_t g_Hlo[NTOK*FFH/2];
__device__ float g_P1 [NTOK*NH];
__device__ float g_G1 [NTOK*NH];
__device__ float g_P2 [NTOK*NH];
__device__ float g_G2 [NTOK*NH];
__device__ float g_partA[NTOK*NH];
__device__ float g_partB[NTOK*NH];
// 18 fp16 matrices [k][n] (128x128), rows padded to 272B -> 2176 uint4 each
// 0-2 node MLP, 3-5 edge MLP, 6-9 Wi col-tiles, 10-13 Wo k-chunks,
// 14 W1-P, 15 W1-G, 16 W11-P, 17 W11-G
__device__ uint4 g_Wb[18*2176];

#define AST 272
// 64-row tile layout
#define M_AHI 0
#define M_ALO 17408
#define M_B   34816
#define M_STAT 69632
#define SMEM64 71680

__device__ __forceinline__ float gelu_f(float x) {
    return 0.5f * x * (1.0f + erff(x * 0.7071067811865475f));
}

__device__ __forceinline__ uint32_t smem_u32(const void* p) {
    uint32_t a;
    asm("{ .reg .u64 t; cvta.to.shared.u64 t, %1; cvt.u32.u64 %0, t; }"
        : "=r"(a) : "l"(p));
    return a;
}

__device__ __forceinline__ uint32_t pack_f16(float v0, float v1) {
    __half2 h = __floats2half2_rn(v0, v1);
    return *(uint32_t*)&h;
}

__device__ __forceinline__ uint2 split2(float v0, float v1) {
    __half h0 = __float2half_rn(v0), h1 = __float2half_rn(v1);
    float r0 = v0 - __half2float(h0), r1 = v1 - __half2float(h1);
    uint32_t hi = ((uint32_t)__half_as_ushort(h1) << 16) | (uint32_t)__half_as_ushort(h0);
    return make_uint2(hi, pack_f16(r0, r1));
}

__device__ __forceinline__ void ldm4(uint32_t r[4], uint32_t a) {
    asm volatile("ldmatrix.sync.aligned.m8n8.x4.shared.b16 {%0,%1,%2,%3}, [%4];"
        : "=r"(r[0]), "=r"(r[1]), "=r"(r[2]), "=r"(r[3]) : "r"(a));
}
__device__ __forceinline__ void ldm4t(uint32_t r[4], uint32_t a) {
    asm volatile("ldmatrix.sync.aligned.m8n8.x4.trans.shared.b16 {%0,%1,%2,%3}, [%4];"
        : "=r"(r[0]), "=r"(r[1]), "=r"(r[2]), "=r"(r[3]) : "r"(a));
}
__device__ __forceinline__ void mma_f16(float c[4], const uint32_t a[4],
                                        uint32_t b0, uint32_t b1) {
    asm volatile(
        "mma.sync.aligned.m16n8k16.row.col.f32.f16.f16.f32 "
        "{%0,%1,%2,%3}, {%4,%5,%6,%7}, {%8,%9}, {%0,%1,%2,%3};"
        : "+f"(c[0]), "+f"(c[1]), "+f"(c[2]), "+f"(c[3])
        : "r"(a[0]), "r"(a[1]), "r"(a[2]), "r"(a[3]), "r"(b0), "r"(b1));
}

// ---------------------------------------------------------------------------
__global__ void detect_kernel(const int* __restrict__ w) {
    int nz = 0;
    for (int i = 2 * (int)threadIdx.x + 1; i < 1024; i += 512) nz |= (w[i] != 0);
    unsigned any = __ballot_sync(0xffffffffu, nz);
    __shared__ int s[8];
    if ((threadIdx.x & 31) == 0) s[threadIdx.x >> 5] = (any != 0);
    __syncthreads();
    if (threadIdx.x == 0) {
        int a = 0;
        #pragma unroll
        for (int i = 0; i < 8; i++) a |= s[i];
        g_is64 = (a == 0);
    }
}

__global__ void convert_kernel(const void* __restrict__ e) {
    int i = blockIdx.x * blockDim.x + threadIdx.x;
    if (i >= NEDGE) return;
    if (g_is64) g_idx32[i] = (int)((const long long*)e)[i];
    else        g_idx32[i] = ((const int*)e)[i];
}

// ---------------------------------------------------------------------------
// wprep: all weights -> fp16 tiles [k][n], rows padded to 272B.
// ---------------------------------------------------------------------------
__global__ void wprep_kernel(const float* W0, const float* W1, const float* W2,
                             const float* W3, const float* W4, const float* W5,
                             const float* Wi, const float* Wo,
                             const float* W1full, const float* W11full) {
    int gid = blockIdx.x * 256 + threadIdx.x;
    if (gid >= 18 * 16384) return;
    int m = gid >> 14, rem = gid & 16383;
    int k = rem >> 7, n = rem & 127;
    float v;
    if (m < 6) {
        const float* W = (m == 0) ? W0 : (m == 1) ? W1 : (m == 2) ? W2
                       : (m == 3) ? W3 : (m == 4) ? W4 : W5;
        v = W[k * 128 + n];
    } else if (m < 10) {
        v = Wi[k * FFH + (m - 6) * 128 + n];
    } else if (m < 14) {
        v = Wo[((m - 10) * 128 + k) * 128 + n];
    } else if (m == 14) {
        v = W1full[k * 128 + n];
    } else if (m == 15) {
        v = W1full[(256 + k) * 128 + n];
    } else if (m == 16) {
        v = W11full[k * 128 + n];
    } else {
        v = W11full[(256 + k) * 128 + n];
    }
    char* basep = (char*)g_Wb + (size_t)m * 34816;
    *(__half*)(basep + (uint32_t)k * 272u + (uint32_t)n * 2u) = __float2half_rn(v);
}

// ---------------------------------------------------------------------------
// nodeLN: gather 2-slot partials, scale, residual, LN1 -> g_h1
// ---------------------------------------------------------------------------
__global__ void nodeLN_kernel(const float* __restrict__ hV,
                              const float* __restrict__ ln1s,
                              const float* __restrict__ ln1b)
{
    int t = blockIdx.x, c = threadIdx.x;   // 128 threads
    int s0 = t * 48;
    float p = g_partA[(size_t)t*NH + c];
    if (s0 / 64 != (s0 + 47) / 64) p += g_partB[(size_t)t*NH + c];
    float x = hV[(size_t)t*NH + c] + p * (1.0f / 30.0f);
    float a = x, b = x * x;
    #pragma unroll
    for (int o = 16; o; o >>= 1) {
        a += __shfl_xor_sync(0xffffffffu, a, o);
        b += __shfl_xor_sync(0xffffffffu, b, o);
    }
    __shared__ float sA[4], sB[4];
    int w = c >> 5, l = c & 31;
    if (l == 0) { sA[w] = a; sB[w] = b; }
    __syncthreads();
    float sum = sA[0] + sA[1] + sA[2] + sA[3];
    float ssq = sB[0] + sB[1] + sB[2] + sB[3];
    float mu = sum * (1.0f / NH);
    float var = ssq * (1.0f / NH) - mu * mu;
    float ri = rsqrtf(var + 1e-5f);
    g_h1[(size_t)t*NH + c] = (x - mu) * ri * ln1s[c] + ln1b[c];
}

// ---------------------------------------------------------------------------
// Shared mma machinery: 64 rows x 128 cols, K=128. 8 warps = 2(M) x 4(N).
// ---------------------------------------------------------------------------
__device__ __forceinline__ void copyB(char* sm, int mat) {
    const uint4* src = &g_Wb[(size_t)mat * 2176];
    uint4* dst = (uint4*)(sm + M_B);
    #pragma unroll
    for (int i = 0; i < 9; i++) {
        int idx = threadIdx.x + 256*i;
        if (idx < 2176) dst[idx] = src[idx];
    }
}

__device__ __forceinline__ void mma_layer64(uint32_t sb, int warpM, int warpN,
                                            int lane, float (&acc)[2][4][4]) {
    #pragma unroll
    for (int m = 0; m < 2; m++)
        #pragma unroll
        for (int j = 0; j < 4; j++)
            #pragma unroll
            for (int c = 0; c < 4; c++) acc[m][j][c] = 0.0f;

    uint32_t aHi = sb + M_AHI + (uint32_t)(warpM*32 + (lane & 15))*AST
                 + (uint32_t)(lane >> 4)*16;
    uint32_t aLo = aHi + (M_ALO - M_AHI);
    uint32_t bB  = sb + M_B + (uint32_t)(lane & 15)*AST
                 + (uint32_t)(warpN*4 + (lane >> 4))*16;

    #pragma unroll
    for (int ks = 0; ks < 8; ks++) {
        uint32_t ah0[4], ah1[4], al0[4], al1[4];
        ldm4(ah0, aHi + ks*32);
        ldm4(ah1, aHi + ks*32 + 16*AST);
        ldm4(al0, aLo + ks*32);
        ldm4(al1, aLo + ks*32 + 16*AST);
        #pragma unroll
        for (int ng = 0; ng < 2; ng++) {
            uint32_t bh[4];
            ldm4t(bh, bB + ks*16*AST + ng*32);
            mma_f16(acc[0][2*ng],   ah0, bh[0], bh[1]);
            mma_f16(acc[1][2*ng],   ah1, bh[0], bh[1]);
            mma_f16(acc[0][2*ng+1], ah0, bh[2], bh[3]);
            mma_f16(acc[1][2*ng+1], ah1, bh[2], bh[3]);
            mma_f16(acc[0][2*ng],   al0, bh[0], bh[1]);
            mma_f16(acc[1][2*ng],   al1, bh[0], bh[1]);
            mma_f16(acc[0][2*ng+1], al0, bh[2], bh[3]);
            mma_f16(acc[1][2*ng+1], al1, bh[2], bh[3]);
        }
    }
}

// load 64 fp32 rows from src (row stride NH), split hi/lo into A regions
__device__ __forceinline__ void loadA64(char* sm, const float* src, int tid) {
    for (int idx = tid; idx < 64*64; idx += 256) {
        int r = idx >> 6, cp = idx & 63;
        float2 x = *(const float2*)&src[(size_t)r*NH + cp*2];
        uint2 s = split2(x.x, x.y);
        *(uint32_t*)(sm + M_AHI + r*AST + cp*4) = s.x;
        *(uint32_t*)(sm + M_ALO + r*AST + cp*4) = s.y;
    }
}

// ---------------------------------------------------------------------------
// tokenPG (mma): C[64x128] = A @ W (+bias). y=0 -> P (bias), y=1 -> G.
// ---------------------------------------------------------------------------
__global__ void __launch_bounds__(256, 3) tokenPG_kernel(
    const float* __restrict__ A, const float* __restrict__ bias,
    float* __restrict__ P, float* __restrict__ G, int matBase)
{
    extern __shared__ char sm[];
    uint32_t sb = smem_u32(sm);
    int tid = threadIdx.x;
    int wid = tid >> 5, lane = tid & 31;
    int warpM = wid & 1, warpN = wid >> 1;
    int qr = lane >> 2, qc = lane & 3;
    int bl0 = blockIdx.x * 64;
    int cBase = warpN*32 + 2*qc;
    int isP = (blockIdx.y == 0);
    float* Out = isP ? P : G;

    loadA64(sm, A + (size_t)bl0*NH, tid);
    copyB(sm, matBase + blockIdx.y);
    __syncthreads();

    float acc[2][4][4];
    mma_layer64(sb, warpM, warpN, lane, acc);

    #pragma unroll
    for (int mf = 0; mf < 2; mf++)
        #pragma unroll
        for (int j = 0; j < 4; j++) {
            int C = cBase + j*8;
            float2 bv = make_float2(0.f, 0.f);
            if (isP) bv = *(const float2*)&bias[C];
            #pragma unroll
            for (int h = 0; h < 2; h++) {
                int R = warpM*32 + mf*16 + h*8 + qr;
                float2 o2;
                o2.x = acc[mf][j][2*h+0] + bv.x;
                o2.y = acc[mf][j][2*h+1] + bv.y;
                *(float2*)&Out[(size_t)(bl0 + R)*NH + C] = o2;
            }
        }
}

// ---------------------------------------------------------------------------
// mlp3: 64 edge rows per CTA, 3 chained layers. MODE 0 = node, 1 = edge.
// ---------------------------------------------------------------------------
template<int MODE>
__global__ void __launch_bounds__(256, 3) mlp3_kernel(
    const float* __restrict__ hE,
    const float* __restrict__ P, const float* __restrict__ G,
    const float* __restrict__ bias2, const float* __restrict__ bias3,
    const float* __restrict__ mask_attend,
    const float* __restrict__ ln3s, const float* __restrict__ ln3b,
    float* __restrict__ out_hE, int matBase)
{
    extern __shared__ char sm[];
    uint32_t sb = smem_u32(sm);

    int tid = threadIdx.x;
    int wid = tid >> 5, lane = tid & 31;
    int warpM = wid & 1, warpN = wid >> 1;
    int qr = lane >> 2, qc = lane & 3;
    int e0 = blockIdx.x * 64;
    int cBase = warpN*32 + 2*qc;

    int Row[2][2];
    #pragma unroll
    for (int mf = 0; mf < 2; mf++)
        #pragma unroll
        for (int h = 0; h < 2; h++)
            Row[mf][h] = warpM*32 + mf*16 + h*8 + qr;

    loadA64(sm, hE + (size_t)e0*NH, tid);
    copyB(sm, matBase + 0);
    __syncthreads();

    float acc[2][4][4];

    // ---- layer 1 ----
    mma_layer64(sb, warpM, warpN, lane, acc);
    __syncthreads();
    {
        const float* Pr[2][2];
        const float* Gr[2][2];
        #pragma unroll
        for (int mf = 0; mf < 2; mf++)
            #pragma unroll
            for (int h = 0; h < 2; h++) {
                int e = e0 + Row[mf][h];
                int tok = e / 48;
                int batch = (e >= NL*NK) ? 1 : 0;
                Pr[mf][h] = P + (size_t)tok * NH;
                Gr[mf][h] = G + (size_t)(batch*NL + g_idx32[e]) * NH;
            }
        #pragma unroll
        for (int mf = 0; mf < 2; mf++)
            #pragma unroll
            for (int j = 0; j < 4; j++) {
                int C = cBase + j*8;
                #pragma unroll
                for (int h = 0; h < 2; h++) {
                    float2 pv = *(const float2*)&Pr[mf][h][C];
                    float2 gv = *(const float2*)&Gr[mf][h][C];
                    float v0 = gelu_f(acc[mf][j][2*h+0] + pv.x + gv.x);
                    float v1 = gelu_f(acc[mf][j][2*h+1] + pv.y + gv.y);
                    uint2 s = split2(v0, v1);
                    int R = Row[mf][h];
                    *(uint32_t*)(sm + M_AHI + R*AST + C*2) = s.x;
                    *(uint32_t*)(sm + M_ALO + R*AST + C*2) = s.y;
                }
            }
    }
    copyB(sm, matBase + 1);
    __syncthreads();

    // ---- layer 2 ----
    mma_layer64(sb, warpM, warpN, lane, acc);
    __syncthreads();
    #pragma unroll
    for (int mf = 0; mf < 2; mf++)
        #pragma unroll
        for (int j = 0; j < 4; j++) {
            int C = cBase + j*8;
            float2 bv = *(const float2*)&bias2[C];
            #pragma unroll
            for (int h = 0; h < 2; h++) {
                float v0 = gelu_f(acc[mf][j][2*h+0] + bv.x);
                float v1 = gelu_f(acc[mf][j][2*h+1] + bv.y);
                uint2 s = split2(v0, v1);
                int R = Row[mf][h];
                *(uint32_t*)(sm + M_AHI + R*AST + C*2) = s.x;
                *(uint32_t*)(sm + M_ALO + R*AST + C*2) = s.y;
            }
        }
    copyB(sm, matBase + 2);
    __syncthreads();

    // ---- layer 3 ----
    mma_layer64(sb, warpM, warpN, lane, acc);
    __syncthreads();

    if (MODE == 0) {
        float* stage = (float*)(sm + M_AHI);  // [64][136] f32, aliases A
        #pragma unroll
        for (int mf = 0; mf < 2; mf++)
            #pragma unroll
            for (int h = 0; h < 2; h++) {
                int R = Row[mf][h];
                float mk = mask_attend[e0 + R];
                #pragma unroll
                for (int j = 0; j < 4; j++) {
                    int C = cBase + j*8;
                    float2 bv = *(const float2*)&bias3[C];
                    float2 o2;
                    o2.x = (acc[mf][j][2*h+0] + bv.x) * mk;
                    o2.y = (acc[mf][j][2*h+1] + bv.y) * mk;
                    *(float2*)&stage[R*136 + C] = o2;
                }
            }
        __syncthreads();
        int t0 = e0 / 48;
        int tend = (e0 + 63) / 48;
        for (int t = t0 + (tid >> 7); t <= tend; t += 2) {
            int col = tid & 127;
            int rs = max(t*48 - e0, 0), re = min(t*48 + 47 - e0, 63);
            float sacc = 0.0f;
            for (int rr = rs; rr <= re; rr++) sacc += stage[rr*136 + col];
            if (t*48 >= e0) g_partA[(size_t)t*NH + col] = sacc;
            else            g_partB[(size_t)t*NH + col] = sacc;
        }
    } else {
        float* stats = (float*)(sm + M_STAT);   // [4 warpN][64 rows][2]
        float s1[2][2], s2[2][2];
        #pragma unroll
        for (int mf = 0; mf < 2; mf++)
            #pragma unroll
            for (int h = 0; h < 2; h++) { s1[mf][h] = 0.f; s2[mf][h] = 0.f; }
        #pragma unroll
        for (int mf = 0; mf < 2; mf++)
            #pragma unroll
            for (int j = 0; j < 4; j++) {
                int C = cBase + j*8;
                float2 bv = *(const float2*)&bias3[C];
                #pragma unroll
                for (int h = 0; h < 2; h++) {
                    int R = Row[mf][h];
                    float2 he = *(const float2*)&hE[(size_t)(e0 + R)*NH + C];
                    float v0 = acc[mf][j][2*h+0] + bv.x + he.x;
                    float v1 = acc[mf][j][2*h+1] + bv.y + he.y;
                    acc[mf][j][2*h+0] = v0;
                    acc[mf][j][2*h+1] = v1;
                    s1[mf][h] += v0 + v1;
                    s2[mf][h] += v0*v0 + v1*v1;
                }
            }
        #pragma unroll
        for (int mf = 0; mf < 2; mf++)
            #pragma unroll
            for (int h = 0; h < 2; h++) {
                #pragma unroll
                for (int o = 1; o < 4; o <<= 1) {
                    s1[mf][h] += __shfl_xor_sync(0xffffffffu, s1[mf][h], o);
                    s2[mf][h] += __shfl_xor_sync(0xffffffffu, s2[mf][h], o);
                }
                if (qc == 0) {
                    stats[(warpN*64 + Row[mf][h])*2 + 0] = s1[mf][h];
                    stats[(warpN*64 + Row[mf][h])*2 + 1] = s2[mf][h];
                }
            }
        __syncthreads();
        #pragma unroll
        for (int mf = 0; mf < 2; mf++)
            #pragma unroll
            for (int h = 0; h < 2; h++) {
                int R = Row[mf][h];
                float S1 = 0.f, S2 = 0.f;
                #pragma unroll
                for (int g = 0; g < 4; g++) {
                    S1 += stats[(g*64 + R)*2 + 0];
                    S2 += stats[(g*64 + R)*2 + 1];
                }
                float mu = S1 * (1.0f / NH);
                float var = S2 * (1.0f / NH) - mu * mu;
                float rinv = rsqrtf(var + 1e-5f);
                #pragma unroll
                for (int j = 0; j < 4; j++) {
                    int C = cBase + j*8;
                    float2 gs = *(const float2*)&ln3s[C];
                    float2 gb = *(const float2*)&ln3b[C];
                    float2 o2;
                    o2.x = (acc[mf][j][2*h+0] - mu) * rinv * gs.x + gb.x;
                    o2.y = (acc[mf][j][2*h+1] - mu) * rinv * gs.y + gb.y;
                    *(float2*)&out_hE[(size_t)(e0 + R)*NH + C] = o2;
                }
            }
    }
}

// ---------------------------------------------------------------------------
// ffn1 (mma): H tile [64tok x 128col] = gelu(h1 @ Wi + bi), store fp16 hi/lo.
// grid (64, 4).
// ---------------------------------------------------------------------------
__global__ void __launch_bounds__(256, 3) ffn1_kernel(const float* __restrict__ bi)
{
    extern __shared__ char sm[];
    uint32_t sb = smem_u32(sm);
    int tid = threadIdx.x;
    int wid = tid >> 5, lane = tid & 31;
    int warpM = wid & 1, warpN = wid >> 1;
    int qr = lane >> 2, qc = lane & 3;
    int bl0 = blockIdx.x * 64;
    int nb  = blockIdx.y * 128;
    int cBase = warpN*32 + 2*qc;

    loadA64(sm, g_h1 + (size_t)bl0*NH, tid);
    copyB(sm, 6 + blockIdx.y);
    __syncthreads();

    float acc[2][4][4];
    mma_layer64(sb, warpM, warpN, lane, acc);

    #pragma unroll
    for (int mf = 0; mf < 2; mf++)
        #pragma unroll
        for (int j = 0; j < 4; j++) {
            int C = cBase + j*8;
            float2 bv = *(const float2*)&bi[nb + C];
            #pragma unroll
            for (int h = 0; h < 2; h++) {
                int R = warpM*32 + mf*16 + h*8 + qr;
                float v0 = gelu_f(acc[mf][j][2*h+0] + bv.x);
                float v1 = gelu_f(acc[mf][j][2*h+1] + bv.y);
                uint2 s = split2(v0, v1);
                uint32_t gi = ((uint32_t)(bl0 + R)*FFH + nb + C) >> 1;
                g_Hhi[gi] = s.x;
                g_Hlo[gi] = s.y;
            }
        }
}

// ---------------------------------------------------------------------------
// ffn2 (mma): hV2 = LN2(h1 + H @ Wo + bo) * mask_V. 32 tok/CTA, K=512.
// ---------------------------------------------------------------------------
#define F2_AHI 0
#define F2_ALO 8704
#define F2_B   17408
#define F2_STAT 52224
#define SMEM_F2 53504

__global__ void __launch_bounds__(256) ffn2_kernel(
    const float* __restrict__ bo,
    const float* __restrict__ ln2s, const float* __restrict__ ln2b,
    const float* __restrict__ mask_V, float* __restrict__ out_hV)
{
    extern __shared__ char sm[];
    uint32_t sb = smem_u32(sm);
    int tid = threadIdx.x;
    int wid = tid >> 5, lane = tid & 31;
    int warpM = wid & 1, warpN = wid >> 1;   // 2 x 4
    int qr = lane >> 2, qc = lane & 3;
    int bl0 = blockIdx.x * 32;
    int cBase = warpN*32 + 2*qc;

    float acc[4][4];
    #pragma unroll
    for (int j = 0; j < 4; j++)
        #pragma unroll
        for (int c = 0; c < 4; c++) acc[j][c] = 0.0f;

    for (int ch = 0; ch < 4; ch++) {
        #pragma unroll
        for (int i = 0; i < 8; i++) {
            int idx = tid + 256*i;
            int r = idx >> 6, q = idx & 63;
            uint32_t gi = (uint32_t)(bl0 + r)*256 + ch*64 + q;
            *(uint32_t*)(sm + F2_AHI + r*AST + q*4) = g_Hhi[gi];
            *(uint32_t*)(sm + F2_ALO + r*AST + q*4) = g_Hlo[gi];
        }
        {
            const uint4* src = &g_Wb[(size_t)(10 + ch) * 2176];
            uint4* dst = (uint4*)(sm + F2_B);
            #pragma unroll
            for (int i = 0; i < 9; i++) {
                int idx = tid + 256*i;
                if (idx < 2176) dst[idx] = src[idx];
            }
        }
        __syncthreads();

        uint32_t aHi = sb + F2_AHI + (uint32_t)(warpM*16 + (lane & 15))*AST
                     + (uint32_t)(lane >> 4)*16;
        uint32_t aLo = aHi + (F2_ALO - F2_AHI);
        uint32_t bB  = sb + F2_B + (uint32_t)(lane & 15)*AST
                     + (uint32_t)(warpN*64 + (lane >> 4)*16);

        #pragma unroll
        for (int ks = 0; ks < 8; ks++) {
            uint32_t ah[4], al[4];
            ldm4(ah, aHi + ks*32);
            ldm4(al, aLo + ks*32);
            #pragma unroll
            for (int ng = 0; ng < 2; ng++) {
                uint32_t bh[4];
                ldm4t(bh, bB + ks*16*AST + ng*32);
                mma_f16(acc[2*ng],   ah, bh[0], bh[1]);
                mma_f16(acc[2*ng+1], ah, bh[2], bh[3]);
                mma_f16(acc[2*ng],   al, bh[0], bh[1]);
                mma_f16(acc[2*ng+1], al, bh[2], bh[3]);
            }
        }
        __syncthreads();
    }

    float* stats = (float*)(sm + F2_STAT);
    float s1[2], s2[2];
    #pragma unroll
    for (int h = 0; h < 2; h++) { s1[h] = 0.f; s2[h] = 0.f; }
    #pragma unroll
    for (int j = 0; j < 4; j++) {
        int C = cBase + j*8;
        float2 bv = *(const float2*)&bo[C];
        #pragma unroll
        for (int h = 0; h < 2; h++) {
            int R = warpM*16 + h*8 + qr;
            float2 hv = *(const float2*)&g_h1[(size_t)(bl0 + R)*NH + C];
            float v0 = acc[j][2*h+0] + bv.x + hv.x;
            float v1 = acc[j][2*h+1] + bv.y + hv.y;
            acc[j][2*h+0] = v0;
            acc[j][2*h+1] = v1;
            s1[h] += v0 + v1;
            s2[h] += v0*v0 + v1*v1;
        }
    }
    #pragma unroll
    for (int h = 0; h < 2; h++) {
        #pragma unroll
        for (int o = 1; o < 4; o <<= 1) {
            s1[h] += __shfl_xor_sync(0xffffffffu, s1[h], o);
            s2[h] += __shfl_xor_sync(0xffffffffu, s2[h], o);
        }
        if (qc == 0) {
            int R = warpM*16 + h*8 + qr;
            stats[(warpN*32 + R)*2 + 0] = s1[h];
            stats[(warpN*32 + R)*2 + 1] = s2[h];
        }
    }
    __syncthreads();
    #pragma unroll
    for (int h = 0; h < 2; h++) {
        int R = warpM*16 + h*8 + qr;
        float S1 = 0.f, S2 = 0.f;
        #pragma unroll
        for (int g = 0; g < 4; g++) {
            S1 += stats[(g*32 + R)*2 + 0];
            S2 += stats[(g*32 + R)*2 + 1];
        }
        float mu = S1 * (1.0f / NH);
        float var = S2 * (1.0f / NH) - mu * mu;
        float rinv = rsqrtf(var + 1e-5f);
        int token = bl0 + R;
        float mk = mask_V[token];
        #pragma unroll
        for (int j = 0; j < 4; j++) {
            int C = cBase + j*8;
            float2 gs = *(const float2*)&ln2s[C];
            float2 gb = *(const float2*)&ln2b[C];
            float2 o2;
            o2.x = ((acc[j][2*h+0] - mu) * rinv * gs.x + gb.x) * mk;
            o2.y = ((acc[j][2*h+1] - mu) * rinv * gs.y + gb.y) * mk;
            *(float2*)&g_hV2[(size_t)token*NH + C] = o2;
            *(float2*)&out_hV[(size_t)token*NH + C] = o2;
        }
    }
}

// ---------------------------------------------------------------------------

extern "C" void kernel_launch(void* const* d_in, const int* in_sizes, int n_in,
                              void* d_out, int out_size)
{
    const float* h_V         = (const float*)d_in[0];
    const float* h_E         = (const float*)d_in[1];
    const void*  E_idx       =               d_in[2];
    const float* mask_V      = (const float*)d_in[3];
    const float* mask_attend = (const float*)d_in[4];
    const float* W1  = (const float*)d_in[5],  *b1  = (const float*)d_in[6];
    const float* W2  = (const float*)d_in[7],  *b2  = (const float*)d_in[8];
    const float* W3  = (const float*)d_in[9],  *b3  = (const float*)d_in[10];
    const float* W11 = (const float*)d_in[11], *b11 = (const float*)d_in[12];
    const float* W12 = (const float*)d_in[13], *b12 = (const float*)d_in[14];
    const float* W13 = (const float*)d_in[15], *b13 = (const float*)d_in[16];
    const float* Wi  = (const float*)d_in[17], *bi  = (const float*)d_in[18];
    const float* Wo  = (const float*)d_in[19], *bo  = (const float*)d_in[20];
    const float* ln1s = (const float*)d_in[21], *ln1b = (const float*)d_in[22];
    const float* ln2s = (const float*)d_in[23], *ln2b = (const float*)d_in[24];
    const float* ln3s = (const float*)d_in[25], *ln3b = (const float*)d_in[26];
    float* out = (float*)d_out;

    float *pP1, *pG1, *pP2, *pG2, *pHV2;
    cudaGetSymbolAddress((void**)&pP1,  g_P1);
    cudaGetSymbolAddress((void**)&pG1,  g_G1);
    cudaGetSymbolAddress((void**)&pP2,  g_P2);
    cudaGetSymbolAddress((void**)&pG2,  g_G2);
    cudaGetSymbolAddress((void**)&pHV2, g_hV2);

    cudaFuncSetAttribute(tokenPG_kernel, cudaFuncAttributeMaxDynamicSharedMemorySize, SMEM64);
    cudaFuncSetAttribute(ffn1_kernel,  cudaFuncAttributeMaxDynamicSharedMemorySize, SMEM64);
    cudaFuncSetAttribute(ffn2_kernel,  cudaFuncAttributeMaxDynamicSharedMemorySize, SMEM_F2);
    cudaFuncSetAttribute(mlp3_kernel<0>, cudaFuncAttributeMaxDynamicSharedMemorySize, SMEM64);
    cudaFuncSetAttribute(mlp3_kernel<1>, cudaFuncAttributeMaxDynamicSharedMemorySize, SMEM64);

    detect_kernel<<<1, 256>>>((const int*)E_idx);
    convert_kernel<<<(NEDGE + 255) / 256, 256>>>(E_idx);

    wprep_kernel<<<(18*16384 + 255)/256, 256>>>(W1 + 128*NH, W2, W3,
                                                W11 + 128*NH, W12, W13, Wi, Wo,
                                                W1, W11);

    tokenPG_kernel<<<dim3(64, 2), 256, SMEM64>>>(h_V, b1, pP1, pG1, 14);

    mlp3_kernel<0><<<NEDGE/64, 256, SMEM64>>>(h_E, pP1, pG1, b2, b3,
                                              mask_attend, nullptr, nullptr,
                                              nullptr, 0);
    nodeLN_kernel<<<NTOK, 128>>>(h_V, ln1s, ln1b);

    ffn1_kernel<<<dim3(64, 4), 256, SMEM64>>>(bi);
    ffn2_kernel<<<128, 256, SMEM_F2>>>(bo, ln2s, ln2b, mask_V, out);

    tokenPG_kernel<<<dim3(64, 2), 256, SMEM64>>>(pHV2, b11, pP2, pG2, 16);

    mlp3_kernel<1><<<NEDGE/64, 256, SMEM64>>>(h_E, pP2, pG2, b12, b13,
                                              nullptr, ln3s, ln3b,
                                              out + (size_t)NTOK * NH, 3);
}

// round 9
// speedup vs baseline: 4.6732x; 1.0696x over previous
#include <cuda_runtime.h>
#include <cuda_fp16.h>
#include <math.h>
#include <stdint.h>

#define NB 2
#define NL 2048
#define NK 48
#define NH 128
#define NTOK (NB*NL)
#define NEDGE (NB*NL*NK)
#define FFH 512

__device__ int   g_is64;
__device__ int   g_idx32[NEDGE];
__device__ float g_hV2[NTOK*NH];
__device__ float g_h1 [NTOK*NH];
__device__ uint32_t g_Hhi[NTOK*FFH/2];
__device__ uint32_t g_Hlo[NTOK*FFH/2];
__device__ float g_P1 [NTOK*NH];
__device__ float g_G1 [NTOK*NH];
__device__ float g_P2 [NTOK*NH];
__device__ float g_G2 [NTOK*NH];
__device__ float g_partA[NTOK*NH];
__device__ float g_partB[NTOK*NH];
// 18 fp16 matrices [k][n] (128x128), rows padded to 272B -> 2176 uint4 each
// 0-2 node MLP, 3-5 edge MLP, 6-9 Wi col-tiles, 10-13 Wo k-chunks,
// 14 W1-P, 15 W1-G, 16 W11-P, 17 W11-G
__device__ uint4 g_Wb[18*2176];

#define AST 272
// 64-row tile layout
#define M_AHI 0
#define M_ALO 17408
#define M_B   34816
#define M_STAT 69632
#define SMEM64 71680

__device__ __forceinline__ float gelu_f(float x) {
    return 0.5f * x * (1.0f + erff(x * 0.7071067811865475f));
}

__device__ __forceinline__ uint32_t smem_u32(const void* p) {
    uint32_t a;
    asm("{ .reg .u64 t; cvta.to.shared.u64 t, %1; cvt.u32.u64 %0, t; }"
        : "=r"(a) : "l"(p));
    return a;
}

__device__ __forceinline__ uint32_t pack_f16(float v0, float v1) {
    __half2 h = __floats2half2_rn(v0, v1);
    return *(uint32_t*)&h;
}

__device__ __forceinline__ uint2 split2(float v0, float v1) {
    __half h0 = __float2half_rn(v0), h1 = __float2half_rn(v1);
    float r0 = v0 - __half2float(h0), r1 = v1 - __half2float(h1);
    uint32_t hi = ((uint32_t)__half_as_ushort(h1) << 16) | (uint32_t)__half_as_ushort(h0);
    return make_uint2(hi, pack_f16(r0, r1));
}

__device__ __forceinline__ void cp16(uint32_t dst, const void* src) {
    asm volatile("cp.async.cg.shared.global [%0], [%1], 16;"
        :: "r"(dst), "l"(src));
}
#define CP_COMMIT() asm volatile("cp.async.commit_group;" ::: "memory")
#define CP_WAIT0()  asm volatile("cp.async.wait_group 0;" ::: "memory")

__device__ __forceinline__ void ldm4(uint32_t r[4], uint32_t a) {
    asm volatile("ldmatrix.sync.aligned.m8n8.x4.shared.b16 {%0,%1,%2,%3}, [%4];"
        : "=r"(r[0]), "=r"(r[1]), "=r"(r[2]), "=r"(r[3]) : "r"(a));
}
__device__ __forceinline__ void ldm4t(uint32_t r[4], uint32_t a) {
    asm volatile("ldmatrix.sync.aligned.m8n8.x4.trans.shared.b16 {%0,%1,%2,%3}, [%4];"
        : "=r"(r[0]), "=r"(r[1]), "=r"(r[2]), "=r"(r[3]) : "r"(a));
}
__device__ __forceinline__ void mma_f16(float c[4], const uint32_t a[4],
                                        uint32_t b0, uint32_t b1) {
    asm volatile(
        "mma.sync.aligned.m16n8k16.row.col.f32.f16.f16.f32 "
        "{%0,%1,%2,%3}, {%4,%5,%6,%7}, {%8,%9}, {%0,%1,%2,%3};"
        : "+f"(c[0]), "+f"(c[1]), "+f"(c[2]), "+f"(c[3])
        : "r"(a[0]), "r"(a[1]), "r"(a[2]), "r"(a[3]), "r"(b0), "r"(b1));
}

// ---------------------------------------------------------------------------
__global__ void detect_kernel(const int* __restrict__ w) {
    int nz = 0;
    for (int i = 2 * (int)threadIdx.x + 1; i < 1024; i += 512) nz |= (w[i] != 0);
    unsigned any = __ballot_sync(0xffffffffu, nz);
    __shared__ int s[8];
    if ((threadIdx.x & 31) == 0) s[threadIdx.x >> 5] = (any != 0);
    __syncthreads();
    if (threadIdx.x == 0) {
        int a = 0;
        #pragma unroll
        for (int i = 0; i < 8; i++) a |= s[i];
        g_is64 = (a == 0);
    }
}

__global__ void convert_kernel(const void* __restrict__ e) {
    int i = blockIdx.x * blockDim.x + threadIdx.x;
    if (i >= NEDGE) return;
    if (g_is64) g_idx32[i] = (int)((const long long*)e)[i];
    else        g_idx32[i] = ((const int*)e)[i];
}

// ---------------------------------------------------------------------------
// wprep: all weights -> fp16 tiles [k][n], rows padded to 272B.
// ---------------------------------------------------------------------------
__global__ void wprep_kernel(const float* W0, const float* W1, const float* W2,
                             const float* W3, const float* W4, const float* W5,
                             const float* Wi, const float* Wo,
                             const float* W1full, const float* W11full) {
    int gid = blockIdx.x * 256 + threadIdx.x;
    if (gid >= 18 * 16384) return;
    int m = gid >> 14, rem = gid & 16383;
    int k = rem >> 7, n = rem & 127;
    float v;
    if (m < 6) {
        const float* W = (m == 0) ? W0 : (m == 1) ? W1 : (m == 2) ? W2
                       : (m == 3) ? W3 : (m == 4) ? W4 : W5;
        v = W[k * 128 + n];
    } else if (m < 10) {
        v = Wi[k * FFH + (m - 6) * 128 + n];
    } else if (m < 14) {
        v = Wo[((m - 10) * 128 + k) * 128 + n];
    } else if (m == 14) {
        v = W1full[k * 128 + n];
    } else if (m == 15) {
        v = W1full[(256 + k) * 128 + n];
    } else if (m == 16) {
        v = W11full[k * 128 + n];
    } else {
        v = W11full[(256 + k) * 128 + n];
    }
    char* basep = (char*)g_Wb + (size_t)m * 34816;
    *(__half*)(basep + (uint32_t)k * 272u + (uint32_t)n * 2u) = __float2half_rn(v);
}

// ---------------------------------------------------------------------------
// nodeLN: gather 2-slot partials, scale, residual, LN1 -> g_h1
// ---------------------------------------------------------------------------
__global__ void nodeLN_kernel(const float* __restrict__ hV,
                              const float* __restrict__ ln1s,
                              const float* __restrict__ ln1b)
{
    int t = blockIdx.x, c = threadIdx.x;   // 128 threads
    int s0 = t * 48;
    float p = g_partA[(size_t)t*NH + c];
    if (s0 / 64 != (s0 + 47) / 64) p += g_partB[(size_t)t*NH + c];
    float x = hV[(size_t)t*NH + c] + p * (1.0f / 30.0f);
    float a = x, b = x * x;
    #pragma unroll
    for (int o = 16; o; o >>= 1) {
        a += __shfl_xor_sync(0xffffffffu, a, o);
        b += __shfl_xor_sync(0xffffffffu, b, o);
    }
    __shared__ float sA[4], sB[4];
    int w = c >> 5, l = c & 31;
    if (l == 0) { sA[w] = a; sB[w] = b; }
    __syncthreads();
    float sum = sA[0] + sA[1] + sA[2] + sA[3];
    float ssq = sB[0] + sB[1] + sB[2] + sB[3];
    float mu = sum * (1.0f / NH);
    float var = ssq * (1.0f / NH) - mu * mu;
    float ri = rsqrtf(var + 1e-5f);
    g_h1[(size_t)t*NH + c] = (x - mu) * ri * ln1s[c] + ln1b[c];
}

// ---------------------------------------------------------------------------
// Shared mma machinery: 64 rows x 128 cols, K=128. 8 warps = 2(M) x 4(N).
// ---------------------------------------------------------------------------
__device__ __forceinline__ void copyB_async(uint32_t dst, int mat) {
    const uint4* src = &g_Wb[(size_t)mat * 2176];
    #pragma unroll
    for (int i = 0; i < 9; i++) {
        int idx = threadIdx.x + 256*i;
        if (idx < 2176) cp16(dst + idx*16, src + idx);
    }
}

// 2-pass (hi+lo) mma over 64x128x128
__device__ __forceinline__ void mma_layer64(uint32_t sb, int warpM, int warpN,
                                            int lane, float (&acc)[2][4][4]) {
    #pragma unroll
    for (int m = 0; m < 2; m++)
        #pragma unroll
        for (int j = 0; j < 4; j++)
            #pragma unroll
            for (int c = 0; c < 4; c++) acc[m][j][c] = 0.0f;

    uint32_t aHi = sb + M_AHI + (uint32_t)(warpM*32 + (lane & 15))*AST
                 + (uint32_t)(lane >> 4)*16;
    uint32_t aLo = aHi + (M_ALO - M_AHI);
    uint32_t bB  = sb + M_B + (uint32_t)(lane & 15)*AST
                 + (uint32_t)(warpN*4 + (lane >> 4))*16;

    #pragma unroll
    for (int ks = 0; ks < 8; ks++) {
        uint32_t ah0[4], ah1[4], al0[4], al1[4];
        ldm4(ah0, aHi + ks*32);
        ldm4(ah1, aHi + ks*32 + 16*AST);
        ldm4(al0, aLo + ks*32);
        ldm4(al1, aLo + ks*32 + 16*AST);
        #pragma unroll
        for (int ng = 0; ng < 2; ng++) {
            uint32_t bh[4];
            ldm4t(bh, bB + ks*16*AST + ng*32);
            mma_f16(acc[0][2*ng],   ah0, bh[0], bh[1]);
            mma_f16(acc[1][2*ng],   ah1, bh[0], bh[1]);
            mma_f16(acc[0][2*ng+1], ah0, bh[2], bh[3]);
            mma_f16(acc[1][2*ng+1], ah1, bh[2], bh[3]);
            mma_f16(acc[0][2*ng],   al0, bh[0], bh[1]);
            mma_f16(acc[1][2*ng],   al1, bh[0], bh[1]);
            mma_f16(acc[0][2*ng+1], al0, bh[2], bh[3]);
            mma_f16(acc[1][2*ng+1], al1, bh[2], bh[3]);
        }
    }
}

// single-pass (hi only) mma
__device__ __forceinline__ void mma_layer64_hi(uint32_t sb, int warpM, int warpN,
                                               int lane, float (&acc)[2][4][4]) {
    #pragma unroll
    for (int m = 0; m < 2; m++)
        #pragma unroll
        for (int j = 0; j < 4; j++)
            #pragma unroll
            for (int c = 0; c < 4; c++) acc[m][j][c] = 0.0f;

    uint32_t aHi = sb + M_AHI + (uint32_t)(warpM*32 + (lane & 15))*AST
                 + (uint32_t)(lane >> 4)*16;
    uint32_t bB  = sb + M_B + (uint32_t)(lane & 15)*AST
                 + (uint32_t)(warpN*4 + (lane >> 4))*16;

    #pragma unroll
    for (int ks = 0; ks < 8; ks++) {
        uint32_t ah0[4], ah1[4];
        ldm4(ah0, aHi + ks*32);
        ldm4(ah1, aHi + ks*32 + 16*AST);
        #pragma unroll
        for (int ng = 0; ng < 2; ng++) {
            uint32_t bh[4];
            ldm4t(bh, bB + ks*16*AST + ng*32);
            mma_f16(acc[0][2*ng],   ah0, bh[0], bh[1]);
            mma_f16(acc[1][2*ng],   ah1, bh[0], bh[1]);
            mma_f16(acc[0][2*ng+1], ah0, bh[2], bh[3]);
            mma_f16(acc[1][2*ng+1], ah1, bh[2], bh[3]);
        }
    }
}

// load 64 fp32 rows, split hi/lo into both A regions
__device__ __forceinline__ void loadA64(char* sm, const float* src, int tid) {
    for (int idx = tid; idx < 64*64; idx += 256) {
        int r = idx >> 6, cp = idx & 63;
        float2 x = *(const float2*)&src[(size_t)r*NH + cp*2];
        uint2 s = split2(x.x, x.y);
        *(uint32_t*)(sm + M_AHI + r*AST + cp*4) = s.x;
        *(uint32_t*)(sm + M_ALO + r*AST + cp*4) = s.y;
    }
}

// load 64 fp32 rows, hi fp16 only
__device__ __forceinline__ void loadA64_hi(char* sm, const float* src, int tid) {
    for (int idx = tid; idx < 64*64; idx += 256) {
        int r = idx >> 6, cp = idx & 63;
        float2 x = *(const float2*)&src[(size_t)r*NH + cp*2];
        *(uint32_t*)(sm + M_AHI + r*AST + cp*4) = pack_f16(x.x, x.y);
    }
}

// ---------------------------------------------------------------------------
// tokenPG (mma): C[64x128] = A @ W (+bias). y=0 -> P (bias), y=1 -> G.
// ---------------------------------------------------------------------------
__global__ void __launch_bounds__(256, 3) tokenPG_kernel(
    const float* __restrict__ A, const float* __restrict__ bias,
    float* __restrict__ P, float* __restrict__ G, int matBase)
{
    extern __shared__ char sm[];
    uint32_t sb = smem_u32(sm);
    int tid = threadIdx.x;
    int wid = tid >> 5, lane = tid & 31;
    int warpM = wid & 1, warpN = wid >> 1;
    int qr = lane >> 2, qc = lane & 3;
    int bl0 = blockIdx.x * 64;
    int cBase = warpN*32 + 2*qc;
    int isP = (blockIdx.y == 0);
    float* Out = isP ? P : G;

    copyB_async(sb + M_B, matBase + blockIdx.y);
    CP_COMMIT();
    loadA64(sm, A + (size_t)bl0*NH, tid);
    CP_WAIT0();
    __syncthreads();

    float acc[2][4][4];
    mma_layer64(sb, warpM, warpN, lane, acc);

    #pragma unroll
    for (int mf = 0; mf < 2; mf++)
        #pragma unroll
        for (int j = 0; j < 4; j++) {
            int C = cBase + j*8;
            float2 bv = make_float2(0.f, 0.f);
            if (isP) bv = *(const float2*)&bias[C];
            #pragma unroll
            for (int h = 0; h < 2; h++) {
                int R = warpM*32 + mf*16 + h*8 + qr;
                float2 o2;
                o2.x = acc[mf][j][2*h+0] + bv.x;
                o2.y = acc[mf][j][2*h+1] + bv.y;
                *(float2*)&Out[(size_t)(bl0 + R)*NH + C] = o2;
            }
        }
}

// ---------------------------------------------------------------------------
// mlp3: 64 edge rows per CTA, 3 chained layers. Layer 1 single-pass fp16,
// layers 2-3 2-pass. B prefetched via cp.async under epilogues.
// MODE 0 = node, 1 = edge.
// ---------------------------------------------------------------------------
template<int MODE>
__global__ void __launch_bounds__(256, 3) mlp3_kernel(
    const float* __restrict__ hE,
    const float* __restrict__ P, const float* __restrict__ G,
    const float* __restrict__ bias2, const float* __restrict__ bias3,
    const float* __restrict__ mask_attend,
    const float* __restrict__ ln3s, const float* __restrict__ ln3b,
    float* __restrict__ out_hE, int matBase)
{
    extern __shared__ char sm[];
    uint32_t sb = smem_u32(sm);

    int tid = threadIdx.x;
    int wid = tid >> 5, lane = tid & 31;
    int warpM = wid & 1, warpN = wid >> 1;
    int qr = lane >> 2, qc = lane & 3;
    int e0 = blockIdx.x * 64;
    int cBase = warpN*32 + 2*qc;

    int Row[2][2];
    #pragma unroll
    for (int mf = 0; mf < 2; mf++)
        #pragma unroll
        for (int h = 0; h < 2; h++)
            Row[mf][h] = warpM*32 + mf*16 + h*8 + qr;

    copyB_async(sb + M_B, matBase + 0);
    CP_COMMIT();
    loadA64_hi(sm, hE + (size_t)e0*NH, tid);
    CP_WAIT0();
    __syncthreads();

    float acc[2][4][4];

    // ---- layer 1 (single-pass) ----
    mma_layer64_hi(sb, warpM, warpN, lane, acc);
    __syncthreads();
    copyB_async(sb + M_B, matBase + 1);
    CP_COMMIT();
    {
        const float* Pr[2][2];
        const float* Gr[2][2];
        #pragma unroll
        for (int mf = 0; mf < 2; mf++)
            #pragma unroll
            for (int h = 0; h < 2; h++) {
                int e = e0 + Row[mf][h];
                int tok = e / 48;
                int batch = (e >= NL*NK) ? 1 : 0;
                Pr[mf][h] = P + (size_t)tok * NH;
                Gr[mf][h] = G + (size_t)(batch*NL + g_idx32[e]) * NH;
            }
        #pragma unroll
        for (int mf = 0; mf < 2; mf++)
            #pragma unroll
            for (int j = 0; j < 4; j++) {
                int C = cBase + j*8;
                #pragma unroll
                for (int h = 0; h < 2; h++) {
                    float2 pv = *(const float2*)&Pr[mf][h][C];
                    float2 gv = *(const float2*)&Gr[mf][h][C];
                    float v0 = gelu_f(acc[mf][j][2*h+0] + pv.x + gv.x);
                    float v1 = gelu_f(acc[mf][j][2*h+1] + pv.y + gv.y);
                    uint2 s = split2(v0, v1);
                    int R = Row[mf][h];
                    *(uint32_t*)(sm + M_AHI + R*AST + C*2) = s.x;
                    *(uint32_t*)(sm + M_ALO + R*AST + C*2) = s.y;
                }
            }
    }
    CP_WAIT0();
    __syncthreads();

    // ---- layer 2 ----
    mma_layer64(sb, warpM, warpN, lane, acc);
    __syncthreads();
    copyB_async(sb + M_B, matBase + 2);
    CP_COMMIT();
    #pragma unroll
    for (int mf = 0; mf < 2; mf++)
        #pragma unroll
        for (int j = 0; j < 4; j++) {
            int C = cBase + j*8;
            float2 bv = *(const float2*)&bias2[C];
            #pragma unroll
            for (int h = 0; h < 2; h++) {
                float v0 = gelu_f(acc[mf][j][2*h+0] + bv.x);
                float v1 = gelu_f(acc[mf][j][2*h+1] + bv.y);
                uint2 s = split2(v0, v1);
                int R = Row[mf][h];
                *(uint32_t*)(sm + M_AHI + R*AST + C*2) = s.x;
                *(uint32_t*)(sm + M_ALO + R*AST + C*2) = s.y;
            }
        }
    CP_WAIT0();
    __syncthreads();

    // ---- layer 3 ----
    mma_layer64(sb, warpM, warpN, lane, acc);
    __syncthreads();

    if (MODE == 0) {
        float* stage = (float*)(sm + M_AHI);  // [64][136] f32, aliases A
        #pragma unroll
        for (int mf = 0; mf < 2; mf++)
            #pragma unroll
            for (int h = 0; h < 2; h++) {
                int R = Row[mf][h];
                float mk = mask_attend[e0 + R];
                #pragma unroll
                for (int j = 0; j < 4; j++) {
                    int C = cBase + j*8;
                    float2 bv = *(const float2*)&bias3[C];
                    float2 o2;
                    o2.x = (acc[mf][j][2*h+0] + bv.x) * mk;
                    o2.y = (acc[mf][j][2*h+1] + bv.y) * mk;
                    *(float2*)&stage[R*136 + C] = o2;
                }
            }
        __syncthreads();
        int t0 = e0 / 48;
        int tend = (e0 + 63) / 48;
        for (int t = t0 + (tid >> 7); t <= tend; t += 2) {
            int col = tid & 127;
            int rs = max(t*48 - e0, 0), re = min(t*48 + 47 - e0, 63);
            float sacc = 0.0f;
            for (int rr = rs; rr <= re; rr++) sacc += stage[rr*136 + col];
            if (t*48 >= e0) g_partA[(size_t)t*NH + col] = sacc;
            else            g_partB[(size_t)t*NH + col] = sacc;
        }
    } else {
        float* stats = (float*)(sm + M_STAT);   // [4 warpN][64 rows][2]
        float s1[2][2], s2[2][2];
        #pragma unroll
        for (int mf = 0; mf < 2; mf++)
            #pragma unroll
            for (int h = 0; h < 2; h++) { s1[mf][h] = 0.f; s2[mf][h] = 0.f; }
        #pragma unroll
        for (int mf = 0; mf < 2; mf++)
            #pragma unroll
            for (int j = 0; j < 4; j++) {
                int C = cBase + j*8;
                float2 bv = *(const float2*)&bias3[C];
                #pragma unroll
                for (int h = 0; h < 2; h++) {
                    int R = Row[mf][h];
                    float2 he = *(const float2*)&hE[(size_t)(e0 + R)*NH + C];
                    float v0 = acc[mf][j][2*h+0] + bv.x + he.x;
                    float v1 = acc[mf][j][2*h+1] + bv.y + he.y;
                    acc[mf][j][2*h+0] = v0;
                    acc[mf][j][2*h+1] = v1;
                    s1[mf][h] += v0 + v1;
                    s2[mf][h] += v0*v0 + v1*v1;
                }
            }
        #pragma unroll
        for (int mf = 0; mf < 2; mf++)
            #pragma unroll
            for (int h = 0; h < 2; h++) {
                #pragma unroll
                for (int o = 1; o < 4; o <<= 1) {
                    s1[mf][h] += __shfl_xor_sync(0xffffffffu, s1[mf][h], o);
                    s2[mf][h] += __shfl_xor_sync(0xffffffffu, s2[mf][h], o);
                }
                if (qc == 0) {
                    stats[(warpN*64 + Row[mf][h])*2 + 0] = s1[mf][h];
                    stats[(warpN*64 + Row[mf][h])*2 + 1] = s2[mf][h];
                }
            }
        __syncthreads();
        #pragma unroll
        for (int mf = 0; mf < 2; mf++)
            #pragma unroll
            for (int h = 0; h < 2; h++) {
                int R = Row[mf][h];
                float S1 = 0.f, S2 = 0.f;
                #pragma unroll
                for (int g = 0; g < 4; g++) {
                    S1 += stats[(g*64 + R)*2 + 0];
                    S2 += stats[(g*64 + R)*2 + 1];
                }
                float mu = S1 * (1.0f / NH);
                float var = S2 * (1.0f / NH) - mu * mu;
                float rinv = rsqrtf(var + 1e-5f);
                #pragma unroll
                for (int j = 0; j < 4; j++) {
                    int C = cBase + j*8;
                    float2 gs = *(const float2*)&ln3s[C];
                    float2 gb = *(const float2*)&ln3b[C];
                    float2 o2;
                    o2.x = (acc[mf][j][2*h+0] - mu) * rinv * gs.x + gb.x;
                    o2.y = (acc[mf][j][2*h+1] - mu) * rinv * gs.y + gb.y;
                    *(float2*)&out_hE[(size_t)(e0 + R)*NH + C] = o2;
                }
            }
    }
}

// ---------------------------------------------------------------------------
// ffn1 (mma): H tile [64tok x 128col] = gelu(h1 @ Wi + bi), store fp16 hi/lo.
// grid (64, 4).
// ---------------------------------------------------------------------------
__global__ void __launch_bounds__(256, 3) ffn1_kernel(const float* __restrict__ bi)
{
    extern __shared__ char sm[];
    uint32_t sb = smem_u32(sm);
    int tid = threadIdx.x;
    int wid = tid >> 5, lane = tid & 31;
    int warpM = wid & 1, warpN = wid >> 1;
    int qr = lane >> 2, qc = lane & 3;
    int bl0 = blockIdx.x * 64;
    int nb  = blockIdx.y * 128;
    int cBase = warpN*32 + 2*qc;

    copyB_async(sb + M_B, 6 + blockIdx.y);
    CP_COMMIT();
    loadA64(sm, g_h1 + (size_t)bl0*NH, tid);
    CP_WAIT0();
    __syncthreads();

    float acc[2][4][4];
    mma_layer64(sb, warpM, warpN, lane, acc);

    #pragma unroll
    for (int mf = 0; mf < 2; mf++)
        #pragma unroll
        for (int j = 0; j < 4; j++) {
            int C = cBase + j*8;
            float2 bv = *(const float2*)&bi[nb + C];
            #pragma unroll
            for (int h = 0; h < 2; h++) {
                int R = warpM*32 + mf*16 + h*8 + qr;
                float v0 = gelu_f(acc[mf][j][2*h+0] + bv.x);
                float v1 = gelu_f(acc[mf][j][2*h+1] + bv.y);
                uint2 s = split2(v0, v1);
                uint32_t gi = ((uint32_t)(bl0 + R)*FFH + nb + C) >> 1;
                g_Hhi[gi] = s.x;
                g_Hlo[gi] = s.y;
            }
        }
}

// ---------------------------------------------------------------------------
// ffn2 (mma): hV2 = LN2(h1 + H @ Wo + bo) * mask_V. 32 tok/CTA, K=512.
// ---------------------------------------------------------------------------
#define F2_AHI 0
#define F2_ALO 8704
#define F2_B   17408
#define F2_STAT 52224
#define SMEM_F2 53504

__global__ void __launch_bounds__(256) ffn2_kernel(
    const float* __restrict__ bo,
    const float* __restrict__ ln2s, const float* __restrict__ ln2b,
    const float* __restrict__ mask_V, float* __restrict__ out_hV)
{
    extern __shared__ char sm[];
    uint32_t sb = smem_u32(sm);
    int tid = threadIdx.x;
    int wid = tid >> 5, lane = tid & 31;
    int warpM = wid & 1, warpN = wid >> 1;   // 2 x 4
    int qr = lane >> 2, qc = lane & 3;
    int bl0 = blockIdx.x * 32;
    int cBase = warpN*32 + 2*qc;

    float acc[4][4];
    #pragma unroll
    for (int j = 0; j < 4; j++)
        #pragma unroll
        for (int c = 0; c < 4; c++) acc[j][c] = 0.0f;

    for (int ch = 0; ch < 4; ch++) {
        // A chunk: 32 rows x 64 uint32 per region, 16B cp.async
        #pragma unroll
        for (int i = 0; i < 2; i++) {
            int idx = tid + 256*i;          // 512 uint4 per region
            int r = idx >> 4, q4 = (idx & 15) * 4;
            uint32_t gi = (uint32_t)(bl0 + r)*256 + ch*64 + q4;
            cp16(sb + F2_AHI + r*AST + q4*4, &g_Hhi[gi]);
            cp16(sb + F2_ALO + r*AST + q4*4, &g_Hlo[gi]);
        }
        copyB_async(sb + F2_B, 10 + ch);
        CP_COMMIT();
        CP_WAIT0();
        __syncthreads();

        uint32_t aHi = sb + F2_AHI + (uint32_t)(warpM*16 + (lane & 15))*AST
                     + (uint32_t)(lane >> 4)*16;
        uint32_t aLo = aHi + (F2_ALO - F2_AHI);
        uint32_t bB  = sb + F2_B + (uint32_t)(lane & 15)*AST
                     + (uint32_t)(warpN*64 + (lane >> 4)*16);

        #pragma unroll
        for (int ks = 0; ks < 8; ks++) {
            uint32_t ah[4], al[4];
            ldm4(ah, aHi + ks*32);
            ldm4(al, aLo + ks*32);
            #pragma unroll
            for (int ng = 0; ng < 2; ng++) {
                uint32_t bh[4];
                ldm4t(bh, bB + ks*16*AST + ng*32);
                mma_f16(acc[2*ng],   ah, bh[0], bh[1]);
                mma_f16(acc[2*ng+1], ah, bh[2], bh[3]);
                mma_f16(acc[2*ng],   al, bh[0], bh[1]);
                mma_f16(acc[2*ng+1], al, bh[2], bh[3]);
            }
        }
        __syncthreads();
    }

    float* stats = (float*)(sm + F2_STAT);
    float s1[2], s2[2];
    #pragma unroll
    for (int h = 0; h < 2; h++) { s1[h] = 0.f; s2[h] = 0.f; }
    #pragma unroll
    for (int j = 0; j < 4; j++) {
        int C = cBase + j*8;
        float2 bv = *(const float2*)&bo[C];
        #pragma unroll
        for (int h = 0; h < 2; h++) {
            int R = warpM*16 + h*8 + qr;
            float2 hv = *(const float2*)&g_h1[(size_t)(bl0 + R)*NH + C];
            float v0 = acc[j][2*h+0] + bv.x + hv.x;
            float v1 = acc[j][2*h+1] + bv.y + hv.y;
            acc[j][2*h+0] = v0;
            acc[j][2*h+1] = v1;
            s1[h] += v0 + v1;
            s2[h] += v0*v0 + v1*v1;
        }
    }
    #pragma unroll
    for (int h = 0; h < 2; h++) {
        #pragma unroll
        for (int o = 1; o < 4; o <<= 1) {
            s1[h] += __shfl_xor_sync(0xffffffffu, s1[h], o);
            s2[h] += __shfl_xor_sync(0xffffffffu, s2[h], o);
        }
        if (qc == 0) {
            int R = warpM*16 + h*8 + qr;
            stats[(warpN*32 + R)*2 + 0] = s1[h];
            stats[(warpN*32 + R)*2 + 1] = s2[h];
        }
    }
    __syncthreads();
    #pragma unroll
    for (int h = 0; h < 2; h++) {
        int R = warpM*16 + h*8 + qr;
        float S1 = 0.f, S2 = 0.f;
        #pragma unroll
        for (int g = 0; g < 4; g++) {
            S1 += stats[(g*32 + R)*2 + 0];
            S2 += stats[(g*32 + R)*2 + 1];
        }
        float mu = S1 * (1.0f / NH);
        float var = S2 * (1.0f / NH) - mu * mu;
        float rinv = rsqrtf(var + 1e-5f);
        int token = bl0 + R;
        float mk = mask_V[token];
        #pragma unroll
        for (int j = 0; j < 4; j++) {
            int C = cBase + j*8;
            float2 gs = *(const float2*)&ln2s[C];
            float2 gb = *(const float2*)&ln2b[C];
            float2 o2;
            o2.x = ((acc[j][2*h+0] - mu) * rinv * gs.x + gb.x) * mk;
            o2.y = ((acc[j][2*h+1] - mu) * rinv * gs.y + gb.y) * mk;
            *(float2*)&g_hV2[(size_t)token*NH + C] = o2;
            *(float2*)&out_hV[(size_t)token*NH + C] = o2;
        }
    }
}

// ---------------------------------------------------------------------------

extern "C" void kernel_launch(void* const* d_in, const int* in_sizes, int n_in,
                              void* d_out, int out_size)
{
    const float* h_V         = (const float*)d_in[0];
    const float* h_E         = (const float*)d_in[1];
    const void*  E_idx       =               d_in[2];
    const float* mask_V      = (const float*)d_in[3];
    const float* mask_attend = (const float*)d_in[4];
    const float* W1  = (const float*)d_in[5],  *b1  = (const float*)d_in[6];
    const float* W2  = (const float*)d_in[7],  *b2  = (const float*)d_in[8];
    const float* W3  = (const float*)d_in[9],  *b3  = (const float*)d_in[10];
    const float* W11 = (const float*)d_in[11], *b11 = (const float*)d_in[12];
    const float* W12 = (const float*)d_in[13], *b12 = (const float*)d_in[14];
    const float* W13 = (const float*)d_in[15], *b13 = (const float*)d_in[16];
    const float* Wi  = (const float*)d_in[17], *bi  = (const float*)d_in[18];
    const float* Wo  = (const float*)d_in[19], *bo  = (const float*)d_in[20];
    const float* ln1s = (const float*)d_in[21], *ln1b = (const float*)d_in[22];
    const float* ln2s = (const float*)d_in[23], *ln2b = (const float*)d_in[24];
    const float* ln3s = (const float*)d_in[25], *ln3b = (const float*)d_in[26];
    float* out = (float*)d_out;

    float *pP1, *pG1, *pP2, *pG2, *pHV2;
    cudaGetSymbolAddress((void**)&pP1,  g_P1);
    cudaGetSymbolAddress((void**)&pG1,  g_G1);
    cudaGetSymbolAddress((void**)&pP2,  g_P2);
    cudaGetSymbolAddress((void**)&pG2,  g_G2);
    cudaGetSymbolAddress((void**)&pHV2, g_hV2);

    cudaFuncSetAttribute(tokenPG_kernel, cudaFuncAttributeMaxDynamicSharedMemorySize, SMEM64);
    cudaFuncSetAttribute(ffn1_kernel,  cudaFuncAttributeMaxDynamicSharedMemorySize, SMEM64);
    cudaFuncSetAttribute(ffn2_kernel,  cudaFuncAttributeMaxDynamicSharedMemorySize, SMEM_F2);
    cudaFuncSetAttribute(mlp3_kernel<0>, cudaFuncAttributeMaxDynamicSharedMemorySize, SMEM64);
    cudaFuncSetAttribute(mlp3_kernel<1>, cudaFuncAttributeMaxDynamicSharedMemorySize, SMEM64);

    detect_kernel<<<1, 256>>>((const int*)E_idx);
    convert_kernel<<<(NEDGE + 255) / 256, 256>>>(E_idx);

    wprep_kernel<<<(18*16384 + 255)/256, 256>>>(W1 + 128*NH, W2, W3,
                                                W11 + 128*NH, W12, W13, Wi, Wo,
                                                W1, W11);

    tokenPG_kernel<<<dim3(64, 2), 256, SMEM64>>>(h_V, b1, pP1, pG1, 14);

    mlp3_kernel<0><<<NEDGE/64, 256, SMEM64>>>(h_E, pP1, pG1, b2, b3,
                                              mask_attend, nullptr, nullptr,
                                              nullptr, 0);
    nodeLN_kernel<<<NTOK, 128>>>(h_V, ln1s, ln1b);

    ffn1_kernel<<<dim3(64, 4), 256, SMEM64>>>(bi);
    ffn2_kernel<<<128, 256, SMEM_F2>>>(bo, ln2s, ln2b, mask_V, out);

    tokenPG_kernel<<<dim3(64, 2), 256, SMEM64>>>(pHV2, b11, pP2, pG2, 16);

    mlp3_kernel<1><<<NEDGE/64, 256, SMEM64>>>(h_E, pP2, pG2, b12, b13,
                                              nullptr, ln3s, ln3b,
                                              out + (size_t)NTOK * NH, 3);
}

// round 10
// speedup vs baseline: 5.3067x; 1.1356x over previous
#include <cuda_runtime.h>
#include <cuda_fp16.h>
#include <math.h>
#include <stdint.h>

#define NB 2
#define NL 2048
#define NK 48
#define NH 128
#define NTOK (NB*NL)
#define NEDGE (NB*NL*NK)
#define FFH 512

__device__ int   g_is64;
__device__ int   g_idx32[NEDGE];
__device__ float g_hV2[NTOK*NH];
__device__ float g_h1 [NTOK*NH];
__device__ uint32_t g_Hhi[NTOK*FFH/2];
__device__ float g_P1 [NTOK*NH];
__device__ float g_G1 [NTOK*NH];
__device__ float g_P2 [NTOK*NH];
__device__ float g_G2 [NTOK*NH];
__device__ float g_partA[NTOK*NH];
__device__ float g_partB[NTOK*NH];
// 18 fp16 matrices [k][n] (128x128), rows padded to 272B -> 2176 uint4 each
// 0-2 node MLP, 3-5 edge MLP, 6-9 Wi col-tiles, 10-13 Wo k-chunks,
// 14 W1-P, 15 W1-G, 16 W11-P, 17 W11-G
__device__ uint4 g_Wb[18*2176];

#define AST 272
// 64-row tile layout (hi-only A)
#define M_A   0
#define M_B   17408
#define M_STAT 52224
#define SMEM64 54272

__device__ __forceinline__ float gelu_f(float x) {
    return 0.5f * x * (1.0f + erff(x * 0.7071067811865475f));
}

__device__ __forceinline__ uint32_t smem_u32(const void* p) {
    uint32_t a;
    asm("{ .reg .u64 t; cvta.to.shared.u64 t, %1; cvt.u32.u64 %0, t; }"
        : "=r"(a) : "l"(p));
    return a;
}

__device__ __forceinline__ uint32_t pack_f16(float v0, float v1) {
    __half2 h = __floats2half2_rn(v0, v1);
    return *(uint32_t*)&h;
}

__device__ __forceinline__ void cp16(uint32_t dst, const void* src) {
    asm volatile("cp.async.cg.shared.global [%0], [%1], 16;"
        :: "r"(dst), "l"(src));
}
#define CP_COMMIT() asm volatile("cp.async.commit_group;" ::: "memory")
#define CP_WAIT0()  asm volatile("cp.async.wait_group 0;" ::: "memory")

__device__ __forceinline__ void ldm4(uint32_t r[4], uint32_t a) {
    asm volatile("ldmatrix.sync.aligned.m8n8.x4.shared.b16 {%0,%1,%2,%3}, [%4];"
        : "=r"(r[0]), "=r"(r[1]), "=r"(r[2]), "=r"(r[3]) : "r"(a));
}
__device__ __forceinline__ void ldm4t(uint32_t r[4], uint32_t a) {
    asm volatile("ldmatrix.sync.aligned.m8n8.x4.trans.shared.b16 {%0,%1,%2,%3}, [%4];"
        : "=r"(r[0]), "=r"(r[1]), "=r"(r[2]), "=r"(r[3]) : "r"(a));
}
__device__ __forceinline__ void mma_f16(float c[4], const uint32_t a[4],
                                        uint32_t b0, uint32_t b1) {
    asm volatile(
        "mma.sync.aligned.m16n8k16.row.col.f32.f16.f16.f32 "
        "{%0,%1,%2,%3}, {%4,%5,%6,%7}, {%8,%9}, {%0,%1,%2,%3};"
        : "+f"(c[0]), "+f"(c[1]), "+f"(c[2]), "+f"(c[3])
        : "r"(a[0]), "r"(a[1]), "r"(a[2]), "r"(a[3]), "r"(b0), "r"(b1));
}

// ---------------------------------------------------------------------------
__global__ void detect_kernel(const int* __restrict__ w) {
    int nz = 0;
    for (int i = 2 * (int)threadIdx.x + 1; i < 1024; i += 512) nz |= (w[i] != 0);
    unsigned any = __ballot_sync(0xffffffffu, nz);
    __shared__ int s[8];
    if ((threadIdx.x & 31) == 0) s[threadIdx.x >> 5] = (any != 0);
    __syncthreads();
    if (threadIdx.x == 0) {
        int a = 0;
        #pragma unroll
        for (int i = 0; i < 8; i++) a |= s[i];
        g_is64 = (a == 0);
    }
}

__global__ void convert_kernel(const void* __restrict__ e) {
    int i = blockIdx.x * blockDim.x + threadIdx.x;
    if (i >= NEDGE) return;
    if (g_is64) g_idx32[i] = (int)((const long long*)e)[i];
    else        g_idx32[i] = ((const int*)e)[i];
}

// ---------------------------------------------------------------------------
// wprep: all weights -> fp16 tiles [k][n], rows padded to 272B.
// ---------------------------------------------------------------------------
__global__ void wprep_kernel(const float* W0, const float* W1, const float* W2,
                             const float* W3, const float* W4, const float* W5,
                             const float* Wi, const float* Wo,
                             const float* W1full, const float* W11full) {
    int gid = blockIdx.x * 256 + threadIdx.x;
    if (gid >= 18 * 16384) return;
    int m = gid >> 14, rem = gid & 16383;
    int k = rem >> 7, n = rem & 127;
    float v;
    if (m < 6) {
        const float* W = (m == 0) ? W0 : (m == 1) ? W1 : (m == 2) ? W2
                       : (m == 3) ? W3 : (m == 4) ? W4 : W5;
        v = W[k * 128 + n];
    } else if (m < 10) {
        v = Wi[k * FFH + (m - 6) * 128 + n];
    } else if (m < 14) {
        v = Wo[((m - 10) * 128 + k) * 128 + n];
    } else if (m == 14) {
        v = W1full[k * 128 + n];
    } else if (m == 15) {
        v = W1full[(256 + k) * 128 + n];
    } else if (m == 16) {
        v = W11full[k * 128 + n];
    } else {
        v = W11full[(256 + k) * 128 + n];
    }
    char* basep = (char*)g_Wb + (size_t)m * 34816;
    *(__half*)(basep + (uint32_t)k * 272u + (uint32_t)n * 2u) = __float2half_rn(v);
}

// ---------------------------------------------------------------------------
// nodeLN: gather 2-slot partials, scale, residual, LN1 -> g_h1
// ---------------------------------------------------------------------------
__global__ void nodeLN_kernel(const float* __restrict__ hV,
                              const float* __restrict__ ln1s,
                              const float* __restrict__ ln1b)
{
    int t = blockIdx.x, c = threadIdx.x;   // 128 threads
    int s0 = t * 48;
    float p = g_partA[(size_t)t*NH + c];
    if (s0 / 64 != (s0 + 47) / 64) p += g_partB[(size_t)t*NH + c];
    float x = hV[(size_t)t*NH + c] + p * (1.0f / 30.0f);
    float a = x, b = x * x;
    #pragma unroll
    for (int o = 16; o; o >>= 1) {
        a += __shfl_xor_sync(0xffffffffu, a, o);
        b += __shfl_xor_sync(0xffffffffu, b, o);
    }
    __shared__ float sA[4], sB[4];
    int w = c >> 5, l = c & 31;
    if (l == 0) { sA[w] = a; sB[w] = b; }
    __syncthreads();
    float sum = sA[0] + sA[1] + sA[2] + sA[3];
    float ssq = sB[0] + sB[1] + sB[2] + sB[3];
    float mu = sum * (1.0f / NH);
    float var = ssq * (1.0f / NH) - mu * mu;
    float ri = rsqrtf(var + 1e-5f);
    g_h1[(size_t)t*NH + c] = (x - mu) * ri * ln1s[c] + ln1b[c];
}

// ---------------------------------------------------------------------------
// Shared mma machinery: 64 rows x 128 cols, K=128, single-pass fp16.
// 8 warps = 2(M) x 4(N).
// ---------------------------------------------------------------------------
__device__ __forceinline__ void copyB_async(uint32_t dst, int mat) {
    const uint4* src = &g_Wb[(size_t)mat * 2176];
    #pragma unroll
    for (int i = 0; i < 9; i++) {
        int idx = threadIdx.x + 256*i;
        if (idx < 2176) cp16(dst + idx*16, src + idx);
    }
}

__device__ __forceinline__ void mma_layer64(uint32_t sb, int warpM, int warpN,
                                            int lane, float (&acc)[2][4][4]) {
    #pragma unroll
    for (int m = 0; m < 2; m++)
        #pragma unroll
        for (int j = 0; j < 4; j++)
            #pragma unroll
            for (int c = 0; c < 4; c++) acc[m][j][c] = 0.0f;

    uint32_t aA = sb + M_A + (uint32_t)(warpM*32 + (lane & 15))*AST
                + (uint32_t)(lane >> 4)*16;
    uint32_t bB = sb + M_B + (uint32_t)(lane & 15)*AST
                + (uint32_t)(warpN*4 + (lane >> 4))*16;

    #pragma unroll
    for (int ks = 0; ks < 8; ks++) {
        uint32_t ah0[4], ah1[4];
        ldm4(ah0, aA + ks*32);
        ldm4(ah1, aA + ks*32 + 16*AST);
        #pragma unroll
        for (int ng = 0; ng < 2; ng++) {
            uint32_t bh[4];
            ldm4t(bh, bB + ks*16*AST + ng*32);
            mma_f16(acc[0][2*ng],   ah0, bh[0], bh[1]);
            mma_f16(acc[1][2*ng],   ah1, bh[0], bh[1]);
            mma_f16(acc[0][2*ng+1], ah0, bh[2], bh[3]);
            mma_f16(acc[1][2*ng+1], ah1, bh[2], bh[3]);
        }
    }
}

// load 64 fp32 rows -> fp16 hi
__device__ __forceinline__ void loadA64(char* sm, const float* src, int tid) {
    for (int idx = tid; idx < 64*64; idx += 256) {
        int r = idx >> 6, cp = idx & 63;
        float2 x = *(const float2*)&src[(size_t)r*NH + cp*2];
        *(uint32_t*)(sm + M_A + r*AST + cp*4) = pack_f16(x.x, x.y);
    }
}

// ---------------------------------------------------------------------------
// tokenPG (mma): C[64x128] = A @ W (+bias). y=0 -> P (bias), y=1 -> G.
// ---------------------------------------------------------------------------
__global__ void __launch_bounds__(256, 3) tokenPG_kernel(
    const float* __restrict__ A, const float* __restrict__ bias,
    float* __restrict__ P, float* __restrict__ G, int matBase)
{
    extern __shared__ char sm[];
    uint32_t sb = smem_u32(sm);
    int tid = threadIdx.x;
    int wid = tid >> 5, lane = tid & 31;
    int warpM = wid & 1, warpN = wid >> 1;
    int qr = lane >> 2, qc = lane & 3;
    int bl0 = blockIdx.x * 64;
    int cBase = warpN*32 + 2*qc;
    int isP = (blockIdx.y == 0);
    float* Out = isP ? P : G;

    copyB_async(sb + M_B, matBase + blockIdx.y);
    CP_COMMIT();
    loadA64(sm, A + (size_t)bl0*NH, tid);
    CP_WAIT0();
    __syncthreads();

    float acc[2][4][4];
    mma_layer64(sb, warpM, warpN, lane, acc);

    #pragma unroll
    for (int mf = 0; mf < 2; mf++)
        #pragma unroll
        for (int j = 0; j < 4; j++) {
            int C = cBase + j*8;
            float2 bv = make_float2(0.f, 0.f);
            if (isP) bv = *(const float2*)&bias[C];
            #pragma unroll
            for (int h = 0; h < 2; h++) {
                int R = warpM*32 + mf*16 + h*8 + qr;
                float2 o2;
                o2.x = acc[mf][j][2*h+0] + bv.x;
                o2.y = acc[mf][j][2*h+1] + bv.y;
                *(float2*)&Out[(size_t)(bl0 + R)*NH + C] = o2;
            }
        }
}

// ---------------------------------------------------------------------------
// mlp3: 64 edge rows per CTA, 3 chained single-pass fp16 layers.
// B prefetched via cp.async under epilogues. MODE 0 = node, 1 = edge.
// ---------------------------------------------------------------------------
template<int MODE>
__global__ void __launch_bounds__(256, 3) mlp3_kernel(
    const float* __restrict__ hE,
    const float* __restrict__ P, const float* __restrict__ G,
    const float* __restrict__ bias2, const float* __restrict__ bias3,
    const float* __restrict__ mask_attend,
    const float* __restrict__ ln3s, const float* __restrict__ ln3b,
    float* __restrict__ out_hE, int matBase)
{
    extern __shared__ char sm[];
    uint32_t sb = smem_u32(sm);

    int tid = threadIdx.x;
    int wid = tid >> 5, lane = tid & 31;
    int warpM = wid & 1, warpN = wid >> 1;
    int qr = lane >> 2, qc = lane & 3;
    int e0 = blockIdx.x * 64;
    int cBase = warpN*32 + 2*qc;

    int Row[2][2];
    #pragma unroll
    for (int mf = 0; mf < 2; mf++)
        #pragma unroll
        for (int h = 0; h < 2; h++)
            Row[mf][h] = warpM*32 + mf*16 + h*8 + qr;

    copyB_async(sb + M_B, matBase + 0);
    CP_COMMIT();
    loadA64(sm, hE + (size_t)e0*NH, tid);
    CP_WAIT0();
    __syncthreads();

    float acc[2][4][4];

    // ---- layer 1 ----
    mma_layer64(sb, warpM, warpN, lane, acc);
    __syncthreads();
    copyB_async(sb + M_B, matBase + 1);
    CP_COMMIT();
    {
        const float* Pr[2][2];
        const float* Gr[2][2];
        #pragma unroll
        for (int mf = 0; mf < 2; mf++)
            #pragma unroll
            for (int h = 0; h < 2; h++) {
                int e = e0 + Row[mf][h];
                int tok = e / 48;
                int batch = (e >= NL*NK) ? 1 : 0;
                Pr[mf][h] = P + (size_t)tok * NH;
                Gr[mf][h] = G + (size_t)(batch*NL + g_idx32[e]) * NH;
            }
        #pragma unroll
        for (int mf = 0; mf < 2; mf++)
            #pragma unroll
            for (int j = 0; j < 4; j++) {
                int C = cBase + j*8;
                #pragma unroll
                for (int h = 0; h < 2; h++) {
                    float2 pv = *(const float2*)&Pr[mf][h][C];
                    float2 gv = *(const float2*)&Gr[mf][h][C];
                    float v0 = gelu_f(acc[mf][j][2*h+0] + pv.x + gv.x);
                    float v1 = gelu_f(acc[mf][j][2*h+1] + pv.y + gv.y);
                    int R = Row[mf][h];
                    *(uint32_t*)(sm + M_A + R*AST + C*2) = pack_f16(v0, v1);
                }
            }
    }
    CP_WAIT0();
    __syncthreads();

    // ---- layer 2 ----
    mma_layer64(sb, warpM, warpN, lane, acc);
    __syncthreads();
    copyB_async(sb + M_B, matBase + 2);
    CP_COMMIT();
    #pragma unroll
    for (int mf = 0; mf < 2; mf++)
        #pragma unroll
        for (int j = 0; j < 4; j++) {
            int C = cBase + j*8;
            float2 bv = *(const float2*)&bias2[C];
            #pragma unroll
            for (int h = 0; h < 2; h++) {
                float v0 = gelu_f(acc[mf][j][2*h+0] + bv.x);
                float v1 = gelu_f(acc[mf][j][2*h+1] + bv.y);
                int R = Row[mf][h];
                *(uint32_t*)(sm + M_A + R*AST + C*2) = pack_f16(v0, v1);
            }
        }
    CP_WAIT0();
    __syncthreads();

    // ---- layer 3 ----
    mma_layer64(sb, warpM, warpN, lane, acc);
    __syncthreads();

    if (MODE == 0) {
        float* stage = (float*)(sm + M_A);  // [64][136] f32, aliases A+B
        #pragma unroll
        for (int mf = 0; mf < 2; mf++)
            #pragma unroll
            for (int h = 0; h < 2; h++) {
                int R = Row[mf][h];
                float mk = mask_attend[e0 + R];
                #pragma unroll
                for (int j = 0; j < 4; j++) {
                    int C = cBase + j*8;
                    float2 bv = *(const float2*)&bias3[C];
                    float2 o2;
                    o2.x = (acc[mf][j][2*h+0] + bv.x) * mk;
                    o2.y = (acc[mf][j][2*h+1] + bv.y) * mk;
                    *(float2*)&stage[R*136 + C] = o2;
                }
            }
        __syncthreads();
        int t0 = e0 / 48;
        int tend = (e0 + 63) / 48;
        for (int t = t0 + (tid >> 7); t <= tend; t += 2) {
            int col = tid & 127;
            int rs = max(t*48 - e0, 0), re = min(t*48 + 47 - e0, 63);
            float sacc = 0.0f;
            for (int rr = rs; rr <= re; rr++) sacc += stage[rr*136 + col];
            if (t*48 >= e0) g_partA[(size_t)t*NH + col] = sacc;
            else            g_partB[(size_t)t*NH + col] = sacc;
        }
    } else {
        float* stats = (float*)(sm + M_STAT);   // [4 warpN][64 rows][2]
        float s1[2][2], s2[2][2];
        #pragma unroll
        for (int mf = 0; mf < 2; mf++)
            #pragma unroll
            for (int h = 0; h < 2; h++) { s1[mf][h] = 0.f; s2[mf][h] = 0.f; }
        #pragma unroll
        for (int mf = 0; mf < 2; mf++)
            #pragma unroll
            for (int j = 0; j < 4; j++) {
                int C = cBase + j*8;
                float2 bv = *(const float2*)&bias3[C];
                #pragma unroll
                for (int h = 0; h < 2; h++) {
                    int R = Row[mf][h];
                    float2 he = *(const float2*)&hE[(size_t)(e0 + R)*NH + C];
                    float v0 = acc[mf][j][2*h+0] + bv.x + he.x;
                    float v1 = acc[mf][j][2*h+1] + bv.y + he.y;
                    acc[mf][j][2*h+0] = v0;
                    acc[mf][j][2*h+1] = v1;
                    s1[mf][h] += v0 + v1;
                    s2[mf][h] += v0*v0 + v1*v1;
                }
            }
        #pragma unroll
        for (int mf = 0; mf < 2; mf++)
            #pragma unroll
            for (int h = 0; h < 2; h++) {
                #pragma unroll
                for (int o = 1; o < 4; o <<= 1) {
                    s1[mf][h] += __shfl_xor_sync(0xffffffffu, s1[mf][h], o);
                    s2[mf][h] += __shfl_xor_sync(0xffffffffu, s2[mf][h], o);
                }
                if (qc == 0) {
                    stats[(warpN*64 + Row[mf][h])*2 + 0] = s1[mf][h];
                    stats[(warpN*64 + Row[mf][h])*2 + 1] = s2[mf][h];
                }
            }
        __syncthreads();
        #pragma unroll
        for (int mf = 0; mf < 2; mf++)
            #pragma unroll
            for (int h = 0; h < 2; h++) {
                int R = Row[mf][h];
                float S1 = 0.f, S2 = 0.f;
                #pragma unroll
                for (int g = 0; g < 4; g++) {
                    S1 += stats[(g*64 + R)*2 + 0];
                    S2 += stats[(g*64 + R)*2 + 1];
                }
                float mu = S1 * (1.0f / NH);
                float var = S2 * (1.0f / NH) - mu * mu;
                float rinv = rsqrtf(var + 1e-5f);
                #pragma unroll
                for (int j = 0; j < 4; j++) {
                    int C = cBase + j*8;
                    float2 gs = *(const float2*)&ln3s[C];
                    float2 gb = *(const float2*)&ln3b[C];
                    float2 o2;
                    o2.x = (acc[mf][j][2*h+0] - mu) * rinv * gs.x + gb.x;
                    o2.y = (acc[mf][j][2*h+1] - mu) * rinv * gs.y + gb.y;
                    *(float2*)&out_hE[(size_t)(e0 + R)*NH + C] = o2;
                }
            }
    }
}

// ---------------------------------------------------------------------------
// ffn1 (mma): H tile [64tok x 128col] = gelu(h1 @ Wi + bi), store fp16.
// grid (64, 4).
// ---------------------------------------------------------------------------
__global__ void __launch_bounds__(256, 3) ffn1_kernel(const float* __restrict__ bi)
{
    extern __shared__ char sm[];
    uint32_t sb = smem_u32(sm);
    int tid = threadIdx.x;
    int wid = tid >> 5, lane = tid & 31;
    int warpM = wid & 1, warpN = wid >> 1;
    int qr = lane >> 2, qc = lane & 3;
    int bl0 = blockIdx.x * 64;
    int nb  = blockIdx.y * 128;
    int cBase = warpN*32 + 2*qc;

    copyB_async(sb + M_B, 6 + blockIdx.y);
    CP_COMMIT();
    loadA64(sm, g_h1 + (size_t)bl0*NH, tid);
    CP_WAIT0();
    __syncthreads();

    float acc[2][4][4];
    mma_layer64(sb, warpM, warpN, lane, acc);

    #pragma unroll
    for (int mf = 0; mf < 2; mf++)
        #pragma unroll
        for (int j = 0; j < 4; j++) {
            int C = cBase + j*8;
            float2 bv = *(const float2*)&bi[nb + C];
            #pragma unroll
            for (int h = 0; h < 2; h++) {
                int R = warpM*32 + mf*16 + h*8 + qr;
                float v0 = gelu_f(acc[mf][j][2*h+0] + bv.x);
                float v1 = gelu_f(acc[mf][j][2*h+1] + bv.y);
                uint32_t gi = ((uint32_t)(bl0 + R)*FFH + nb + C) >> 1;
                g_Hhi[gi] = pack_f16(v0, v1);
            }
        }
}

// ---------------------------------------------------------------------------
// ffn2 (mma): hV2 = LN2(h1 + H @ Wo + bo) * mask_V. 32 tok/CTA, K=512.
// ---------------------------------------------------------------------------
#define F2_A   0
#define F2_B   8704
#define F2_STAT 43520
#define SMEM_F2 45568

__global__ void __launch_bounds__(256) ffn2_kernel(
    const float* __restrict__ bo,
    const float* __restrict__ ln2s, const float* __restrict__ ln2b,
    const float* __restrict__ mask_V, float* __restrict__ out_hV)
{
    extern __shared__ char sm[];
    uint32_t sb = smem_u32(sm);
    int tid = threadIdx.x;
    int wid = tid >> 5, lane = tid & 31;
    int warpM = wid & 1, warpN = wid >> 1;   // 2 x 4
    int qr = lane >> 2, qc = lane & 3;
    int bl0 = blockIdx.x * 32;
    int cBase = warpN*32 + 2*qc;

    float acc[4][4];
    #pragma unroll
    for (int j = 0; j < 4; j++)
        #pragma unroll
        for (int c = 0; c < 4; c++) acc[j][c] = 0.0f;

    for (int ch = 0; ch < 4; ch++) {
        // A chunk: 32 rows x 64 uint32, 16B cp.async (512 uint4)
        {
            int idx = tid;                  // 512 loads over 256 threads x2
            #pragma unroll
            for (int i = 0; i < 2; i++) {
                int r = idx >> 4, q4 = (idx & 15) * 4;
                uint32_t gi = (uint32_t)(bl0 + r)*256 + ch*64 + q4;
                cp16(sb + F2_A + r*AST + q4*4, &g_Hhi[gi]);
                idx += 256;
            }
        }
        copyB_async(sb + F2_B, 10 + ch);
        CP_COMMIT();
        CP_WAIT0();
        __syncthreads();

        uint32_t aA = sb + F2_A + (uint32_t)(warpM*16 + (lane & 15))*AST
                    + (uint32_t)(lane >> 4)*16;
        uint32_t bB = sb + F2_B + (uint32_t)(lane & 15)*AST
                    + (uint32_t)(warpN*64 + (lane >> 4)*16);

        #pragma unroll
        for (int ks = 0; ks < 8; ks++) {
            uint32_t ah[4];
            ldm4(ah, aA + ks*32);
            #pragma unroll
            for (int ng = 0; ng < 2; ng++) {
                uint32_t bh[4];
                ldm4t(bh, bB + ks*16*AST + ng*32);
                mma_f16(acc[2*ng],   ah, bh[0], bh[1]);
                mma_f16(acc[2*ng+1], ah, bh[2], bh[3]);
            }
        }
        __syncthreads();
    }

    float* stats = (float*)(sm + F2_STAT);
    float s1[2], s2[2];
    #pragma unroll
    for (int h = 0; h < 2; h++) { s1[h] = 0.f; s2[h] = 0.f; }
    #pragma unroll
    for (int j = 0; j < 4; j++) {
        int C = cBase + j*8;
        float2 bv = *(const float2*)&bo[C];
        #pragma unroll
        for (int h = 0; h < 2; h++) {
            int R = warpM*16 + h*8 + qr;
            float2 hv = *(const float2*)&g_h1[(size_t)(bl0 + R)*NH + C];
            float v0 = acc[j][2*h+0] + bv.x + hv.x;
            float v1 = acc[j][2*h+1] + bv.y + hv.y;
            acc[j][2*h+0] = v0;
            acc[j][2*h+1] = v1;
            s1[h] += v0 + v1;
            s2[h] += v0*v0 + v1*v1;
        }
    }
    #pragma unroll
    for (int h = 0; h < 2; h++) {
        #pragma unroll
        for (int o = 1; o < 4; o <<= 1) {
            s1[h] += __shfl_xor_sync(0xffffffffu, s1[h], o);
            s2[h] += __shfl_xor_sync(0xffffffffu, s2[h], o);
        }
        if (qc == 0) {
            int R = warpM*16 + h*8 + qr;
            stats[(warpN*32 + R)*2 + 0] = s1[h];
            stats[(warpN*32 + R)*2 + 1] = s2[h];
        }
    }
    __syncthreads();
    #pragma unroll
    for (int h = 0; h < 2; h++) {
        int R = warpM*16 + h*8 + qr;
        float S1 = 0.f, S2 = 0.f;
        #pragma unroll
        for (int g = 0; g < 4; g++) {
            S1 += stats[(g*32 + R)*2 + 0];
            S2 += stats[(g*32 + R)*2 + 1];
        }
        float mu = S1 * (1.0f / NH);
        float var = S2 * (1.0f / NH) - mu * mu;
        float rinv = rsqrtf(var + 1e-5f);
        int token = bl0 + R;
        float mk = mask_V[token];
        #pragma unroll
        for (int j = 0; j < 4; j++) {
            int C = cBase + j*8;
            float2 gs = *(const float2*)&ln2s[C];
            float2 gb = *(const float2*)&ln2b[C];
            float2 o2;
            o2.x = ((acc[j][2*h+0] - mu) * rinv * gs.x + gb.x) * mk;
            o2.y = ((acc[j][2*h+1] - mu) * rinv * gs.y + gb.y) * mk;
            *(float2*)&g_hV2[(size_t)token*NH + C] = o2;
            *(float2*)&out_hV[(size_t)token*NH + C] = o2;
        }
    }
}

// ---------------------------------------------------------------------------

extern "C" void kernel_launch(void* const* d_in, const int* in_sizes, int n_in,
                              void* d_out, int out_size)
{
    const float* h_V         = (const float*)d_in[0];
    const float* h_E         = (const float*)d_in[1];
    const void*  E_idx       =               d_in[2];
    const float* mask_V      = (const float*)d_in[3];
    const float* mask_attend = (const float*)d_in[4];
    const float* W1  = (const float*)d_in[5],  *b1  = (const float*)d_in[6];
    const float* W2  = (const float*)d_in[7],  *b2  = (const float*)d_in[8];
    const float* W3  = (const float*)d_in[9],  *b3  = (const float*)d_in[10];
    const float* W11 = (const float*)d_in[11], *b11 = (const float*)d_in[12];
    const float* W12 = (const float*)d_in[13], *b12 = (const float*)d_in[14];
    const float* W13 = (const float*)d_in[15], *b13 = (const float*)d_in[16];
    const float* Wi  = (const float*)d_in[17], *bi  = (const float*)d_in[18];
    const float* Wo  = (const float*)d_in[19], *bo  = (const float*)d_in[20];
    const float* ln1s = (const float*)d_in[21], *ln1b = (const float*)d_in[22];
    const float* ln2s = (const float*)d_in[23], *ln2b = (const float*)d_in[24];
    const float* ln3s = (const float*)d_in[25], *ln3b = (const float*)d_in[26];
    float* out = (float*)d_out;

    float *pP1, *pG1, *pP2, *pG2, *pHV2;
    cudaGetSymbolAddress((void**)&pP1,  g_P1);
    cudaGetSymbolAddress((void**)&pG1,  g_G1);
    cudaGetSymbolAddress((void**)&pP2,  g_P2);
    cudaGetSymbolAddress((void**)&pG2,  g_G2);
    cudaGetSymbolAddress((void**)&pHV2, g_hV2);

    cudaFuncSetAttribute(tokenPG_kernel, cudaFuncAttributeMaxDynamicSharedMemorySize, SMEM64);
    cudaFuncSetAttribute(ffn1_kernel,  cudaFuncAttributeMaxDynamicSharedMemorySize, SMEM64);
    cudaFuncSetAttribute(ffn2_kernel,  cudaFuncAttributeMaxDynamicSharedMemorySize, SMEM_F2);
    cudaFuncSetAttribute(mlp3_kernel<0>, cudaFuncAttributeMaxDynamicSharedMemorySize, SMEM64);
    cudaFuncSetAttribute(mlp3_kernel<1>, cudaFuncAttributeMaxDynamicSharedMemorySize, SMEM64);

    detect_kernel<<<1, 256>>>((const int*)E_idx);
    convert_kernel<<<(NEDGE + 255) / 256, 256>>>(E_idx);

    wprep_kernel<<<(18*16384 + 255)/256, 256>>>(W1 + 128*NH, W2, W3,
                                                W11 + 128*NH, W12, W13, Wi, Wo,
                                                W1, W11);

    tokenPG_kernel<<<dim3(64, 2), 256, SMEM64>>>(h_V, b1, pP1, pG1, 14);

    mlp3_kernel<0><<<NEDGE/64, 256, SMEM64>>>(h_E, pP1, pG1, b2, b3,
                                              mask_attend, nullptr, nullptr,
                                              nullptr, 0);
    nodeLN_kernel<<<NTOK, 128>>>(h_V, ln1s, ln1b);

    ffn1_kernel<<<dim3(64, 4), 256, SMEM64>>>(bi);
    ffn2_kernel<<<128, 256, SMEM_F2>>>(bo, ln2s, ln2b, mask_V, out);

    tokenPG_kernel<<<dim3(64, 2), 256, SMEM64>>>(pHV2, b11, pP2, pG2, 16);

    mlp3_kernel<1><<<NEDGE/64, 256, SMEM64>>>(h_E, pP2, pG2, b12, b13,
                                              nullptr, ln3s, ln3b,
                                              out + (size_t)NTOK * NH, 3);
}

// round 11
// speedup vs baseline: 5.4556x; 1.0281x over previous
#include <cuda_runtime.h>
#include <cuda_fp16.h>
#include <math.h>
#include <stdint.h>

#define NB 2
#define NL 2048
#define NK 48
#define NH 128
#define NTOK (NB*NL)
#define NEDGE (NB*NL*NK)
#define FFH 512

__device__ int   g_is64;
__device__ int   g_idx32[NEDGE];
__device__ float g_h1 [NTOK*NH];
__device__ uint32_t g_Hhi[NTOK*FFH/2];
__device__ float g_P1 [NTOK*NH];
__device__ float g_G1 [NTOK*NH];
__device__ float g_P2 [NTOK*NH];
__device__ float g_G2 [NTOK*NH];
__device__ float g_partA[NTOK*NH];
__device__ float g_partB[NTOK*NH];
// 18 fp16 matrices [k][n] (128x128), rows padded to 272B -> 2176 uint4 each
// 0-2 node MLP, 3-5 edge MLP, 6-9 Wi col-tiles, 10-13 Wo k-chunks,
// 14 W1-P, 15 W1-G, 16 W11-P, 17 W11-G
__device__ uint4 g_Wb[18*2176];

#define AST 272
// 64-row tile layout (hi-only A)
#define M_A   0
#define M_B   17408
#define M_STAT 52224
#define SMEM64 54272
#define SMEMNF 54784

__device__ __forceinline__ float gelu_f(float x) {
    return 0.5f * x * (1.0f + erff(x * 0.7071067811865475f));
}

__device__ __forceinline__ uint32_t smem_u32(const void* p) {
    uint32_t a;
    asm("{ .reg .u64 t; cvta.to.shared.u64 t, %1; cvt.u32.u64 %0, t; }"
        : "=r"(a) : "l"(p));
    return a;
}

__device__ __forceinline__ uint32_t pack_f16(float v0, float v1) {
    __half2 h = __floats2half2_rn(v0, v1);
    return *(uint32_t*)&h;
}

__device__ __forceinline__ void cp16(uint32_t dst, const void* src) {
    asm volatile("cp.async.cg.shared.global [%0], [%1], 16;"
        :: "r"(dst), "l"(src));
}
#define CP_COMMIT() asm volatile("cp.async.commit_group;" ::: "memory")
#define CP_WAIT0()  asm volatile("cp.async.wait_group 0;" ::: "memory")
#define PREF_L2(p)  asm volatile("prefetch.global.L2 [%0];" :: "l"(p))

__device__ __forceinline__ void ldm4(uint32_t r[4], uint32_t a) {
    asm volatile("ldmatrix.sync.aligned.m8n8.x4.shared.b16 {%0,%1,%2,%3}, [%4];"
        : "=r"(r[0]), "=r"(r[1]), "=r"(r[2]), "=r"(r[3]) : "r"(a));
}
__device__ __forceinline__ void ldm4t(uint32_t r[4], uint32_t a) {
    asm volatile("ldmatrix.sync.aligned.m8n8.x4.trans.shared.b16 {%0,%1,%2,%3}, [%4];"
        : "=r"(r[0]), "=r"(r[1]), "=r"(r[2]), "=r"(r[3]) : "r"(a));
}
__device__ __forceinline__ void mma_f16(float c[4], const uint32_t a[4],
                                        uint32_t b0, uint32_t b1) {
    asm volatile(
        "mma.sync.aligned.m16n8k16.row.col.f32.f16.f16.f32 "
        "{%0,%1,%2,%3}, {%4,%5,%6,%7}, {%8,%9}, {%0,%1,%2,%3};"
        : "+f"(c[0]), "+f"(c[1]), "+f"(c[2]), "+f"(c[3])
        : "r"(a[0]), "r"(a[1]), "r"(a[2]), "r"(a[3]), "r"(b0), "r"(b1));
}

// ---------------------------------------------------------------------------
__global__ void detect_kernel(const int* __restrict__ w) {
    int nz = 0;
    for (int i = 2 * (int)threadIdx.x + 1; i < 1024; i += 512) nz |= (w[i] != 0);
    unsigned any = __ballot_sync(0xffffffffu, nz);
    __shared__ int s[8];
    if ((threadIdx.x & 31) == 0) s[threadIdx.x >> 5] = (any != 0);
    __syncthreads();
    if (threadIdx.x == 0) {
        int a = 0;
        #pragma unroll
        for (int i = 0; i < 8; i++) a |= s[i];
        g_is64 = (a == 0);
    }
}

__global__ void convert_kernel(const void* __restrict__ e) {
    int i = blockIdx.x * blockDim.x + threadIdx.x;
    if (i >= NEDGE) return;
    if (g_is64) g_idx32[i] = (int)((const long long*)e)[i];
    else        g_idx32[i] = ((const int*)e)[i];
}

// ---------------------------------------------------------------------------
// wprep: all weights -> fp16 tiles [k][n], rows padded to 272B.
// ---------------------------------------------------------------------------
__global__ void wprep_kernel(const float* W0, const float* W1, const float* W2,
                             const float* W3, const float* W4, const float* W5,
                             const float* Wi, const float* Wo,
                             const float* W1full, const float* W11full) {
    int gid = blockIdx.x * 256 + threadIdx.x;
    if (gid >= 18 * 16384) return;
    int m = gid >> 14, rem = gid & 16383;
    int k = rem >> 7, n = rem & 127;
    float v;
    if (m < 6) {
        const float* W = (m == 0) ? W0 : (m == 1) ? W1 : (m == 2) ? W2
                       : (m == 3) ? W3 : (m == 4) ? W4 : W5;
        v = W[k * 128 + n];
    } else if (m < 10) {
        v = Wi[k * FFH + (m - 6) * 128 + n];
    } else if (m < 14) {
        v = Wo[((m - 10) * 128 + k) * 128 + n];
    } else if (m == 14) {
        v = W1full[k * 128 + n];
    } else if (m == 15) {
        v = W1full[(256 + k) * 128 + n];
    } else if (m == 16) {
        v = W11full[k * 128 + n];
    } else {
        v = W11full[(256 + k) * 128 + n];
    }
    char* basep = (char*)g_Wb + (size_t)m * 34816;
    *(__half*)(basep + (uint32_t)k * 272u + (uint32_t)n * 2u) = __float2half_rn(v);
}

// ---------------------------------------------------------------------------
// Shared mma machinery: 64 rows x 128 cols, K=128, single-pass fp16.
// 8 warps = 2(M) x 4(N).
// ---------------------------------------------------------------------------
__device__ __forceinline__ void copyB_async(uint32_t dst, int mat) {
    const uint4* src = &g_Wb[(size_t)mat * 2176];
    #pragma unroll
    for (int i = 0; i < 9; i++) {
        int idx = threadIdx.x + 256*i;
        if (idx < 2176) cp16(dst + idx*16, src + idx);
    }
}

__device__ __forceinline__ void mma_layer64(uint32_t sb, int warpM, int warpN,
                                            int lane, float (&acc)[2][4][4]) {
    #pragma unroll
    for (int m = 0; m < 2; m++)
        #pragma unroll
        for (int j = 0; j < 4; j++)
            #pragma unroll
            for (int c = 0; c < 4; c++) acc[m][j][c] = 0.0f;

    uint32_t aA = sb + M_A + (uint32_t)(warpM*32 + (lane & 15))*AST
                + (uint32_t)(lane >> 4)*16;
    uint32_t bB = sb + M_B + (uint32_t)(lane & 15)*AST
                + (uint32_t)(warpN*4 + (lane >> 4))*16;

    #pragma unroll
    for (int ks = 0; ks < 8; ks++) {
        uint32_t ah0[4], ah1[4];
        ldm4(ah0, aA + ks*32);
        ldm4(ah1, aA + ks*32 + 16*AST);
        #pragma unroll
        for (int ng = 0; ng < 2; ng++) {
            uint32_t bh[4];
            ldm4t(bh, bB + ks*16*AST + ng*32);
            mma_f16(acc[0][2*ng],   ah0, bh[0], bh[1]);
            mma_f16(acc[1][2*ng],   ah1, bh[0], bh[1]);
            mma_f16(acc[0][2*ng+1], ah0, bh[2], bh[3]);
            mma_f16(acc[1][2*ng+1], ah1, bh[2], bh[3]);
        }
    }
}

// load 64 fp32 rows -> fp16
__device__ __forceinline__ void loadA64(char* sm, const float* src, int tid) {
    for (int idx = tid; idx < 64*64; idx += 256) {
        int r = idx >> 6, cp = idx & 63;
        float2 x = *(const float2*)&src[(size_t)r*NH + cp*2];
        *(uint32_t*)(sm + M_A + r*AST + cp*4) = pack_f16(x.x, x.y);
    }
}

// ---------------------------------------------------------------------------
// tokenPG (mma): C[64x128] = A @ W (+bias). y=0 -> P (bias), y=1 -> G.
// ---------------------------------------------------------------------------
__global__ void __launch_bounds__(256, 3) tokenPG_kernel(
    const float* __restrict__ A, const float* __restrict__ bias,
    float* __restrict__ P, float* __restrict__ G, int matBase)
{
    extern __shared__ char sm[];
    uint32_t sb = smem_u32(sm);
    int tid = threadIdx.x;
    int wid = tid >> 5, lane = tid & 31;
    int warpM = wid & 1, warpN = wid >> 1;
    int qr = lane >> 2, qc = lane & 3;
    int bl0 = blockIdx.x * 64;
    int cBase = warpN*32 + 2*qc;
    int isP = (blockIdx.y == 0);
    float* Out = isP ? P : G;

    copyB_async(sb + M_B, matBase + blockIdx.y);
    CP_COMMIT();
    loadA64(sm, A + (size_t)bl0*NH, tid);
    CP_WAIT0();
    __syncthreads();

    float acc[2][4][4];
    mma_layer64(sb, warpM, warpN, lane, acc);

    #pragma unroll
    for (int mf = 0; mf < 2; mf++)
        #pragma unroll
        for (int j = 0; j < 4; j++) {
            int C = cBase + j*8;
            float2 bv = make_float2(0.f, 0.f);
            if (isP) bv = *(const float2*)&bias[C];
            #pragma unroll
            for (int h = 0; h < 2; h++) {
                int R = warpM*32 + mf*16 + h*8 + qr;
                float2 o2;
                o2.x = acc[mf][j][2*h+0] + bv.x;
                o2.y = acc[mf][j][2*h+1] + bv.y;
                *(float2*)&Out[(size_t)(bl0 + R)*NH + C] = o2;
            }
        }
}

// ---------------------------------------------------------------------------
// mlp3: 64 edge rows per CTA. MODE 0 = node (2 layers + masked Z row-sum),
// MODE 1 = edge (3 layers + residual + LN3 + out).
// ---------------------------------------------------------------------------
template<int MODE>
__global__ void __launch_bounds__(256, 3) mlp3_kernel(
    const float* __restrict__ hE,
    const float* __restrict__ P, const float* __restrict__ G,
    const float* __restrict__ bias2, const float* __restrict__ bias3,
    const float* __restrict__ mask_attend,
    const float* __restrict__ ln3s, const float* __restrict__ ln3b,
    float* __restrict__ out_hE, int matBase)
{
    extern __shared__ char sm[];
    uint32_t sb = smem_u32(sm);

    int tid = threadIdx.x;
    int wid = tid >> 5, lane = tid & 31;
    int warpM = wid & 1, warpN = wid >> 1;
    int qr = lane >> 2, qc = lane & 3;
    int e0 = blockIdx.x * 64;
    int cBase = warpN*32 + 2*qc;

    int Row[2][2];
    #pragma unroll
    for (int mf = 0; mf < 2; mf++)
        #pragma unroll
        for (int h = 0; h < 2; h++)
            Row[mf][h] = warpM*32 + mf*16 + h*8 + qr;

    copyB_async(sb + M_B, matBase + 0);
    CP_COMMIT();
    loadA64(sm, hE + (size_t)e0*NH, tid);
    // L2 prefetch of P/G gather rows for epilogue 1
    {
        int r = tid >> 2, ln = tid & 3;
        int e = e0 + r;
        int tok = e / 48;
        int batch = (e >= NL*NK) ? 1 : 0;
        const float* pp = P + (size_t)tok*NH + ln*32;
        const float* gg = G + (size_t)(batch*NL + g_idx32[e])*NH + ln*32;
        PREF_L2(pp);
        PREF_L2(gg);
    }
    CP_WAIT0();
    __syncthreads();

    float acc[2][4][4];

    // ---- layer 1 ----
    mma_layer64(sb, warpM, warpN, lane, acc);
    __syncthreads();
    copyB_async(sb + M_B, matBase + 1);
    CP_COMMIT();
    {
        const float* Pr[2][2];
        const float* Gr[2][2];
        #pragma unroll
        for (int mf = 0; mf < 2; mf++)
            #pragma unroll
            for (int h = 0; h < 2; h++) {
                int e = e0 + Row[mf][h];
                int tok = e / 48;
                int batch = (e >= NL*NK) ? 1 : 0;
                Pr[mf][h] = P + (size_t)tok * NH;
                Gr[mf][h] = G + (size_t)(batch*NL + g_idx32[e]) * NH;
            }
        #pragma unroll
        for (int mf = 0; mf < 2; mf++)
            #pragma unroll
            for (int j = 0; j < 4; j++) {
                int C = cBase + j*8;
                #pragma unroll
                for (int h = 0; h < 2; h++) {
                    float2 pv = *(const float2*)&Pr[mf][h][C];
                    float2 gv = *(const float2*)&Gr[mf][h][C];
                    float v0 = gelu_f(acc[mf][j][2*h+0] + pv.x + gv.x);
                    float v1 = gelu_f(acc[mf][j][2*h+1] + pv.y + gv.y);
                    int R = Row[mf][h];
                    *(uint32_t*)(sm + M_A + R*AST + C*2) = pack_f16(v0, v1);
                }
            }
    }
    CP_WAIT0();
    __syncthreads();

    // ---- layer 2 ----
    mma_layer64(sb, warpM, warpN, lane, acc);
    __syncthreads();

    if (MODE == 0) {
        // Z = gelu(acc + b2); stage Z*mask (fp32); per-token row-sum -> partials
        float* stage = (float*)(sm + M_A);  // [64][136] f32 (aliases A+B)
        #pragma unroll
        for (int mf = 0; mf < 2; mf++)
            #pragma unroll
            for (int h = 0; h < 2; h++) {
                int R = Row[mf][h];
                float mk = mask_attend[e0 + R];
                #pragma unroll
                for (int j = 0; j < 4; j++) {
                    int C = cBase + j*8;
                    float2 bv = *(const float2*)&bias2[C];
                    float2 o2;
                    o2.x = gelu_f(acc[mf][j][2*h+0] + bv.x) * mk;
                    o2.y = gelu_f(acc[mf][j][2*h+1] + bv.y) * mk;
                    *(float2*)&stage[R*136 + C] = o2;
                }
            }
        __syncthreads();
        int t0 = e0 / 48;
        int tend = (e0 + 63) / 48;
        for (int t = t0 + (tid >> 7); t <= tend; t += 2) {
            int col = tid & 127;
            int rs = max(t*48 - e0, 0), re = min(t*48 + 47 - e0, 63);
            float sacc = 0.0f;
            for (int rr = rs; rr <= re; rr++) sacc += stage[rr*136 + col];
            if (t*48 >= e0) g_partA[(size_t)t*NH + col] = sacc;
            else            g_partB[(size_t)t*NH + col] = sacc;
        }
        return;
    }

    // ---- edge path: layer-2 epilogue, layer 3, LN3 ----
    copyB_async(sb + M_B, matBase + 2);
    CP_COMMIT();
    #pragma unroll
    for (int mf = 0; mf < 2; mf++)
        #pragma unroll
        for (int j = 0; j < 4; j++) {
            int C = cBase + j*8;
            float2 bv = *(const float2*)&bias2[C];
            #pragma unroll
            for (int h = 0; h < 2; h++) {
                float v0 = gelu_f(acc[mf][j][2*h+0] + bv.x);
                float v1 = gelu_f(acc[mf][j][2*h+1] + bv.y);
                int R = Row[mf][h];
                *(uint32_t*)(sm + M_A + R*AST + C*2) = pack_f16(v0, v1);
            }
        }
    CP_WAIT0();
    __syncthreads();

    mma_layer64(sb, warpM, warpN, lane, acc);
    __syncthreads();

    float* stats = (float*)(sm + M_STAT);   // [4 warpN][64 rows][2]
    float s1[2][2], s2[2][2];
    #pragma unroll
    for (int mf = 0; mf < 2; mf++)
        #pragma unroll
        for (int h = 0; h < 2; h++) { s1[mf][h] = 0.f; s2[mf][h] = 0.f; }
    #pragma unroll
    for (int mf = 0; mf < 2; mf++)
        #pragma unroll
        for (int j = 0; j < 4; j++) {
            int C = cBase + j*8;
            float2 bv = *(const float2*)&bias3[C];
            #pragma unroll
            for (int h = 0; h < 2; h++) {
                int R = Row[mf][h];
                float2 he = *(const float2*)&hE[(size_t)(e0 + R)*NH + C];
                float v0 = acc[mf][j][2*h+0] + bv.x + he.x;
                float v1 = acc[mf][j][2*h+1] + bv.y + he.y;
                acc[mf][j][2*h+0] = v0;
                acc[mf][j][2*h+1] = v1;
                s1[mf][h] += v0 + v1;
                s2[mf][h] += v0*v0 + v1*v1;
            }
        }
    #pragma unroll
    for (int mf = 0; mf < 2; mf++)
        #pragma unroll
        for (int h = 0; h < 2; h++) {
            #pragma unroll
            for (int o = 1; o < 4; o <<= 1) {
                s1[mf][h] += __shfl_xor_sync(0xffffffffu, s1[mf][h], o);
                s2[mf][h] += __shfl_xor_sync(0xffffffffu, s2[mf][h], o);
            }
            if (qc == 0) {
                stats[(warpN*64 + Row[mf][h])*2 + 0] = s1[mf][h];
                stats[(warpN*64 + Row[mf][h])*2 + 1] = s2[mf][h];
            }
        }
    __syncthreads();
    #pragma unroll
    for (int mf = 0; mf < 2; mf++)
        #pragma unroll
        for (int h = 0; h < 2; h++) {
            int R = Row[mf][h];
            float S1 = 0.f, S2 = 0.f;
            #pragma unroll
            for (int g = 0; g < 4; g++) {
                S1 += stats[(g*64 + R)*2 + 0];
                S2 += stats[(g*64 + R)*2 + 1];
            }
            float mu = S1 * (1.0f / NH);
            float var = S2 * (1.0f / NH) - mu * mu;
            float rinv = rsqrtf(var + 1e-5f);
            #pragma unroll
            for (int j = 0; j < 4; j++) {
                int C = cBase + j*8;
                float2 gs = *(const float2*)&ln3s[C];
                float2 gb = *(const float2*)&ln3b[C];
                float2 o2;
                o2.x = (acc[mf][j][2*h+0] - mu) * rinv * gs.x + gb.x;
                o2.y = (acc[mf][j][2*h+1] - mu) * rinv * gs.y + gb.y;
                *(float2*)&out_hE[(size_t)(e0 + R)*NH + C] = o2;
            }
        }
}

// ---------------------------------------------------------------------------
// nodeFin: dh = S@W3 + (Σmask)*b3 ; h1 = LN1(hV + dh/30). 64 tokens/CTA.
// ---------------------------------------------------------------------------
__global__ void __launch_bounds__(256) nodeFin_kernel(
    const float* __restrict__ hV, const float* __restrict__ b3,
    const float* __restrict__ mask_attend,
    const float* __restrict__ ln1s, const float* __restrict__ ln1b)
{
    extern __shared__ char sm[];
    uint32_t sb = smem_u32(sm);
    int tid = threadIdx.x;
    int wid = tid >> 5, lane = tid & 31;
    int warpM = wid & 1, warpN = wid >> 1;
    int qr = lane >> 2, qc = lane & 3;
    int bl0 = blockIdx.x * 64;
    int cBase = warpN*32 + 2*qc;

    copyB_async(sb + M_B, 2);   // W3
    CP_COMMIT();
    // load S = partA (+ partB if token spans tiles), quantize fp16
    for (int idx = tid; idx < 64*64; idx += 256) {
        int r = idx >> 6, cp = idx & 63;
        int t = bl0 + r;
        float2 x = *(const float2*)&g_partA[(size_t)t*NH + cp*2];
        int s0 = t * 48;
        if (s0 / 64 != (s0 + 47) / 64) {
            float2 y = *(const float2*)&g_partB[(size_t)t*NH + cp*2];
            x.x += y.x; x.y += y.y;
        }
        *(uint32_t*)(sm + M_A + r*AST + cp*4) = pack_f16(x.x, x.y);
    }
    CP_WAIT0();
    __syncthreads();

    float acc[2][4][4];
    mma_layer64(sb, warpM, warpN, lane, acc);

    float* stats = (float*)(sm + M_STAT);
    float* msum  = (float*)(sm + M_STAT + 2048);
    if (tid < 64) {
        int t = bl0 + tid;
        float s = 0.0f;
        #pragma unroll 4
        for (int k = 0; k < NK; k += 4) {
            float4 m4 = *(const float4*)&mask_attend[t*NK + k];
            s += m4.x + m4.y + m4.z + m4.w;
        }
        msum[tid] = s;
    }
    __syncthreads();

    int Row[2][2];
    #pragma unroll
    for (int mf = 0; mf < 2; mf++)
        #pragma unroll
        for (int h = 0; h < 2; h++)
            Row[mf][h] = warpM*32 + mf*16 + h*8 + qr;

    float s1[2][2], s2[2][2];
    #pragma unroll
    for (int mf = 0; mf < 2; mf++)
        #pragma unroll
        for (int h = 0; h < 2; h++) { s1[mf][h] = 0.f; s2[mf][h] = 0.f; }

    #pragma unroll
    for (int mf = 0; mf < 2; mf++)
        #pragma unroll
        for (int j = 0; j < 4; j++) {
            int C = cBase + j*8;
            float2 bv = *(const float2*)&b3[C];
            #pragma unroll
            for (int h = 0; h < 2; h++) {
                int R = Row[mf][h];
                int t = bl0 + R;
                float ms = msum[R];
                float2 hv = *(const float2*)&hV[(size_t)t*NH + C];
                float v0 = hv.x + (acc[mf][j][2*h+0] + ms*bv.x) * (1.0f/30.0f);
                float v1 = hv.y + (acc[mf][j][2*h+1] + ms*bv.y) * (1.0f/30.0f);
                acc[mf][j][2*h+0] = v0;
                acc[mf][j][2*h+1] = v1;
                s1[mf][h] += v0 + v1;
                s2[mf][h] += v0*v0 + v1*v1;
            }
        }
    #pragma unroll
    for (int mf = 0; mf < 2; mf++)
        #pragma unroll
        for (int h = 0; h < 2; h++) {
            #pragma unroll
            for (int o = 1; o < 4; o <<= 1) {
                s1[mf][h] += __shfl_xor_sync(0xffffffffu, s1[mf][h], o);
                s2[mf][h] += __shfl_xor_sync(0xffffffffu, s2[mf][h], o);
            }
            if (qc == 0) {
                stats[(warpN*64 + Row[mf][h])*2 + 0] = s1[mf][h];
                stats[(warpN*64 + Row[mf][h])*2 + 1] = s2[mf][h];
            }
        }
    __syncthreads();
    #pragma unroll
    for (int mf = 0; mf < 2; mf++)
        #pragma unroll
        for (int h = 0; h < 2; h++) {
            int R = Row[mf][h];
            float S1 = 0.f, S2 = 0.f;
            #pragma unroll
            for (int g = 0; g < 4; g++) {
                S1 += stats[(g*64 + R)*2 + 0];
                S2 += stats[(g*64 + R)*2 + 1];
            }
            float mu = S1 * (1.0f / NH);
            float var = S2 * (1.0f / NH) - mu * mu;
            float rinv = rsqrtf(var + 1e-5f);
            #pragma unroll
            for (int j = 0; j < 4; j++) {
                int C = cBase + j*8;
                float2 gs = *(const float2*)&ln1s[C];
                float2 gb = *(const float2*)&ln1b[C];
                float2 o2;
                o2.x = (acc[mf][j][2*h+0] - mu) * rinv * gs.x + gb.x;
                o2.y = (acc[mf][j][2*h+1] - mu) * rinv * gs.y + gb.y;
                *(float2*)&g_h1[(size_t)(bl0 + R)*NH + C] = o2;
            }
        }
}

// ---------------------------------------------------------------------------
// ffn1 (mma): H tile [64tok x 128col] = gelu(h1 @ Wi + bi), store fp16.
// grid (64, 4).
// ---------------------------------------------------------------------------
__global__ void __launch_bounds__(256, 3) ffn1_kernel(const float* __restrict__ bi)
{
    extern __shared__ char sm[];
    uint32_t sb = smem_u32(sm);
    int tid = threadIdx.x;
    int wid = tid >> 5, lane = tid & 31;
    int warpM = wid & 1, warpN = wid >> 1;
    int qr = lane >> 2, qc = lane & 3;
    int bl0 = blockIdx.x * 64;
    int nb  = blockIdx.y * 128;
    int cBase = warpN*32 + 2*qc;

    copyB_async(sb + M_B, 6 + blockIdx.y);
    CP_COMMIT();
    loadA64(sm, g_h1 + (size_t)bl0*NH, tid);
    CP_WAIT0();
    __syncthreads();

    float acc[2][4][4];
    mma_layer64(sb, warpM, warpN, lane, acc);

    #pragma unroll
    for (int mf = 0; mf < 2; mf++)
        #pragma unroll
        for (int j = 0; j < 4; j++) {
            int C = cBase + j*8;
            float2 bv = *(const float2*)&bi[nb + C];
            #pragma unroll
            for (int h = 0; h < 2; h++) {
                int R = warpM*32 + mf*16 + h*8 + qr;
                float v0 = gelu_f(acc[mf][j][2*h+0] + bv.x);
                float v1 = gelu_f(acc[mf][j][2*h+1] + bv.y);
                uint32_t gi = ((uint32_t)(bl0 + R)*FFH + nb + C) >> 1;
                g_Hhi[gi] = pack_f16(v0, v1);
            }
        }
}

// ---------------------------------------------------------------------------
// ffn2 (mma): hV2 = LN2(h1 + H @ Wo + bo) * mask_V, then fused
// P2 = hV2@W11P + b11, G2 = hV2@W11G. 32 tok/CTA, grid 128.
// ---------------------------------------------------------------------------
#define F2_A   0
#define F2_B   8704
#define F2_STAT 43520
#define SMEM_F2 45568

__device__ __forceinline__ void mma_32(uint32_t sb, int warpM, int warpN,
                                       int lane, float (&acc)[4][4]) {
    #pragma unroll
    for (int j = 0; j < 4; j++)
        #pragma unroll
        for (int c = 0; c < 4; c++) acc[j][c] = 0.0f;
    uint32_t aA = sb + F2_A + (uint32_t)(warpM*16 + (lane & 15))*AST
                + (uint32_t)(lane >> 4)*16;
    uint32_t bB = sb + F2_B + (uint32_t)(lane & 15)*AST
                + (uint32_t)(warpN*4 + (lane >> 4))*16;
    #pragma unroll
    for (int ks = 0; ks < 8; ks++) {
        uint32_t ah[4];
        ldm4(ah, aA + ks*32);
        #pragma unroll
        for (int ng = 0; ng < 2; ng++) {
            uint32_t bh[4];
            ldm4t(bh, bB + ks*16*AST + ng*32);
            mma_f16(acc[2*ng],   ah, bh[0], bh[1]);
            mma_f16(acc[2*ng+1], ah, bh[2], bh[3]);
        }
    }
}

__global__ void __launch_bounds__(256) ffn2_kernel(
    const float* __restrict__ bo,
    const float* __restrict__ ln2s, const float* __restrict__ ln2b,
    const float* __restrict__ mask_V, const float* __restrict__ b11,
    float* __restrict__ out_hV, float* __restrict__ P2, float* __restrict__ G2)
{
    extern __shared__ char sm[];
    uint32_t sb = smem_u32(sm);
    int tid = threadIdx.x;
    int wid = tid >> 5, lane = tid & 31;
    int warpM = wid & 1, warpN = wid >> 1;   // 2 x 4
    int qr = lane >> 2, qc = lane & 3;
    int bl0 = blockIdx.x * 32;
    int cBase = warpN*32 + 2*qc;

    float acc[4][4];
    #pragma unroll
    for (int j = 0; j < 4; j++)
        #pragma unroll
        for (int c = 0; c < 4; c++) acc[j][c] = 0.0f;

    for (int ch = 0; ch < 4; ch++) {
        {
            int idx = tid;
            #pragma unroll
            for (int i = 0; i < 2; i++) {
                int r = idx >> 4, q4 = (idx & 15) * 4;
                uint32_t gi = (uint32_t)(bl0 + r)*256 + ch*64 + q4;
                cp16(sb + F2_A + r*AST + q4*4, &g_Hhi[gi]);
                idx += 256;
            }
        }
        copyB_async(sb + F2_B, 10 + ch);
        CP_COMMIT();
        CP_WAIT0();
        __syncthreads();

        uint32_t aA = sb + F2_A + (uint32_t)(warpM*16 + (lane & 15))*AST
                    + (uint32_t)(lane >> 4)*16;
        uint32_t bB = sb + F2_B + (uint32_t)(lane & 15)*AST
                    + (uint32_t)(warpN*64 + (lane >> 4)*16);

        #pragma unroll
        for (int ks = 0; ks < 8; ks++) {
            uint32_t ah[4];
            ldm4(ah, aA + ks*32);
            #pragma unroll
            for (int ng = 0; ng < 2; ng++) {
                uint32_t bh[4];
                ldm4t(bh, bB + ks*16*AST + ng*32);
                mma_f16(acc[2*ng],   ah, bh[0], bh[1]);
                mma_f16(acc[2*ng+1], ah, bh[2], bh[3]);
            }
        }
        __syncthreads();
    }

    float* stats = (float*)(sm + F2_STAT);
    float s1[2], s2[2];
    #pragma unroll
    for (int h = 0; h < 2; h++) { s1[h] = 0.f; s2[h] = 0.f; }
    #pragma unroll
    for (int j = 0; j < 4; j++) {
        int C = cBase + j*8;
        float2 bv = *(const float2*)&bo[C];
        #pragma unroll
        for (int h = 0; h < 2; h++) {
            int R = warpM*16 + h*8 + qr;
            float2 hv = *(const float2*)&g_h1[(size_t)(bl0 + R)*NH + C];
            float v0 = acc[j][2*h+0] + bv.x + hv.x;
            float v1 = acc[j][2*h+1] + bv.y + hv.y;
            acc[j][2*h+0] = v0;
            acc[j][2*h+1] = v1;
            s1[h] += v0 + v1;
            s2[h] += v0*v0 + v1*v1;
        }
    }
    #pragma unroll
    for (int h = 0; h < 2; h++) {
        #pragma unroll
        for (int o = 1; o < 4; o <<= 1) {
            s1[h] += __shfl_xor_sync(0xffffffffu, s1[h], o);
            s2[h] += __shfl_xor_sync(0xffffffffu, s2[h], o);
        }
        if (qc == 0) {
            int R = warpM*16 + h*8 + qr;
            stats[(warpN*32 + R)*2 + 0] = s1[h];
            stats[(warpN*32 + R)*2 + 1] = s2[h];
        }
    }
    __syncthreads();
    #pragma unroll
    for (int h = 0; h < 2; h++) {
        int R = warpM*16 + h*8 + qr;
        float S1 = 0.f, S2 = 0.f;
        #pragma unroll
        for (int g = 0; g < 4; g++) {
            S1 += stats[(g*32 + R)*2 + 0];
            S2 += stats[(g*32 + R)*2 + 1];
        }
        float mu = S1 * (1.0f / NH);
        float var = S2 * (1.0f / NH) - mu * mu;
        float rinv = rsqrtf(var + 1e-5f);
        int token = bl0 + R;
        float mk = mask_V[token];
        #pragma unroll
        for (int j = 0; j < 4; j++) {
            int C = cBase + j*8;
            float2 gs = *(const float2*)&ln2s[C];
            float2 gb = *(const float2*)&ln2b[C];
            float2 o2;
            o2.x = ((acc[j][2*h+0] - mu) * rinv * gs.x + gb.x) * mk;
            o2.y = ((acc[j][2*h+1] - mu) * rinv * gs.y + gb.y) * mk;
            *(float2*)&out_hV[(size_t)token*NH + C] = o2;
            // stash hV2 fp16 into F2_A for PG GEMMs
            *(uint32_t*)(sm + F2_A + R*AST + C*2) = pack_f16(o2.x, o2.y);
        }
    }
    __syncthreads();

    // fused P2 = hV2 @ W11P + b11
    copyB_async(sb + F2_B, 16);
    CP_COMMIT();
    CP_WAIT0();
    __syncthreads();
    float acc2[4][4];
    mma_32(sb, warpM, warpN, lane, acc2);
    #pragma unroll
    for (int j = 0; j < 4; j++) {
        int C = cBase + j*8;
        float2 bv = *(const float2*)&b11[C];
        #pragma unroll
        for (int h = 0; h < 2; h++) {
            int R = warpM*16 + h*8 + qr;
            float2 o2;
            o2.x = acc2[j][2*h+0] + bv.x;
            o2.y = acc2[j][2*h+1] + bv.y;
            *(float2*)&P2[(size_t)(bl0 + R)*NH + C] = o2;
        }
    }
    __syncthreads();

    // fused G2 = hV2 @ W11G
    copyB_async(sb + F2_B, 17);
    CP_COMMIT();
    CP_WAIT0();
    __syncthreads();
    mma_32(sb, warpM, warpN, lane, acc2);
    #pragma unroll
    for (int j = 0; j < 4; j++) {
        int C = cBase + j*8;
        #pragma unroll
        for (int h = 0; h < 2; h++) {
            int R = warpM*16 + h*8 + qr;
            float2 o2;
            o2.x = acc2[j][2*h+0];
            o2.y = acc2[j][2*h+1];
            *(float2*)&G2[(size_t)(bl0 + R)*NH + C] = o2;
        }
    }
}

// ---------------------------------------------------------------------------

extern "C" void kernel_launch(void* const* d_in, const int* in_sizes, int n_in,
                              void* d_out, int out_size)
{
    const float* h_V         = (const float*)d_in[0];
    const float* h_E         = (const float*)d_in[1];
    const void*  E_idx       =               d_in[2];
    const float* mask_V      = (const float*)d_in[3];
    const float* mask_attend = (const float*)d_in[4];
    const float* W1  = (const float*)d_in[5],  *b1  = (const float*)d_in[6];
    const float* W2  = (const float*)d_in[7],  *b2  = (const float*)d_in[8];
    const float* W3  = (const float*)d_in[9],  *b3  = (const float*)d_in[10];
    const float* W11 = (const float*)d_in[11], *b11 = (const float*)d_in[12];
    const float* W12 = (const float*)d_in[13], *b12 = (const float*)d_in[14];
    const float* W13 = (const float*)d_in[15], *b13 = (const float*)d_in[16];
    const float* Wi  = (const float*)d_in[17], *bi  = (const float*)d_in[18];
    const float* Wo  = (const float*)d_in[19], *bo  = (const float*)d_in[20];
    const float* ln1s = (const float*)d_in[21], *ln1b = (const float*)d_in[22];
    const float* ln2s = (const float*)d_in[23], *ln2b = (const float*)d_in[24];
    const float* ln3s = (const float*)d_in[25], *ln3b = (const float*)d_in[26];
    float* out = (float*)d_out;

    float *pP1, *pG1, *pP2, *pG2;
    cudaGetSymbolAddress((void**)&pP1,  g_P1);
    cudaGetSymbolAddress((void**)&pG1,  g_G1);
    cudaGetSymbolAddress((void**)&pP2,  g_P2);
    cudaGetSymbolAddress((void**)&pG2,  g_G2);

    cudaFuncSetAttribute(tokenPG_kernel, cudaFuncAttributeMaxDynamicSharedMemorySize, SMEM64);
    cudaFuncSetAttribute(ffn1_kernel,  cudaFuncAttributeMaxDynamicSharedMemorySize, SMEM64);
    cudaFuncSetAttribute(ffn2_kernel,  cudaFuncAttributeMaxDynamicSharedMemorySize, SMEM_F2);
    cudaFuncSetAttribute(nodeFin_kernel, cudaFuncAttributeMaxDynamicSharedMemorySize, SMEMNF);
    cudaFuncSetAttribute(mlp3_kernel<0>, cudaFuncAttributeMaxDynamicSharedMemorySize, SMEM64);
    cudaFuncSetAttribute(mlp3_kernel<1>, cudaFuncAttributeMaxDynamicSharedMemorySize, SMEM64);

    detect_kernel<<<1, 256>>>((const int*)E_idx);
    convert_kernel<<<(NEDGE + 255) / 256, 256>>>(E_idx);

    wprep_kernel<<<(18*16384 + 255)/256, 256>>>(W1 + 128*NH, W2, W3,
                                                W11 + 128*NH, W12, W13, Wi, Wo,
                                                W1, W11);

    tokenPG_kernel<<<dim3(64, 2), 256, SMEM64>>>(h_V, b1, pP1, pG1, 14);

    mlp3_kernel<0><<<NEDGE/64, 256, SMEM64>>>(h_E, pP1, pG1, b2, nullptr,
                                              mask_attend, nullptr, nullptr,
                                              nullptr, 0);
    nodeFin_kernel<<<64, 256, SMEMNF>>>(h_V, b3, mask_attend, ln1s, ln1b);

    ffn1_kernel<<<dim3(64, 4), 256, SMEM64>>>(bi);
    ffn2_kernel<<<128, 256, SMEM_F2>>>(bo, ln2s, ln2b, mask_V, b11,
                                       out, pP2, pG2);

    mlp3_kernel<1><<<NEDGE/64, 256, SMEM64>>>(h_E, pP2, pG2, b12, b13,
                                              nullptr, ln3s, ln3b,
                                              out + (size_t)NTOK * NH, 3);
}

// round 12
// speedup vs baseline: 5.9310x; 1.0871x over previous
#include <cuda_runtime.h>
#include <cuda_fp16.h>
#include <math.h>
#include <stdint.h>

#define NB 2
#define NL 2048
#define NK 48
#define NH 128
#define NTOK (NB*NL)
#define NEDGE (NB*NL*NK)
#define FFH 512

__device__ int   g_is64;
__device__ int   g_idx32[NEDGE];
__device__ float g_h1 [NTOK*NH];
__device__ uint32_t g_h1f16[NTOK*NH/2];
__device__ uint32_t g_hEf16[NEDGE*NH/2];
__device__ uint32_t g_Hhi[NTOK*FFH/2];
__device__ float g_P1 [NTOK*NH];
__device__ float g_G1 [NTOK*NH];
__device__ float g_P2 [NTOK*NH];
__device__ float g_G2 [NTOK*NH];
__device__ float g_partA[NTOK*NH];
__device__ float g_partB[NTOK*NH];
// 18 fp16 matrices [k][n] (128x128), rows padded to 272B -> 2176 uint4 each
// 0-2 node MLP, 3-5 edge MLP, 6-9 Wi col-tiles, 10-13 Wo k-chunks,
// 14 W1-P, 15 W1-G, 16 W11-P, 17 W11-G
__device__ uint4 g_Wb[18*2176];

#define AST 272
// 64-row tile layout (hi-only A)
#define M_A   0
#define M_B   17408
#define M_STAT 52224
#define SMEM64 54272
#define SMEMNF 54784

__device__ __forceinline__ float gelu_f(float x) {
    return 0.5f * x * (1.0f + erff(x * 0.7071067811865475f));
}

__device__ __forceinline__ uint32_t smem_u32(const void* p) {
    uint32_t a;
    asm("{ .reg .u64 t; cvta.to.shared.u64 t, %1; cvt.u32.u64 %0, t; }"
        : "=r"(a) : "l"(p));
    return a;
}

__device__ __forceinline__ uint32_t pack_f16(float v0, float v1) {
    __half2 h = __floats2half2_rn(v0, v1);
    return *(uint32_t*)&h;
}

__device__ __forceinline__ void cp16(uint32_t dst, const void* src) {
    asm volatile("cp.async.cg.shared.global [%0], [%1], 16;"
        :: "r"(dst), "l"(src));
}
#define CP_COMMIT() asm volatile("cp.async.commit_group;" ::: "memory")
#define CP_WAIT0()  asm volatile("cp.async.wait_group 0;" ::: "memory")
#define PREF_L2(p)  asm volatile("prefetch.global.L2 [%0];" :: "l"(p))

__device__ __forceinline__ void ldm4(uint32_t r[4], uint32_t a) {
    asm volatile("ldmatrix.sync.aligned.m8n8.x4.shared.b16 {%0,%1,%2,%3}, [%4];"
        : "=r"(r[0]), "=r"(r[1]), "=r"(r[2]), "=r"(r[3]) : "r"(a));
}
__device__ __forceinline__ void ldm4t(uint32_t r[4], uint32_t a) {
    asm volatile("ldmatrix.sync.aligned.m8n8.x4.trans.shared.b16 {%0,%1,%2,%3}, [%4];"
        : "=r"(r[0]), "=r"(r[1]), "=r"(r[2]), "=r"(r[3]) : "r"(a));
}
__device__ __forceinline__ void mma_f16(float c[4], const uint32_t a[4],
                                        uint32_t b0, uint32_t b1) {
    asm volatile(
        "mma.sync.aligned.m16n8k16.row.col.f32.f16.f16.f32 "
        "{%0,%1,%2,%3}, {%4,%5,%6,%7}, {%8,%9}, {%0,%1,%2,%3};"
        : "+f"(c[0]), "+f"(c[1]), "+f"(c[2]), "+f"(c[3])
        : "r"(a[0]), "r"(a[1]), "r"(a[2]), "r"(a[3]), "r"(b0), "r"(b1));
}

// ---------------------------------------------------------------------------
__global__ void detect_kernel(const int* __restrict__ w) {
    int nz = 0;
    for (int i = 2 * (int)threadIdx.x + 1; i < 1024; i += 512) nz |= (w[i] != 0);
    unsigned any = __ballot_sync(0xffffffffu, nz);
    __shared__ int s[8];
    if ((threadIdx.x & 31) == 0) s[threadIdx.x >> 5] = (any != 0);
    __syncthreads();
    if (threadIdx.x == 0) {
        int a = 0;
        #pragma unroll
        for (int i = 0; i < 8; i++) a |= s[i];
        g_is64 = (a == 0);
    }
}

__global__ void convert_kernel(const void* __restrict__ e) {
    int i = blockIdx.x * blockDim.x + threadIdx.x;
    if (i >= NEDGE) return;
    if (g_is64) g_idx32[i] = (int)((const long long*)e)[i];
    else        g_idx32[i] = ((const int*)e)[i];
}

// ---------------------------------------------------------------------------
// wprep: all weights -> fp16 tiles [k][n], rows padded to 272B.
// ---------------------------------------------------------------------------
__global__ void wprep_kernel(const float* W0, const float* W1, const float* W2,
                             const float* W3, const float* W4, const float* W5,
                             const float* Wi, const float* Wo,
                             const float* W1full, const float* W11full) {
    int gid = blockIdx.x * 256 + threadIdx.x;
    if (gid >= 18 * 16384) return;
    int m = gid >> 14, rem = gid & 16383;
    int k = rem >> 7, n = rem & 127;
    float v;
    if (m < 6) {
        const float* W = (m == 0) ? W0 : (m == 1) ? W1 : (m == 2) ? W2
                       : (m == 3) ? W3 : (m == 4) ? W4 : W5;
        v = W[k * 128 + n];
    } else if (m < 10) {
        v = Wi[k * FFH + (m - 6) * 128 + n];
    } else if (m < 14) {
        v = Wo[((m - 10) * 128 + k) * 128 + n];
    } else if (m == 14) {
        v = W1full[k * 128 + n];
    } else if (m == 15) {
        v = W1full[(256 + k) * 128 + n];
    } else if (m == 16) {
        v = W11full[k * 128 + n];
    } else {
        v = W11full[(256 + k) * 128 + n];
    }
    char* basep = (char*)g_Wb + (size_t)m * 34816;
    *(__half*)(basep + (uint32_t)k * 272u + (uint32_t)n * 2u) = __float2half_rn(v);
}

// ---------------------------------------------------------------------------
// Shared mma machinery: 64 rows x 128 cols, K=128, single-pass fp16.
// 8 warps = 2(M) x 4(N).
// ---------------------------------------------------------------------------
__device__ __forceinline__ void copyB_async(uint32_t dst, int mat) {
    const uint4* src = &g_Wb[(size_t)mat * 2176];
    #pragma unroll
    for (int i = 0; i < 9; i++) {
        int idx = threadIdx.x + 256*i;
        if (idx < 2176) cp16(dst + idx*16, src + idx);
    }
}

__device__ __forceinline__ void mma_layer64(uint32_t sb, int warpM, int warpN,
                                            int lane, float (&acc)[2][4][4]) {
    #pragma unroll
    for (int m = 0; m < 2; m++)
        #pragma unroll
        for (int j = 0; j < 4; j++)
            #pragma unroll
            for (int c = 0; c < 4; c++) acc[m][j][c] = 0.0f;

    uint32_t aA = sb + M_A + (uint32_t)(warpM*32 + (lane & 15))*AST
                + (uint32_t)(lane >> 4)*16;
    uint32_t bB = sb + M_B + (uint32_t)(lane & 15)*AST
                + (uint32_t)(warpN*4 + (lane >> 4))*16;

    #pragma unroll
    for (int ks = 0; ks < 8; ks++) {
        uint32_t ah0[4], ah1[4];
        ldm4(ah0, aA + ks*32);
        ldm4(ah1, aA + ks*32 + 16*AST);
        #pragma unroll
        for (int ng = 0; ng < 2; ng++) {
            uint32_t bh[4];
            ldm4t(bh, bB + ks*16*AST + ng*32);
            mma_f16(acc[0][2*ng],   ah0, bh[0], bh[1]);
            mma_f16(acc[1][2*ng],   ah1, bh[0], bh[1]);
            mma_f16(acc[0][2*ng+1], ah0, bh[2], bh[3]);
            mma_f16(acc[1][2*ng+1], ah1, bh[2], bh[3]);
        }
    }
}

// load 64 fp32 rows -> fp16 into smem
__device__ __forceinline__ void loadA64(char* sm, const float* src, int tid) {
    for (int idx = tid; idx < 64*64; idx += 256) {
        int r = idx >> 6, cp = idx & 63;
        float2 x = *(const float2*)&src[(size_t)r*NH + cp*2];
        *(uint32_t*)(sm + M_A + r*AST + cp*4) = pack_f16(x.x, x.y);
    }
}

// cp.async 64 fp16 rows from packed cache (row stride 64 uint32)
__device__ __forceinline__ void loadA64_cached(uint32_t sb, const uint32_t* cache,
                                               size_t row0, int tid) {
    #pragma unroll
    for (int i = 0; i < 4; i++) {
        int idx = tid + 256*i;          // 1024 x 16B
        int r = idx >> 4, q4 = (idx & 15) * 4;
        cp16(sb + M_A + r*AST + q4*4, &cache[(row0 + r)*64 + q4]);
    }
}

// ---------------------------------------------------------------------------
// tokenPG fused: P = A@W14 + b ; G = A@W15. 64 tokens/CTA, grid 64.
// ---------------------------------------------------------------------------
__global__ void __launch_bounds__(256, 3) tokenPG_kernel(
    const float* __restrict__ A, const float* __restrict__ bias,
    float* __restrict__ P, float* __restrict__ G)
{
    extern __shared__ char sm[];
    uint32_t sb = smem_u32(sm);
    int tid = threadIdx.x;
    int wid = tid >> 5, lane = tid & 31;
    int warpM = wid & 1, warpN = wid >> 1;
    int qr = lane >> 2, qc = lane & 3;
    int bl0 = blockIdx.x * 64;
    int cBase = warpN*32 + 2*qc;

    copyB_async(sb + M_B, 14);
    CP_COMMIT();
    loadA64(sm, A + (size_t)bl0*NH, tid);
    CP_WAIT0();
    __syncthreads();

    float acc[2][4][4];
    mma_layer64(sb, warpM, warpN, lane, acc);
    __syncthreads();
    copyB_async(sb + M_B, 15);
    CP_COMMIT();

    #pragma unroll
    for (int mf = 0; mf < 2; mf++)
        #pragma unroll
        for (int j = 0; j < 4; j++) {
            int C = cBase + j*8;
            float2 bv = *(const float2*)&bias[C];
            #pragma unroll
            for (int h = 0; h < 2; h++) {
                int R = warpM*32 + mf*16 + h*8 + qr;
                float2 o2;
                o2.x = acc[mf][j][2*h+0] + bv.x;
                o2.y = acc[mf][j][2*h+1] + bv.y;
                *(float2*)&P[(size_t)(bl0 + R)*NH + C] = o2;
            }
        }
    CP_WAIT0();
    __syncthreads();

    mma_layer64(sb, warpM, warpN, lane, acc);
    #pragma unroll
    for (int mf = 0; mf < 2; mf++)
        #pragma unroll
        for (int j = 0; j < 4; j++) {
            int C = cBase + j*8;
            #pragma unroll
            for (int h = 0; h < 2; h++) {
                int R = warpM*32 + mf*16 + h*8 + qr;
                float2 o2;
                o2.x = acc[mf][j][2*h+0];
                o2.y = acc[mf][j][2*h+1];
                *(float2*)&G[(size_t)(bl0 + R)*NH + C] = o2;
            }
        }
}

// ---------------------------------------------------------------------------
// mlp3: 64 edge rows per CTA. MODE 0 = node (2 layers + masked Z row-sum;
// also writes hE fp16 cache). MODE 1 = edge (3 layers + residual + LN3;
// A built from fp16 cache via cp.async).
// ---------------------------------------------------------------------------
template<int MODE>
__global__ void __launch_bounds__(256, 3) mlp3_kernel(
    const float* __restrict__ hE,
    const float* __restrict__ P, const float* __restrict__ G,
    const float* __restrict__ bias2, const float* __restrict__ bias3,
    const float* __restrict__ mask_attend,
    const float* __restrict__ ln3s, const float* __restrict__ ln3b,
    float* __restrict__ out_hE, int matBase)
{
    extern __shared__ char sm[];
    uint32_t sb = smem_u32(sm);

    int tid = threadIdx.x;
    int wid = tid >> 5, lane = tid & 31;
    int warpM = wid & 1, warpN = wid >> 1;
    int qr = lane >> 2, qc = lane & 3;
    int e0 = blockIdx.x * 64;
    int cBase = warpN*32 + 2*qc;

    int Row[2][2];
    #pragma unroll
    for (int mf = 0; mf < 2; mf++)
        #pragma unroll
        for (int h = 0; h < 2; h++)
            Row[mf][h] = warpM*32 + mf*16 + h*8 + qr;

    copyB_async(sb + M_B, matBase + 0);
    if (MODE == 0) {
        CP_COMMIT();
        // convert hE -> fp16 smem + write cache
        for (int idx = tid; idx < 64*64; idx += 256) {
            int r = idx >> 6, cp = idx & 63;
            float2 x = *(const float2*)&hE[(size_t)(e0 + r)*NH + cp*2];
            uint32_t u = pack_f16(x.x, x.y);
            *(uint32_t*)(sm + M_A + r*AST + cp*4) = u;
            g_hEf16[(size_t)(e0 + r)*64 + cp] = u;
        }
    } else {
        loadA64_cached(sb, g_hEf16, (size_t)e0, tid);
        CP_COMMIT();
    }
    // L2 prefetch of P/G gather rows for epilogue 1
    {
        int r = tid >> 2, ln = tid & 3;
        int e = e0 + r;
        int tok = e / 48;
        int batch = (e >= NL*NK) ? 1 : 0;
        const float* pp = P + (size_t)tok*NH + ln*32;
        const float* gg = G + (size_t)(batch*NL + g_idx32[e])*NH + ln*32;
        PREF_L2(pp);
        PREF_L2(gg);
    }
    CP_WAIT0();
    __syncthreads();

    float acc[2][4][4];

    // ---- layer 1 ----
    mma_layer64(sb, warpM, warpN, lane, acc);
    __syncthreads();
    copyB_async(sb + M_B, matBase + 1);
    CP_COMMIT();
    {
        const float* Pr[2][2];
        const float* Gr[2][2];
        #pragma unroll
        for (int mf = 0; mf < 2; mf++)
            #pragma unroll
            for (int h = 0; h < 2; h++) {
                int e = e0 + Row[mf][h];
                int tok = e / 48;
                int batch = (e >= NL*NK) ? 1 : 0;
                Pr[mf][h] = P + (size_t)tok * NH;
                Gr[mf][h] = G + (size_t)(batch*NL + g_idx32[e]) * NH;
            }
        #pragma unroll
        for (int mf = 0; mf < 2; mf++)
            #pragma unroll
            for (int j = 0; j < 4; j++) {
                int C = cBase + j*8;
                #pragma unroll
                for (int h = 0; h < 2; h++) {
                    float2 pv = *(const float2*)&Pr[mf][h][C];
                    float2 gv = *(const float2*)&Gr[mf][h][C];
                    float v0 = gelu_f(acc[mf][j][2*h+0] + pv.x + gv.x);
                    float v1 = gelu_f(acc[mf][j][2*h+1] + pv.y + gv.y);
                    int R = Row[mf][h];
                    *(uint32_t*)(sm + M_A + R*AST + C*2) = pack_f16(v0, v1);
                }
            }
    }
    CP_WAIT0();
    __syncthreads();

    // ---- layer 2 ----
    mma_layer64(sb, warpM, warpN, lane, acc);
    __syncthreads();

    if (MODE == 0) {
        // Z = gelu(acc + b2); stage Z*mask (fp32); per-token row-sum -> partials
        float* stage = (float*)(sm + M_A);  // [64][136] f32 (aliases A+B)
        #pragma unroll
        for (int mf = 0; mf < 2; mf++)
            #pragma unroll
            for (int h = 0; h < 2; h++) {
                int R = Row[mf][h];
                float mk = mask_attend[e0 + R];
                #pragma unroll
                for (int j = 0; j < 4; j++) {
                    int C = cBase + j*8;
                    float2 bv = *(const float2*)&bias2[C];
                    float2 o2;
                    o2.x = gelu_f(acc[mf][j][2*h+0] + bv.x) * mk;
                    o2.y = gelu_f(acc[mf][j][2*h+1] + bv.y) * mk;
                    *(float2*)&stage[R*136 + C] = o2;
                }
            }
        __syncthreads();
        int t0 = e0 / 48;
        int tend = (e0 + 63) / 48;
        for (int t = t0 + (tid >> 7); t <= tend; t += 2) {
            int col = tid & 127;
            int rs = max(t*48 - e0, 0), re = min(t*48 + 47 - e0, 63);
            float sacc = 0.0f;
            for (int rr = rs; rr <= re; rr++) sacc += stage[rr*136 + col];
            if (t*48 >= e0) g_partA[(size_t)t*NH + col] = sacc;
            else            g_partB[(size_t)t*NH + col] = sacc;
        }
        return;
    }

    // ---- edge path: layer-2 epilogue, layer 3, LN3 ----
    copyB_async(sb + M_B, matBase + 2);
    CP_COMMIT();
    #pragma unroll
    for (int mf = 0; mf < 2; mf++)
        #pragma unroll
        for (int j = 0; j < 4; j++) {
            int C = cBase + j*8;
            float2 bv = *(const float2*)&bias2[C];
            #pragma unroll
            for (int h = 0; h < 2; h++) {
                float v0 = gelu_f(acc[mf][j][2*h+0] + bv.x);
                float v1 = gelu_f(acc[mf][j][2*h+1] + bv.y);
                int R = Row[mf][h];
                *(uint32_t*)(sm + M_A + R*AST + C*2) = pack_f16(v0, v1);
            }
        }
    CP_WAIT0();
    __syncthreads();

    mma_layer64(sb, warpM, warpN, lane, acc);
    __syncthreads();

    float* stats = (float*)(sm + M_STAT);   // [4 warpN][64 rows][2]
    float s1[2][2], s2[2][2];
    #pragma unroll
    for (int mf = 0; mf < 2; mf++)
        #pragma unroll
        for (int h = 0; h < 2; h++) { s1[mf][h] = 0.f; s2[mf][h] = 0.f; }
    #pragma unroll
    for (int mf = 0; mf < 2; mf++)
        #pragma unroll
        for (int j = 0; j < 4; j++) {
            int C = cBase + j*8;
            float2 bv = *(const float2*)&bias3[C];
            #pragma unroll
            for (int h = 0; h < 2; h++) {
                int R = Row[mf][h];
                float2 he = *(const float2*)&hE[(size_t)(e0 + R)*NH + C];
                float v0 = acc[mf][j][2*h+0] + bv.x + he.x;
                float v1 = acc[mf][j][2*h+1] + bv.y + he.y;
                acc[mf][j][2*h+0] = v0;
                acc[mf][j][2*h+1] = v1;
                s1[mf][h] += v0 + v1;
                s2[mf][h] += v0*v0 + v1*v1;
            }
        }
    #pragma unroll
    for (int mf = 0; mf < 2; mf++)
        #pragma unroll
        for (int h = 0; h < 2; h++) {
            #pragma unroll
            for (int o = 1; o < 4; o <<= 1) {
                s1[mf][h] += __shfl_xor_sync(0xffffffffu, s1[mf][h], o);
                s2[mf][h] += __shfl_xor_sync(0xffffffffu, s2[mf][h], o);
            }
            if (qc == 0) {
                stats[(warpN*64 + Row[mf][h])*2 + 0] = s1[mf][h];
                stats[(warpN*64 + Row[mf][h])*2 + 1] = s2[mf][h];
            }
        }
    __syncthreads();
    #pragma unroll
    for (int mf = 0; mf < 2; mf++)
        #pragma unroll
        for (int h = 0; h < 2; h++) {
            int R = Row[mf][h];
            float S1 = 0.f, S2 = 0.f;
            #pragma unroll
            for (int g = 0; g < 4; g++) {
                S1 += stats[(g*64 + R)*2 + 0];
                S2 += stats[(g*64 + R)*2 + 1];
            }
            float mu = S1 * (1.0f / NH);
            float var = S2 * (1.0f / NH) - mu * mu;
            float rinv = rsqrtf(var + 1e-5f);
            #pragma unroll
            for (int j = 0; j < 4; j++) {
                int C = cBase + j*8;
                float2 gs = *(const float2*)&ln3s[C];
                float2 gb = *(const float2*)&ln3b[C];
                float2 o2;
                o2.x = (acc[mf][j][2*h+0] - mu) * rinv * gs.x + gb.x;
                o2.y = (acc[mf][j][2*h+1] - mu) * rinv * gs.y + gb.y;
                *(float2*)&out_hE[(size_t)(e0 + R)*NH + C] = o2;
            }
        }
}

// ---------------------------------------------------------------------------
// nodeFin: dh = S@W3 + (Σmask)*b3 ; h1 = LN1(hV + dh/30). 64 tokens/CTA.
// Writes g_h1 (fp32) and g_h1f16 (packed) for ffn1.
// ---------------------------------------------------------------------------
__global__ void __launch_bounds__(256) nodeFin_kernel(
    const float* __restrict__ hV, const float* __restrict__ b3,
    const float* __restrict__ mask_attend,
    const float* __restrict__ ln1s, const float* __restrict__ ln1b)
{
    extern __shared__ char sm[];
    uint32_t sb = smem_u32(sm);
    int tid = threadIdx.x;
    int wid = tid >> 5, lane = tid & 31;
    int warpM = wid & 1, warpN = wid >> 1;
    int qr = lane >> 2, qc = lane & 3;
    int bl0 = blockIdx.x * 64;
    int cBase = warpN*32 + 2*qc;

    copyB_async(sb + M_B, 2);   // W3
    CP_COMMIT();
    for (int idx = tid; idx < 64*64; idx += 256) {
        int r = idx >> 6, cp = idx & 63;
        int t = bl0 + r;
        float2 x = *(const float2*)&g_partA[(size_t)t*NH + cp*2];
        int s0 = t * 48;
        if (s0 / 64 != (s0 + 47) / 64) {
            float2 y = *(const float2*)&g_partB[(size_t)t*NH + cp*2];
            x.x += y.x; x.y += y.y;
        }
        *(uint32_t*)(sm + M_A + r*AST + cp*4) = pack_f16(x.x, x.y);
    }
    CP_WAIT0();
    __syncthreads();

    float acc[2][4][4];
    mma_layer64(sb, warpM, warpN, lane, acc);

    float* stats = (float*)(sm + M_STAT);
    float* msum  = (float*)(sm + M_STAT + 2048);
    if (tid < 64) {
        int t = bl0 + tid;
        float s = 0.0f;
        #pragma unroll 4
        for (int k = 0; k < NK; k += 4) {
            float4 m4 = *(const float4*)&mask_attend[t*NK + k];
            s += m4.x + m4.y + m4.z + m4.w;
        }
        msum[tid] = s;
    }
    __syncthreads();

    int Row[2][2];
    #pragma unroll
    for (int mf = 0; mf < 2; mf++)
        #pragma unroll
        for (int h = 0; h < 2; h++)
            Row[mf][h] = warpM*32 + mf*16 + h*8 + qr;

    float s1[2][2], s2[2][2];
    #pragma unroll
    for (int mf = 0; mf < 2; mf++)
        #pragma unroll
        for (int h = 0; h < 2; h++) { s1[mf][h] = 0.f; s2[mf][h] = 0.f; }

    #pragma unroll
    for (int mf = 0; mf < 2; mf++)
        #pragma unroll
        for (int j = 0; j < 4; j++) {
            int C = cBase + j*8;
            float2 bv = *(const float2*)&b3[C];
            #pragma unroll
            for (int h = 0; h < 2; h++) {
                int R = Row[mf][h];
                int t = bl0 + R;
                float ms = msum[R];
                float2 hv = *(const float2*)&hV[(size_t)t*NH + C];
                float v0 = hv.x + (acc[mf][j][2*h+0] + ms*bv.x) * (1.0f/30.0f);
                float v1 = hv.y + (acc[mf][j][2*h+1] + ms*bv.y) * (1.0f/30.0f);
                acc[mf][j][2*h+0] = v0;
                acc[mf][j][2*h+1] = v1;
                s1[mf][h] += v0 + v1;
                s2[mf][h] += v0*v0 + v1*v1;
            }
        }
    #pragma unroll
    for (int mf = 0; mf < 2; mf++)
        #pragma unroll
        for (int h = 0; h < 2; h++) {
            #pragma unroll
            for (int o = 1; o < 4; o <<= 1) {
                s1[mf][h] += __shfl_xor_sync(0xffffffffu, s1[mf][h], o);
                s2[mf][h] += __shfl_xor_sync(0xffffffffu, s2[mf][h], o);
            }
            if (qc == 0) {
                stats[(warpN*64 + Row[mf][h])*2 + 0] = s1[mf][h];
                stats[(warpN*64 + Row[mf][h])*2 + 1] = s2[mf][h];
            }
        }
    __syncthreads();
    #pragma unroll
    for (int mf = 0; mf < 2; mf++)
        #pragma unroll
        for (int h = 0; h < 2; h++) {
            int R = Row[mf][h];
            float S1 = 0.f, S2 = 0.f;
            #pragma unroll
            for (int g = 0; g < 4; g++) {
                S1 += stats[(g*64 + R)*2 + 0];
                S2 += stats[(g*64 + R)*2 + 1];
            }
            float mu = S1 * (1.0f / NH);
            float var = S2 * (1.0f / NH) - mu * mu;
            float rinv = rsqrtf(var + 1e-5f);
            #pragma unroll
            for (int j = 0; j < 4; j++) {
                int C = cBase + j*8;
                float2 gs = *(const float2*)&ln1s[C];
                float2 gb = *(const float2*)&ln1b[C];
                float2 o2;
                o2.x = (acc[mf][j][2*h+0] - mu) * rinv * gs.x + gb.x;
                o2.y = (acc[mf][j][2*h+1] - mu) * rinv * gs.y + gb.y;
                *(float2*)&g_h1[(size_t)(bl0 + R)*NH + C] = o2;
                g_h1f16[(size_t)(bl0 + R)*64 + (C >> 1)] = pack_f16(o2.x, o2.y);
            }
        }
}

// ---------------------------------------------------------------------------
// ffn1 (mma): H tile [64tok x 128col] = gelu(h1 @ Wi + bi), store fp16.
// A built from g_h1f16 cache via cp.async. grid (64, 4).
// ---------------------------------------------------------------------------
__global__ void __launch_bounds__(256, 3) ffn1_kernel(const float* __restrict__ bi)
{
    extern __shared__ char sm[];
    uint32_t sb = smem_u32(sm);
    int tid = threadIdx.x;
    int wid = tid >> 5, lane = tid & 31;
    int warpM = wid & 1, warpN = wid >> 1;
    int qr = lane >> 2, qc = lane & 3;
    int bl0 = blockIdx.x * 64;
    int nb  = blockIdx.y * 128;
    int cBase = warpN*32 + 2*qc;

    copyB_async(sb + M_B, 6 + blockIdx.y);
    loadA64_cached(sb, g_h1f16, (size_t)bl0, tid);
    CP_COMMIT();
    CP_WAIT0();
    __syncthreads();

    float acc[2][4][4];
    mma_layer64(sb, warpM, warpN, lane, acc);

    #pragma unroll
    for (int mf = 0; mf < 2; mf++)
        #pragma unroll
        for (int j = 0; j < 4; j++) {
            int C = cBase + j*8;
            float2 bv = *(const float2*)&bi[nb + C];
            #pragma unroll
            for (int h = 0; h < 2; h++) {
                int R = warpM*32 + mf*16 + h*8 + qr;
                float v0 = gelu_f(acc[mf][j][2*h+0] + bv.x);
                float v1 = gelu_f(acc[mf][j][2*h+1] + bv.y);
                uint32_t gi = ((uint32_t)(bl0 + R)*FFH + nb + C) >> 1;
                g_Hhi[gi] = pack_f16(v0, v1);
            }
        }
}

// ---------------------------------------------------------------------------
// ffn2 (mma): hV2 = LN2(h1 + H @ Wo + bo) * mask_V, then fused
// P2 = hV2@W11P + b11, G2 = hV2@W11G. 32 tok/CTA, grid 128.
// ---------------------------------------------------------------------------
#define F2_A   0
#define F2_B   8704
#define F2_STAT 43520
#define SMEM_F2 45568

__device__ __forceinline__ void mma_32(uint32_t sb, int warpM, int warpN,
                                       int lane, float (&acc)[4][4]) {
    #pragma unroll
    for (int j = 0; j < 4; j++)
        #pragma unroll
        for (int c = 0; c < 4; c++) acc[j][c] = 0.0f;
    uint32_t aA = sb + F2_A + (uint32_t)(warpM*16 + (lane & 15))*AST
                + (uint32_t)(lane >> 4)*16;
    uint32_t bB = sb + F2_B + (uint32_t)(lane & 15)*AST
                + (uint32_t)(warpN*4 + (lane >> 4))*16;
    #pragma unroll
    for (int ks = 0; ks < 8; ks++) {
        uint32_t ah[4];
        ldm4(ah, aA + ks*32);
        #pragma unroll
        for (int ng = 0; ng < 2; ng++) {
            uint32_t bh[4];
            ldm4t(bh, bB + ks*16*AST + ng*32);
            mma_f16(acc[2*ng],   ah, bh[0], bh[1]);
            mma_f16(acc[2*ng+1], ah, bh[2], bh[3]);
        }
    }
}

__global__ void __launch_bounds__(256) ffn2_kernel(
    const float* __restrict__ bo,
    const float* __restrict__ ln2s, const float* __restrict__ ln2b,
    const float* __restrict__ mask_V, const float* __restrict__ b11,
    float* __restrict__ out_hV, float* __restrict__ P2, float* __restrict__ G2)
{
    extern __shared__ char sm[];
    uint32_t sb = smem_u32(sm);
    int tid = threadIdx.x;
    int wid = tid >> 5, lane = tid & 31;
    int warpM = wid & 1, warpN = wid >> 1;   // 2 x 4
    int qr = lane >> 2, qc = lane & 3;
    int bl0 = blockIdx.x * 32;
    int cBase = warpN*32 + 2*qc;

    float acc[4][4];
    #pragma unroll
    for (int j = 0; j < 4; j++)
        #pragma unroll
        for (int c = 0; c < 4; c++) acc[j][c] = 0.0f;

    for (int ch = 0; ch < 4; ch++) {
        {
            int idx = tid;
            #pragma unroll
            for (int i = 0; i < 2; i++) {
                int r = idx >> 4, q4 = (idx & 15) * 4;
                uint32_t gi = (uint32_t)(bl0 + r)*256 + ch*64 + q4;
                cp16(sb + F2_A + r*AST + q4*4, &g_Hhi[gi]);
                idx += 256;
            }
        }
        copyB_async(sb + F2_B, 10 + ch);
        CP_COMMIT();
        CP_WAIT0();
        __syncthreads();

        uint32_t aA = sb + F2_A + (uint32_t)(warpM*16 + (lane & 15))*AST
                    + (uint32_t)(lane >> 4)*16;
        uint32_t bB = sb + F2_B + (uint32_t)(lane & 15)*AST
                    + (uint32_t)(warpN*64 + (lane >> 4)*16);

        #pragma unroll
        for (int ks = 0; ks < 8; ks++) {
            uint32_t ah[4];
            ldm4(ah, aA + ks*32);
            #pragma unroll
            for (int ng = 0; ng < 2; ng++) {
                uint32_t bh[4];
                ldm4t(bh, bB + ks*16*AST + ng*32);
                mma_f16(acc[2*ng],   ah, bh[0], bh[1]);
                mma_f16(acc[2*ng+1], ah, bh[2], bh[3]);
            }
        }
        __syncthreads();
    }

    float* stats = (float*)(sm + F2_STAT);
    float s1[2], s2[2];
    #pragma unroll
    for (int h = 0; h < 2; h++) { s1[h] = 0.f; s2[h] = 0.f; }
    #pragma unroll
    for (int j = 0; j < 4; j++) {
        int C = cBase + j*8;
        float2 bv = *(const float2*)&bo[C];
        #pragma unroll
        for (int h = 0; h < 2; h++) {
            int R = warpM*16 + h*8 + qr;
            float2 hv = *(const float2*)&g_h1[(size_t)(bl0 + R)*NH + C];
            float v0 = acc[j][2*h+0] + bv.x + hv.x;
            float v1 = acc[j][2*h+1] + bv.y + hv.y;
            acc[j][2*h+0] = v0;
            acc[j][2*h+1] = v1;
            s1[h] += v0 + v1;
            s2[h] += v0*v0 + v1*v1;
        }
    }
    #pragma unroll
    for (int h = 0; h < 2; h++) {
        #pragma unroll
        for (int o = 1; o < 4; o <<= 1) {
            s1[h] += __shfl_xor_sync(0xffffffffu, s1[h], o);
            s2[h] += __shfl_xor_sync(0xffffffffu, s2[h], o);
        }
        if (qc == 0) {
            int R = warpM*16 + h*8 + qr;
            stats[(warpN*32 + R)*2 + 0] = s1[h];
            stats[(warpN*32 + R)*2 + 1] = s2[h];
        }
    }
    __syncthreads();
    #pragma unroll
    for (int h = 0; h < 2; h++) {
        int R = warpM*16 + h*8 + qr;
        float S1 = 0.f, S2 = 0.f;
        #pragma unroll
        for (int g = 0; g < 4; g++) {
            S1 += stats[(g*32 + R)*2 + 0];
            S2 += stats[(g*32 + R)*2 + 1];
        }
        float mu = S1 * (1.0f / NH);
        float var = S2 * (1.0f / NH) - mu * mu;
        float rinv = rsqrtf(var + 1e-5f);
        int token = bl0 + R;
        float mk = mask_V[token];
        #pragma unroll
        for (int j = 0; j < 4; j++) {
            int C = cBase + j*8;
            float2 gs = *(const float2*)&ln2s[C];
            float2 gb = *(const float2*)&ln2b[C];
            float2 o2;
            o2.x = ((acc[j][2*h+0] - mu) * rinv * gs.x + gb.x) * mk;
            o2.y = ((acc[j][2*h+1] - mu) * rinv * gs.y + gb.y) * mk;
            *(float2*)&out_hV[(size_t)token*NH + C] = o2;
            *(uint32_t*)(sm + F2_A + R*AST + C*2) = pack_f16(o2.x, o2.y);
        }
    }
    __syncthreads();

    // fused P2 = hV2 @ W11P + b11
    copyB_async(sb + F2_B, 16);
    CP_COMMIT();
    CP_WAIT0();
    __syncthreads();
    float acc2[4][4];
    mma_32(sb, warpM, warpN, lane, acc2);
    #pragma unroll
    for (int j = 0; j < 4; j++) {
        int C = cBase + j*8;
        float2 bv = *(const float2*)&b11[C];
        #pragma unroll
        for (int h = 0; h < 2; h++) {
            int R = warpM*16 + h*8 + qr;
            float2 o2;
            o2.x = acc2[j][2*h+0] + bv.x;
            o2.y = acc2[j][2*h+1] + bv.y;
            *(float2*)&P2[(size_t)(bl0 + R)*NH + C] = o2;
        }
    }
    __syncthreads();

    // fused G2 = hV2 @ W11G
    copyB_async(sb + F2_B, 17);
    CP_COMMIT();
    CP_WAIT0();
    __syncthreads();
    mma_32(sb, warpM, warpN, lane, acc2);
    #pragma unroll
    for (int j = 0; j < 4; j++) {
        int C = cBase + j*8;
        #pragma unroll
        for (int h = 0; h < 2; h++) {
            int R = warpM*16 + h*8 + qr;
            float2 o2;
            o2.x = acc2[j][2*h+0];
            o2.y = acc2[j][2*h+1];
            *(float2*)&G2[(size_t)(bl0 + R)*NH + C] = o2;
        }
    }
}

// ---------------------------------------------------------------------------

extern "C" void kernel_launch(void* const* d_in, const int* in_sizes, int n_in,
                              void* d_out, int out_size)
{
    const float* h_V         = (const float*)d_in[0];
    const float* h_E         = (const float*)d_in[1];
    const void*  E_idx       =               d_in[2];
    const float* mask_V      = (const float*)d_in[3];
    const float* mask_attend = (const float*)d_in[4];
    const float* W1  = (const float*)d_in[5],  *b1  = (const float*)d_in[6];
    const float* W2  = (const float*)d_in[7],  *b2  = (const float*)d_in[8];
    const float* W3  = (const float*)d_in[9],  *b3  = (const float*)d_in[10];
    const float* W11 = (const float*)d_in[11], *b11 = (const float*)d_in[12];
    const float* W12 = (const float*)d_in[13], *b12 = (const float*)d_in[14];
    const float* W13 = (const float*)d_in[15], *b13 = (const float*)d_in[16];
    const float* Wi  = (const float*)d_in[17], *bi  = (const float*)d_in[18];
    const float* Wo  = (const float*)d_in[19], *bo  = (const float*)d_in[20];
    const float* ln1s = (const float*)d_in[21], *ln1b = (const float*)d_in[22];
    const float* ln2s = (const float*)d_in[23], *ln2b = (const float*)d_in[24];
    const float* ln3s = (const float*)d_in[25], *ln3b = (const float*)d_in[26];
    float* out = (float*)d_out;

    float *pP1, *pG1, *pP2, *pG2;
    cudaGetSymbolAddress((void**)&pP1,  g_P1);
    cudaGetSymbolAddress((void**)&pG1,  g_G1);
    cudaGetSymbolAddress((void**)&pP2,  g_P2);
    cudaGetSymbolAddress((void**)&pG2,  g_G2);

    cudaFuncSetAttribute(tokenPG_kernel, cudaFuncAttributeMaxDynamicSharedMemorySize, SMEM64);
    cudaFuncSetAttribute(ffn1_kernel,  cudaFuncAttributeMaxDynamicSharedMemorySize, SMEM64);
    cudaFuncSetAttribute(ffn2_kernel,  cudaFuncAttributeMaxDynamicSharedMemorySize, SMEM_F2);
    cudaFuncSetAttribute(nodeFin_kernel, cudaFuncAttributeMaxDynamicSharedMemorySize, SMEMNF);
    cudaFuncSetAttribute(mlp3_kernel<0>, cudaFuncAttributeMaxDynamicSharedMemorySize, SMEM64);
    cudaFuncSetAttribute(mlp3_kernel<1>, cudaFuncAttributeMaxDynamicSharedMemorySize, SMEM64);

    detect_kernel<<<1, 256>>>((const int*)E_idx);
    convert_kernel<<<(NEDGE + 255) / 256, 256>>>(E_idx);

    wprep_kernel<<<(18*16384 + 255)/256, 256>>>(W1 + 128*NH, W2, W3,
                                                W11 + 128*NH, W12, W13, Wi, Wo,
                                                W1, W11);

    tokenPG_kernel<<<64, 256, SMEM64>>>(h_V, b1, pP1, pG1);

    mlp3_kernel<0><<<NEDGE/64, 256, SMEM64>>>(h_E, pP1, pG1, b2, nullptr,
                                              mask_attend, nullptr, nullptr,
                                              nullptr, 0);
    nodeFin_kernel<<<64, 256, SMEMNF>>>(h_V, b3, mask_attend, ln1s, ln1b);

    ffn1_kernel<<<dim3(64, 4), 256, SMEM64>>>(bi);
    ffn2_kernel<<<128, 256, SMEM_F2>>>(bo, ln2s, ln2b, mask_V, b11,
                                       out, pP2, pG2);

    mlp3_kernel<1><<<NEDGE/64, 256, SMEM64>>>(h_E, pP2, pG2, b12, b13,
                                              nullptr, ln3s, ln3b,
                                              out + (size_t)NTOK * NH, 3);
}